// round 6
// baseline (speedup 1.0000x reference)
#include <cuda_runtime.h>
#include <cuda_fp16.h>
#include <math.h>
#include <stdint.h>

typedef __half fp16;

#define B_   2
#define S_   8192
#define C_   1536
#define P_   512
#define H_   32
#define F_   128
#define HF   4096
#define P2   1024
#define M_   1024     // B_*P_

// ---------------- scratch (device globals) ------------------------------------
__device__ __align__(16) fp16 g_xnh[M_ * C_];
__device__ __align__(16) fp16 g_xgh[M_ * C_];
__device__ __align__(16) fp16 g_wqth[HF * C_], g_wqtl[HF * C_];
__device__ __align__(16) fp16 g_wkth[HF * C_], g_wktl[HF * C_];
__device__ __align__(16) fp16 g_wyqh[F_ * C_], g_wyql[F_ * C_];
__device__ __align__(16) fp16 g_wykh[F_ * C_], g_wykl[F_ * C_];
__device__ __align__(16) fp16 g_posh[P2 * HF], g_posl[P2 * HF];
__device__ __align__(16) fp16 g_qh [M_ * HF];
__device__ __align__(16) fp16 g_kh [M_ * HF], g_kl[M_ * HF];
__device__ float g_bias [2 * H_ * P2];
__device__ float g_ypart[8 * M_ * F_];
__device__ float g_QK [(size_t)B_ * H_ * P_ * P_];
__device__ float g_Qp [(size_t)B_ * H_ * P_ * P2];
__device__ float g_Kp [(size_t)B_ * H_ * P_ * P2];

// ---------------- helpers ------------------------------------------------------
__device__ __forceinline__ void hsplit2(float x, float y, uint32_t& hw, uint32_t& lw)
{
    __half hx = __float2half(x);
    __half hy = __float2half(y);
    __half lx = __float2half(x - __half2float(hx));
    __half ly = __float2half(y - __half2float(hy));
    __half2 hp = __halves2half2(hx, hy);
    __half2 lp = __halves2half2(lx, ly);
    hw = *reinterpret_cast<uint32_t*>(&hp);
    lw = *reinterpret_cast<uint32_t*>(&lp);
}

__device__ __forceinline__ void cp16(uint32_t* smem_ptr, const fp16* gptr)
{
    uint32_t s = (uint32_t)__cvta_generic_to_shared(smem_ptr);
    asm volatile("cp.async.cg.shared.global [%0], [%1], 16;\n" :: "r"(s), "l"(gptr));
}

#define MMA_FP16(c, a, b)                                                       \
    asm volatile(                                                               \
        "mma.sync.aligned.m16n8k16.row.col.f32.f16.f16.f32 "                    \
        "{%0,%1,%2,%3}, {%4,%5,%6,%7}, {%8,%9}, {%0,%1,%2,%3};\n"               \
        : "+f"((c)[0]), "+f"((c)[1]), "+f"((c)[2]), "+f"((c)[3])                \
        : "r"((a)[0]), "r"((a)[1]), "r"((a)[2]), "r"((a)[3]),                   \
          "r"((b)[0]), "r"((b)[1]))

#define LDSM4(d0, d1, d2, d3, a)                                                \
    asm volatile(                                                               \
        "ldmatrix.sync.aligned.m8n8.x4.shared.b16 {%0,%1,%2,%3}, [%4];\n"       \
        : "=r"(d0), "=r"(d1), "=r"(d2), "=r"(d3) : "r"(a))

// one k16 sub-step, 2x4 warp layout: 8 LDSM.x4 + 32 MMAs per warp
#define FRAG_LDSM(sst, j0)                                                      \
    do {                                                                        \
        uint32_t ah[4][4], bh[4][2], bl[4][2];                                  \
        _Pragma("unroll")                                                       \
        for (int mt = 0; mt < 4; mt++) {                                        \
            uint32_t aa = (sst) + aoff + mt * 1280u + (j0) * 4u;                \
            LDSM4(ah[mt][0], ah[mt][1], ah[mt][2], ah[mt][3], aa);              \
        }                                                                       \
        _Pragma("unroll")                                                       \
        for (int tp = 0; tp < 2; tp++) {                                        \
            uint32_t ba = (sst) + boff + tp * 1280u + (j0) * 4u + 10240u;       \
            LDSM4(bh[2*tp][0], bh[2*tp+1][0], bh[2*tp][1], bh[2*tp+1][1], ba);  \
            LDSM4(bl[2*tp][0], bl[2*tp+1][0], bl[2*tp][1], bl[2*tp+1][1],       \
                  ba + 10240u);                                                 \
        }                                                                       \
        _Pragma("unroll")                                                       \
        for (int mt = 0; mt < 4; mt++)                                          \
            _Pragma("unroll")                                                   \
            for (int nt = 0; nt < 4; nt++) {                                    \
                MMA_FP16(acc[mt][nt], ah[mt], bh[nt]);                          \
                MMA_FP16(acc[mt][nt], ah[mt], bl[nt]);                          \
            }                                                                   \
    } while (0)

// stage = [Ah 10240B][Bh 10240B][Bl 10240B] = 30720B; 3 stages
#define LOAD_STAGE(s, kpos, Ah, Bh, Bl, lda, ldb)                               \
    {                                                                           \
        uint32_t* sb = sm + (s) * 7680;                                         \
        _Pragma("unroll")                                                       \
        for (int ci = 0; ci < 2; ci++) {                                        \
            int qq = tid + ci * 256;                                            \
            int rw = qq >> 2, cc = qq & 3;                                      \
            uint32_t so = rw * 20 + cc * 4;                                     \
            size_t ga = (size_t)(rowA0 + rw) * (lda) + (kpos) + cc * 8;         \
            size_t gb = (size_t)(col0 + rw) * (ldb) + (kpos) + cc * 8;          \
            cp16(sb + so,        (Ah) + ga);                                    \
            cp16(sb + 2560 + so, (Bh) + gb);                                    \
            cp16(sb + 5120 + so, (Bl) + gb);                                    \
        }                                                                       \
    }

// 3-stage cp.async pipeline (requires nk >= 2)
#define GEMM_MAIN(Ah, Bh, Bl, lda, ldb, kb, nk)                                 \
    {                                                                           \
        LOAD_STAGE(0, (kb), Ah, Bh, Bl, lda, ldb);                              \
        asm volatile("cp.async.commit_group;\n");                               \
        LOAD_STAGE(1, (kb) + 32, Ah, Bh, Bl, lda, ldb);                         \
        asm volatile("cp.async.commit_group;\n");                               \
        for (int it = 0; it < (nk); it++) {                                     \
            if (it + 2 < (nk)) asm volatile("cp.async.wait_group 1;\n");        \
            else               asm volatile("cp.async.wait_group 0;\n");        \
            __syncthreads();                                                    \
            uint32_t sst = smb + (uint32_t)((it % 3) * 30720);                  \
            FRAG_LDSM(sst, 0);                                                  \
            if (it + 2 < (nk)) {                                                \
                LOAD_STAGE((it + 2) % 3, (kb) + (it + 2) * 32,                  \
                           Ah, Bh, Bl, lda, ldb);                               \
                asm volatile("cp.async.commit_group;\n");                       \
            }                                                                   \
            FRAG_LDSM(sst, 8);                                                  \
        }                                                                       \
    }

// 2(m) x 4(n) warp layout: warp tile 64m x 32n
#define GEMM_PREAMBLE                                                           \
    extern __shared__ uint32_t sm[];                                            \
    uint32_t smb = (uint32_t)__cvta_generic_to_shared(sm);                      \
    int tid = threadIdx.x;                                                      \
    int warp = tid >> 5, lane = tid & 31;                                       \
    int g = lane >> 2, tig = lane & 3;                                          \
    int lr = lane & 15, lh = lane >> 4;                                         \
    int m0 = (warp >> 2) * 64, n0 = (warp & 3) * 32;                            \
    uint32_t aoff = ((m0 + lr) * 20 + lh * 4) * 4;                              \
    uint32_t boff = ((n0 + lr) * 20 + lh * 4) * 4;                              \
    float acc[4][4][4];                                                         \
    _Pragma("unroll")                                                           \
    for (int i = 0; i < 4; i++)                                                 \
        _Pragma("unroll")                                                       \
        for (int j = 0; j < 4; j++)                                             \
            _Pragma("unroll")                                                   \
            for (int l = 0; l < 4; l++) acc[i][j][l] = 0.f;

#define EPI_F32(Cp, ldc, alpha)                                                 \
    _Pragma("unroll")                                                           \
    for (int mt = 0; mt < 4; mt++)                                              \
        _Pragma("unroll")                                                       \
        for (int nt = 0; nt < 4; nt++) {                                        \
            int r = rowA0 + m0 + mt * 16 + g;                                   \
            int cix = col0 + n0 + nt * 8 + tig * 2;                             \
            *(float2*)((Cp) + (size_t)r * (ldc) + cix) =                        \
                make_float2(acc[mt][nt][0] * (alpha), acc[mt][nt][1] * (alpha));\
            *(float2*)((Cp) + (size_t)(r + 8) * (ldc) + cix) =                  \
                make_float2(acc[mt][nt][2] * (alpha), acc[mt][nt][3] * (alpha));\
        }

#define GEMM_SMEM 92160

// ---------------- kernel: pool + RMS norm + GELU (hi fp16 out) ----------------
__global__ __launch_bounds__(256) void pool_norm_kernel(
    const float* __restrict__ x, const float* __restrict__ norm_w)
{
    int bid = blockIdx.x;
    int b = bid >> 9, p = bid & 511;
    int tid = threadIdx.x;

    const float* xrow = x + ((size_t)b * S_ + (size_t)p * 16) * C_;
    float xp[6];
#pragma unroll
    for (int j = 0; j < 6; j++) xp[j] = 0.f;
    for (int r = 0; r < 16; r++) {
        const float* xr = xrow + (size_t)r * C_;
#pragma unroll
        for (int j = 0; j < 6; j++) xp[j] += xr[tid + j * 256];
    }
    float ssq = 0.f;
#pragma unroll
    for (int j = 0; j < 6; j++) { xp[j] *= (1.f / 16.f); ssq += xp[j] * xp[j]; }

    __shared__ float red[256];
    red[tid] = ssq;
    __syncthreads();
    for (int s = 128; s > 0; s >>= 1) {
        if (tid < s) red[tid] += red[tid + s];
        __syncthreads();
    }
    float scale = 1.f / sqrtf(red[0] * (1.f / (float)C_) + 1e-8f);

    size_t base = (size_t)bid * C_;
#pragma unroll
    for (int j = 0; j < 6; j++) {
        int ch = tid + j * 256;
        float v = xp[j] * scale * norm_w[ch];
        float gv = v * 0.5f * (1.f + erff(v * 0.70710678118654752f));
        g_xnh[base + ch] = __float2half(v);
        g_xgh[base + ch] = __float2half(gv);
    }
}

// ---------------- kernel: pos features @ Wpos + bpos (split fp16 out) ---------
__global__ __launch_bounds__(128) void pos_kernel(
    const float* __restrict__ Wpos, const float* __restrict__ bpos)
{
    int d   = blockIdx.x;
    int tid = threadIdx.x;
    __shared__ float feat[32];

    int rel = d - P_;
    if (tid < 16) {
        double geo = exp((double)tid * (log(497.0) / 16.0));
        float center = (float)tid + (float)geo;
        float oh = (center > fabsf((float)rel)) ? 1.f : 0.f;
        float sg = (rel > 0) ? 1.f : ((rel < 0) ? -1.f : 0.f);
        feat[tid]      = oh;
        feat[tid + 16] = oh * sg;
    }
    __syncthreads();

    float f[32];
#pragma unroll
    for (int c = 0; c < 32; c++) f[c] = feat[c];

    for (int n = tid; n < HF; n += 128) {
        float acc = bpos[n];
#pragma unroll
        for (int c = 0; c < 32; c++) acc += f[c] * Wpos[c * HF + n];
        __half h = __float2half(acc);
        g_posh[(size_t)d * HF + n] = h;
        g_posl[(size_t)d * HF + n] = __float2half(acc - __half2float(h));
    }
}

// ---------------- kernel: rel-bias tables Bias[sel][h][d] = 0.25*rb·pos -------
__global__ __launch_bounds__(256) void bias_kernel(
    const float* __restrict__ qrb, const float* __restrict__ krb)
{
    int d = blockIdx.x;
    int lane = threadIdx.x & 31, w = threadIdx.x >> 5;
    for (int h = w; h < H_; h += 8) {
        float sq = 0.f, sk = 0.f;
        size_t pb = (size_t)d * HF + h * F_;
        for (int c = lane; c < F_; c += 32) {
            float pv = __half2float(g_posh[pb + c]) + __half2float(g_posl[pb + c]);
            sq += qrb[h * F_ + c] * pv;
            sk += krb[h * F_ + c] * pv;
        }
#pragma unroll
        for (int o = 16; o; o >>= 1) {
            sq += __shfl_xor_sync(0xffffffffu, sq, o);
            sk += __shfl_xor_sync(0xffffffffu, sk, o);
        }
        if (lane == 0) {
            g_bias[h * P2 + d]           = 0.25f * sq;
            g_bias[H_ * P2 + h * P2 + d] = 0.25f * sk;
        }
    }
}

// ---------------- kernel: weight transpose-convert W[K,N] -> T[N,K] split -----
__global__ __launch_bounds__(256) void wconv_kernel(
    const float* __restrict__ W, fp16* __restrict__ Th, fp16* __restrict__ Tl,
    int K, int N)
{
    __shared__ float t[32][33];
    int nt0 = blockIdx.x * 32, kt0 = blockIdx.y * 32;
    int tx = threadIdx.x & 31, ty = threadIdx.x >> 5;
#pragma unroll
    for (int i = 0; i < 4; i++)
        t[ty + i * 8][tx] = W[(size_t)(kt0 + ty + i * 8) * N + nt0 + tx];
    __syncthreads();
#pragma unroll
    for (int i = 0; i < 4; i++) {
        int n = nt0 + ty + i * 8, k = kt0 + tx;
        float v = t[tx][ty + i * 8];
        __half h = __float2half(v);
        Th[(size_t)n * K + k] = h;
        Tl[(size_t)n * K + k] = __float2half(v - __half2float(h));
    }
}

// ---------------- kernel: projection GEMM (q/k) -------------------------------
__global__ __launch_bounds__(256, 2) void proj_gemm(
    const fp16* __restrict__ Ah,
    const fp16* __restrict__ Bh, const fp16* __restrict__ Bl,
    fp16* __restrict__ Oh, fp16* __restrict__ Ol)
{
    GEMM_PREAMBLE
    int rowA0 = blockIdx.y * 128, col0 = blockIdx.x * 128;
    GEMM_MAIN(Ah, Bh, Bl, C_, C_, 0, C_ / 32);

    uint32_t* oh = (uint32_t*)Oh;
    uint32_t* ol = (uint32_t*)Ol;
#pragma unroll
    for (int mt = 0; mt < 4; mt++)
#pragma unroll
        for (int nt = 0; nt < 4; nt++) {
            int r = rowA0 + m0 + mt * 16 + g;
            int n = col0 + n0 + nt * 8 + tig * 2;
            uint32_t hw, lw;
            size_t ix0 = ((size_t)r * HF + n) >> 1;
            size_t ix1 = ((size_t)(r + 8) * HF + n) >> 1;
            hsplit2(acc[mt][nt][0], acc[mt][nt][1], hw, lw);
            oh[ix0] = hw;
            if (ol) ol[ix0] = lw;
            hsplit2(acc[mt][nt][2], acc[mt][nt][3], hw, lw);
            oh[ix1] = hw;
            if (ol) ol[ix1] = lw;
        }
}

// ---------------- kernel: yq/yk GEMM, split-K x4 -------------------------------
__global__ __launch_bounds__(256, 2) void y_gemm(
    const fp16* __restrict__ Ah,
    const fp16* __restrict__ B0h, const fp16* __restrict__ B0l,
    const fp16* __restrict__ B1h, const fp16* __restrict__ B1l,
    float* __restrict__ ypart)
{
    GEMM_PREAMBLE
    int z = blockIdx.z;
    const fp16* Bh = (z >= 4) ? B1h : B0h;
    const fp16* Bl = (z >= 4) ? B1l : B0l;
    int kb = (z & 3) * 384;
    int rowA0 = blockIdx.y * 128, col0 = 0;
    GEMM_MAIN(Ah, Bh, Bl, C_, C_, kb, 12);
    float* C = ypart + (size_t)z * M_ * F_;
    EPI_F32(C, F_, 1.0f)
}

// ---------------- kernel: batched relative GEMM (QK / Qp / Kp) ----------------
__global__ __launch_bounds__(256, 2) void rel_gemm(
    const fp16* __restrict__ Ahb,
    const fp16* __restrict__ Bhb, const fp16* __restrict__ Blb,
    float* __restrict__ Cbase, const float* __restrict__ biasT,
    int N, int bInB, int band, float alpha)
{
    GEMM_PREAMBLE
    int z = blockIdx.z, b = z >> 5, h = z & 31;
    int tx, ty;
    if (band) { int i = blockIdx.x; ty = i / 5; tx = 3 - ty + (i % 5); }
    else      { tx = blockIdx.x; ty = blockIdx.y; }
    const fp16* Ah = Ahb + (size_t)b * P_ * HF + h * F_;
    const fp16* Bh = Bhb + (bInB ? (size_t)b * P_ * HF : 0) + h * F_;
    const fp16* Bl = Blb + (bInB ? (size_t)b * P_ * HF : 0) + h * F_;
    float* C = Cbase + (size_t)z * P_ * N;
    int rowA0 = ty * 128, col0 = tx * 128;
    GEMM_MAIN(Ah, Bh, Bl, HF, HF, 0, 4);

    const float* bp = biasT ? (biasT + (size_t)h * N) : (const float*)0;
#pragma unroll
    for (int mt = 0; mt < 4; mt++)
#pragma unroll
        for (int nt = 0; nt < 4; nt++) {
            int r = rowA0 + m0 + mt * 16 + g;
            int cix = col0 + n0 + nt * 8 + tig * 2;
            float b0 = 0.f, b1 = 0.f;
            if (bp) { float2 v = *(const float2*)(bp + cix); b0 = v.x; b1 = v.y; }
            *(float2*)(C + (size_t)r * N + cix) =
                make_float2(acc[mt][nt][0] * alpha + b0, acc[mt][nt][1] * alpha + b1);
            *(float2*)(C + (size_t)(r + 8) * N + cix) =
                make_float2(acc[mt][nt][2] * alpha + b0, acc[mt][nt][3] * alpha + b1);
        }
}

// ---------------- kernel: fused gather + a@Wout epilogue ----------------------
#define A_QSTRIDE 1057
#define A_KSTRIDE 33
#define SMEM_FINAL ((32 * A_QSTRIDE + 2 * 32 * 128) * 4)
#define M128 (M_ * F_)

__global__ __launch_bounds__(256) void final_kernel(
    const float* __restrict__ QK, const float* __restrict__ Qp,
    const float* __restrict__ Kp, const float* __restrict__ ypart,
    const float* __restrict__ Wout, const float* __restrict__ bout,
    float* __restrict__ out)
{
    extern __shared__ float smem[];
    float* a_s  = smem;
    float* yq_s = smem + 32 * A_QSTRIDE;
    float* yk_s = yq_s + 32 * 128;

    int b  = blockIdx.z;
    int qt = blockIdx.y * 32;
    int kt = blockIdx.x * 32;
    int tid = threadIdx.x;

    for (int i = tid; i < 32 * 128; i += 256) {
        int q = i >> 7, f = i & 127;
        size_t rq = ((size_t)(b * P_ + qt + q)) * F_ + f;
        size_t rk = ((size_t)(b * P_ + kt + q)) * F_ + f;
        float vq = 0.f, vk = 0.f;
#pragma unroll
        for (int s = 0; s < 4; s++) {
            vq += ypart[(size_t)s * M128 + rq];
            vk += ypart[(size_t)(4 + s) * M128 + rk];
        }
        yq_s[i] = vq;
        yk_s[i] = vk;
    }

    for (int i = tid; i < 32 * 32 * 32; i += 256) {
        int h = i >> 10, q = (i >> 5) & 31, k = i & 31;
        int gq = qt + q, gk = kt + k;
        size_t zb = (size_t)(b * 32 + h);
        float v = QK[(zb * P_ + gq) * P_ + gk]
                + Qp[(zb * P_ + gq) * P2 + (P_ + gk - gq)];
        a_s[q * A_QSTRIDE + k * A_KSTRIDE + h] = v;
    }
    __syncthreads();

    for (int i = tid; i < 32 * 32 * 32; i += 256) {
        int h = i >> 10, k = (i >> 5) & 31, q = i & 31;
        int gq = qt + q, gk = kt + k;
        size_t zb = (size_t)(b * 32 + h);
        a_s[q * A_QSTRIDE + k * A_KSTRIDE + h] +=
            Kp[(zb * P_ + gk) * P2 + (P_ + gq - gk)];
    }
    __syncthreads();

    int lane = tid & 31, warp = tid >> 5;
    float w[32][4];
#pragma unroll
    for (int h = 0; h < 32; h++)
#pragma unroll
        for (int j = 0; j < 4; j++) w[h][j] = Wout[h * F_ + lane + j * 32];
    float bo[4];
#pragma unroll
    for (int j = 0; j < 4; j++) bo[j] = bout[lane + j * 32];

    for (int p = warp; p < 1024; p += 8) {
        int q = p >> 5, k = p & 31;
        const float* ap = a_s + q * A_QSTRIDE + k * A_KSTRIDE;
        float acc[4];
#pragma unroll
        for (int j = 0; j < 4; j++)
            acc[j] = bo[j] + yq_s[q * 128 + lane + j * 32]
                           + yk_s[k * 128 + lane + j * 32];
#pragma unroll
        for (int h = 0; h < 32; h++) {
            float ah = ap[h];
#pragma unroll
            for (int j = 0; j < 4; j++) acc[j] += ah * w[h][j];
        }
        float* orow = out + (((size_t)(b * P_) + qt + q) * P_ + kt + k) * F_ + lane;
#pragma unroll
        for (int j = 0; j < 4; j++) orow[j * 32] = acc[j];
    }
}

// ---------------- launch ------------------------------------------------------
extern "C" void kernel_launch(void* const* d_in, const int* in_sizes, int n_in,
                              void* d_out, int out_size)
{
    const float* x        = (const float*)d_in[0];
    const float* norm_w   = (const float*)d_in[1];
    const float* Wq       = (const float*)d_in[2];
    const float* Wk       = (const float*)d_in[3];
    const float* Wpos     = (const float*)d_in[4];
    const float* bpos     = (const float*)d_in[5];
    const float* q_r_bias = (const float*)d_in[6];
    const float* k_r_bias = (const float*)d_in[7];
    const float* Wyq      = (const float*)d_in[8];
    const float* Wyk      = (const float*)d_in[9];
    const float* Wout     = (const float*)d_in[10];
    const float* bout     = (const float*)d_in[11];
    float* out = (float*)d_out;

    fp16 *p_xnh, *p_xgh;
    fp16 *p_wqth, *p_wqtl, *p_wkth, *p_wktl, *p_wyqh, *p_wyql, *p_wykh, *p_wykl;
    fp16 *p_posh, *p_posl, *p_qh, *p_kh, *p_kl;
    float *p_bias, *p_ypart, *p_QK, *p_Qp, *p_Kp;
    cudaGetSymbolAddress((void**)&p_xnh,  g_xnh);
    cudaGetSymbolAddress((void**)&p_xgh,  g_xgh);
    cudaGetSymbolAddress((void**)&p_wqth, g_wqth);
    cudaGetSymbolAddress((void**)&p_wqtl, g_wqtl);
    cudaGetSymbolAddress((void**)&p_wkth, g_wkth);
    cudaGetSymbolAddress((void**)&p_wktl, g_wktl);
    cudaGetSymbolAddress((void**)&p_wyqh, g_wyqh);
    cudaGetSymbolAddress((void**)&p_wyql, g_wyql);
    cudaGetSymbolAddress((void**)&p_wykh, g_wykh);
    cudaGetSymbolAddress((void**)&p_wykl, g_wykl);
    cudaGetSymbolAddress((void**)&p_posh, g_posh);
    cudaGetSymbolAddress((void**)&p_posl, g_posl);
    cudaGetSymbolAddress((void**)&p_qh,   g_qh);
    cudaGetSymbolAddress((void**)&p_kh,   g_kh);
    cudaGetSymbolAddress((void**)&p_kl,   g_kl);
    cudaGetSymbolAddress((void**)&p_bias, g_bias);
    cudaGetSymbolAddress((void**)&p_ypart, g_ypart);
    cudaGetSymbolAddress((void**)&p_QK,   g_QK);
    cudaGetSymbolAddress((void**)&p_Qp,   g_Qp);
    cudaGetSymbolAddress((void**)&p_Kp,   g_Kp);

    cudaFuncSetAttribute(proj_gemm, cudaFuncAttributeMaxDynamicSharedMemorySize, GEMM_SMEM);
    cudaFuncSetAttribute(y_gemm,    cudaFuncAttributeMaxDynamicSharedMemorySize, GEMM_SMEM);
    cudaFuncSetAttribute(rel_gemm,  cudaFuncAttributeMaxDynamicSharedMemorySize, GEMM_SMEM);
    cudaFuncSetAttribute(final_kernel, cudaFuncAttributeMaxDynamicSharedMemorySize, SMEM_FINAL);

    // reordered so ncu capture (skip ~3-5) lands on proj_gemm
    wconv_kernel<<<dim3(128, 48), 256>>>(Wq, p_wqth, p_wqtl, C_, HF);  // 0
    wconv_kernel<<<dim3(128, 48), 256>>>(Wk, p_wkth, p_wktl, C_, HF);  // 1
    pool_norm_kernel<<<1024, 256>>>(x, norm_w);                        // 2
    proj_gemm<<<dim3(32, 8), 256, GEMM_SMEM>>>(                        // 3
        p_xnh, p_wqth, p_wqtl, p_qh, (fp16*)0);
    proj_gemm<<<dim3(32, 8), 256, GEMM_SMEM>>>(                        // 4
        p_xnh, p_wkth, p_wktl, p_kh, p_kl);

    pos_kernel<<<1024, 128>>>(Wpos, bpos);                             // 5
    bias_kernel<<<1024, 256>>>(q_r_bias, k_r_bias);                    // 6
    wconv_kernel<<<dim3(4, 48), 256>>>(Wyq, p_wyqh, p_wyql, C_, F_);   // 7
    wconv_kernel<<<dim3(4, 48), 256>>>(Wyk, p_wykh, p_wykl, C_, F_);   // 8
    y_gemm<<<dim3(1, 8, 8), 256, GEMM_SMEM>>>(
        p_xgh, p_wyqh, p_wyql, p_wykh, p_wykl, p_ypart);

    rel_gemm<<<dim3(4, 4, 64), 256, GEMM_SMEM>>>(
        p_qh, p_kh, p_kl, p_QK, (const float*)0, P_, 1, 0, 1.0f);
    rel_gemm<<<dim3(20, 1, 64), 256, GEMM_SMEM>>>(
        p_qh, p_posh, p_posl, p_Qp, p_bias,           P2, 0, 1, 0.25f);
    rel_gemm<<<dim3(20, 1, 64), 256, GEMM_SMEM>>>(
        p_kh, p_posh, p_posl, p_Kp, p_bias + H_ * P2, P2, 0, 1, 0.25f);

    final_kernel<<<dim3(16, 16, 2), 256, SMEM_FINAL>>>(
        p_QK, p_Qp, p_Kp, p_ypart, Wout, bout, out);
}

// round 9
// speedup vs baseline: 1.0414x; 1.0414x over previous
#include <cuda_runtime.h>
#include <cuda_fp16.h>
#include <math.h>
#include <stdint.h>

typedef __half fp16;

#define B_   2
#define S_   8192
#define C_   1536
#define P_   512
#define H_   32
#define F_   128
#define HF   4096
#define P2   1024
#define M_   1024     // B_*P_

// ---------------- scratch (device globals) ------------------------------------
__device__ __align__(16) fp16 g_xnh[M_ * C_];
__device__ __align__(16) fp16 g_xgh[M_ * C_];
__device__ __align__(16) fp16 g_wqth[HF * C_], g_wqtl[HF * C_];
__device__ __align__(16) fp16 g_wkth[HF * C_], g_wktl[HF * C_];
__device__ __align__(16) fp16 g_wyqh[F_ * C_], g_wyql[F_ * C_];
__device__ __align__(16) fp16 g_wykh[F_ * C_], g_wykl[F_ * C_];
__device__ __align__(16) fp16 g_posh[P2 * HF], g_posl[P2 * HF];
__device__ __align__(16) fp16 g_qh [M_ * HF];
__device__ __align__(16) fp16 g_kh [M_ * HF], g_kl[M_ * HF];
__device__ float g_bias [2 * H_ * P2];
__device__ float g_ypart[8 * M_ * F_];
__device__ __align__(16) fp16 g_QK [(size_t)B_ * H_ * P_ * P_];
__device__ __align__(16) fp16 g_Qp [(size_t)B_ * H_ * P_ * P2];
__device__ __align__(16) fp16 g_Kp [(size_t)B_ * H_ * P_ * P2];

// ---------------- helpers ------------------------------------------------------
__device__ __forceinline__ void hsplit2(float x, float y, uint32_t& hw, uint32_t& lw)
{
    __half hx = __float2half(x);
    __half hy = __float2half(y);
    __half lx = __float2half(x - __half2float(hx));
    __half ly = __float2half(y - __half2float(hy));
    __half2 hp = __halves2half2(hx, hy);
    __half2 lp = __halves2half2(lx, ly);
    hw = *reinterpret_cast<uint32_t*>(&hp);
    lw = *reinterpret_cast<uint32_t*>(&lp);
}

__device__ __forceinline__ void cp16(uint32_t* smem_ptr, const fp16* gptr)
{
    uint32_t s = (uint32_t)__cvta_generic_to_shared(smem_ptr);
    asm volatile("cp.async.cg.shared.global [%0], [%1], 16;\n" :: "r"(s), "l"(gptr));
}

#define MMA_FP16(c, a, b)                                                       \
    asm volatile(                                                               \
        "mma.sync.aligned.m16n8k16.row.col.f32.f16.f16.f32 "                    \
        "{%0,%1,%2,%3}, {%4,%5,%6,%7}, {%8,%9}, {%0,%1,%2,%3};\n"               \
        : "+f"((c)[0]), "+f"((c)[1]), "+f"((c)[2]), "+f"((c)[3])                \
        : "r"((a)[0]), "r"((a)[1]), "r"((a)[2]), "r"((a)[3]),                   \
          "r"((b)[0]), "r"((b)[1]))

#define LDSM4(d0, d1, d2, d3, a)                                                \
    asm volatile(                                                               \
        "ldmatrix.sync.aligned.m8n8.x4.shared.b16 {%0,%1,%2,%3}, [%4];\n"       \
        : "=r"(d0), "=r"(d1), "=r"(d2), "=r"(d3) : "r"(a))

// one k16 sub-step, 4(m)x2(n) warp layout: 10 LDSM.x4 + 32 MMAs per warp
#define FRAG_LDSM(sst, j0)                                                      \
    do {                                                                        \
        uint32_t ah[2][4], bh[8][2], bl[8][2];                                  \
        _Pragma("unroll")                                                       \
        for (int mt = 0; mt < 2; mt++) {                                        \
            uint32_t aa = (sst) + aoff + mt * 1280u + (j0) * 4u;                \
            LDSM4(ah[mt][0], ah[mt][1], ah[mt][2], ah[mt][3], aa);              \
        }                                                                       \
        _Pragma("unroll")                                                       \
        for (int tp = 0; tp < 4; tp++) {                                        \
            uint32_t ba = (sst) + boff + tp * 1280u + (j0) * 4u + 10240u;       \
            LDSM4(bh[2*tp][0], bh[2*tp+1][0], bh[2*tp][1], bh[2*tp+1][1], ba);  \
            LDSM4(bl[2*tp][0], bl[2*tp+1][0], bl[2*tp][1], bl[2*tp+1][1],       \
                  ba + 10240u);                                                 \
        }                                                                       \
        _Pragma("unroll")                                                       \
        for (int mt = 0; mt < 2; mt++)                                          \
            _Pragma("unroll")                                                   \
            for (int nt = 0; nt < 8; nt++) {                                    \
                MMA_FP16(acc[mt][nt], ah[mt], bh[nt]);                          \
                MMA_FP16(acc[mt][nt], ah[mt], bl[nt]);                          \
            }                                                                   \
    } while (0)

// stage = [Ah 10240B][Bh 10240B][Bl 10240B] = 30720B; 3 stages
#define LOAD_STAGE(s, kpos, Ah, Bh, Bl, lda, ldb)                               \
    {                                                                           \
        uint32_t* sb = sm + (s) * 7680;                                         \
        _Pragma("unroll")                                                       \
        for (int ci = 0; ci < 2; ci++) {                                        \
            int qq = tid + ci * 256;                                            \
            int rw = qq >> 2, cc = qq & 3;                                      \
            uint32_t so = rw * 20 + cc * 4;                                     \
            size_t ga = (size_t)(rowA0 + rw) * (lda) + (kpos) + cc * 8;         \
            size_t gb = (size_t)(col0 + rw) * (ldb) + (kpos) + cc * 8;          \
            cp16(sb + so,        (Ah) + ga);                                    \
            cp16(sb + 2560 + so, (Bh) + gb);                                    \
            cp16(sb + 5120 + so, (Bl) + gb);                                    \
        }                                                                       \
    }

// 3-stage cp.async pipeline (requires nk >= 2)
#define GEMM_MAIN(Ah, Bh, Bl, lda, ldb, kb, nk)                                 \
    {                                                                           \
        LOAD_STAGE(0, (kb), Ah, Bh, Bl, lda, ldb);                              \
        asm volatile("cp.async.commit_group;\n");                               \
        LOAD_STAGE(1, (kb) + 32, Ah, Bh, Bl, lda, ldb);                         \
        asm volatile("cp.async.commit_group;\n");                               \
        for (int it = 0; it < (nk); it++) {                                     \
            if (it + 2 < (nk)) asm volatile("cp.async.wait_group 1;\n");        \
            else               asm volatile("cp.async.wait_group 0;\n");        \
            __syncthreads();                                                    \
            uint32_t sst = smb + (uint32_t)((it % 3) * 30720);                  \
            FRAG_LDSM(sst, 0);                                                  \
            if (it + 2 < (nk)) {                                                \
                LOAD_STAGE((it + 2) % 3, (kb) + (it + 2) * 32,                  \
                           Ah, Bh, Bl, lda, ldb);                               \
                asm volatile("cp.async.commit_group;\n");                       \
            }                                                                   \
            FRAG_LDSM(sst, 8);                                                  \
        }                                                                       \
    }

// 4(m) x 2(n) warp layout
#define GEMM_PREAMBLE                                                           \
    extern __shared__ uint32_t sm[];                                            \
    uint32_t smb = (uint32_t)__cvta_generic_to_shared(sm);                      \
    int tid = threadIdx.x;                                                      \
    int warp = tid >> 5, lane = tid & 31;                                       \
    int g = lane >> 2, tig = lane & 3;                                          \
    int lr = lane & 15, lh = lane >> 4;                                         \
    int m0 = (warp >> 1) * 32, n0 = (warp & 1) * 64;                            \
    uint32_t aoff = ((m0 + lr) * 20 + lh * 4) * 4;                              \
    uint32_t boff = ((n0 + lr) * 20 + lh * 4) * 4;                              \
    float acc[2][8][4];                                                         \
    _Pragma("unroll")                                                           \
    for (int i = 0; i < 2; i++)                                                 \
        _Pragma("unroll")                                                       \
        for (int j = 0; j < 8; j++)                                             \
            _Pragma("unroll")                                                   \
            for (int l = 0; l < 4; l++) acc[i][j][l] = 0.f;

#define EPI_F32(Cp, ldc, alpha)                                                 \
    _Pragma("unroll")                                                           \
    for (int mt = 0; mt < 2; mt++)                                              \
        _Pragma("unroll")                                                       \
        for (int nt = 0; nt < 8; nt++) {                                        \
            int r = rowA0 + m0 + mt * 16 + g;                                   \
            int cix = col0 + n0 + nt * 8 + tig * 2;                             \
            *(float2*)((Cp) + (size_t)r * (ldc) + cix) =                        \
                make_float2(acc[mt][nt][0] * (alpha), acc[mt][nt][1] * (alpha));\
            *(float2*)((Cp) + (size_t)(r + 8) * (ldc) + cix) =                  \
                make_float2(acc[mt][nt][2] * (alpha), acc[mt][nt][3] * (alpha));\
        }

#define GEMM_SMEM 92160

// ---------------- kernel: pool + RMS norm + GELU (hi fp16 out) ----------------
__global__ __launch_bounds__(256) void pool_norm_kernel(
    const float* __restrict__ x, const float* __restrict__ norm_w)
{
    int bid = blockIdx.x;
    int b = bid >> 9, p = bid & 511;
    int tid = threadIdx.x;

    const float* xrow = x + ((size_t)b * S_ + (size_t)p * 16) * C_;
    float xp[6];
#pragma unroll
    for (int j = 0; j < 6; j++) xp[j] = 0.f;
    for (int r = 0; r < 16; r++) {
        const float* xr = xrow + (size_t)r * C_;
#pragma unroll
        for (int j = 0; j < 6; j++) xp[j] += xr[tid + j * 256];
    }
    float ssq = 0.f;
#pragma unroll
    for (int j = 0; j < 6; j++) { xp[j] *= (1.f / 16.f); ssq += xp[j] * xp[j]; }

    __shared__ float red[256];
    red[tid] = ssq;
    __syncthreads();
    for (int s = 128; s > 0; s >>= 1) {
        if (tid < s) red[tid] += red[tid + s];
        __syncthreads();
    }
    float scale = 1.f / sqrtf(red[0] * (1.f / (float)C_) + 1e-8f);

    size_t base = (size_t)bid * C_;
#pragma unroll
    for (int j = 0; j < 6; j++) {
        int ch = tid + j * 256;
        float v = xp[j] * scale * norm_w[ch];
        float gv = v * 0.5f * (1.f + erff(v * 0.70710678118654752f));
        g_xnh[base + ch] = __float2half(v);
        g_xgh[base + ch] = __float2half(gv);
    }
}

// ---------------- kernel: pos features @ Wpos + bpos (split fp16 out) ---------
__global__ __launch_bounds__(128) void pos_kernel(
    const float* __restrict__ Wpos, const float* __restrict__ bpos)
{
    int d   = blockIdx.x;
    int tid = threadIdx.x;
    __shared__ float feat[32];

    int rel = d - P_;
    if (tid < 16) {
        double geo = exp((double)tid * (log(497.0) / 16.0));
        float center = (float)tid + (float)geo;
        float oh = (center > fabsf((float)rel)) ? 1.f : 0.f;
        float sg = (rel > 0) ? 1.f : ((rel < 0) ? -1.f : 0.f);
        feat[tid]      = oh;
        feat[tid + 16] = oh * sg;
    }
    __syncthreads();

    float f[32];
#pragma unroll
    for (int c = 0; c < 32; c++) f[c] = feat[c];

    for (int n = tid; n < HF; n += 128) {
        float acc = bpos[n];
#pragma unroll
        for (int c = 0; c < 32; c++) acc += f[c] * Wpos[c * HF + n];
        __half h = __float2half(acc);
        g_posh[(size_t)d * HF + n] = h;
        g_posl[(size_t)d * HF + n] = __float2half(acc - __half2float(h));
    }
}

// ---------------- kernel: rel-bias tables Bias[sel][h][d] = 0.25*rb·pos -------
__global__ __launch_bounds__(256) void bias_kernel(
    const float* __restrict__ qrb, const float* __restrict__ krb)
{
    int d = blockIdx.x;
    int lane = threadIdx.x & 31, w = threadIdx.x >> 5;
    for (int h = w; h < H_; h += 8) {
        float sq = 0.f, sk = 0.f;
        size_t pb = (size_t)d * HF + h * F_;
        for (int c = lane; c < F_; c += 32) {
            float pv = __half2float(g_posh[pb + c]) + __half2float(g_posl[pb + c]);
            sq += qrb[h * F_ + c] * pv;
            sk += krb[h * F_ + c] * pv;
        }
#pragma unroll
        for (int o = 16; o; o >>= 1) {
            sq += __shfl_xor_sync(0xffffffffu, sq, o);
            sk += __shfl_xor_sync(0xffffffffu, sk, o);
        }
        if (lane == 0) {
            g_bias[h * P2 + d]           = 0.25f * sq;
            g_bias[H_ * P2 + h * P2 + d] = 0.25f * sk;
        }
    }
}

// ---------------- kernel: weight transpose-convert W[K,N] -> T[N,K] split -----
__global__ __launch_bounds__(256) void wconv_kernel(
    const float* __restrict__ W, fp16* __restrict__ Th, fp16* __restrict__ Tl,
    int K, int N)
{
    __shared__ float t[32][33];
    int nt0 = blockIdx.x * 32, kt0 = blockIdx.y * 32;
    int tx = threadIdx.x & 31, ty = threadIdx.x >> 5;
#pragma unroll
    for (int i = 0; i < 4; i++)
        t[ty + i * 8][tx] = W[(size_t)(kt0 + ty + i * 8) * N + nt0 + tx];
    __syncthreads();
#pragma unroll
    for (int i = 0; i < 4; i++) {
        int n = nt0 + ty + i * 8, k = kt0 + tx;
        float v = t[tx][ty + i * 8];
        __half h = __float2half(v);
        Th[(size_t)n * K + k] = h;
        Tl[(size_t)n * K + k] = __float2half(v - __half2float(h));
    }
}

// ---------------- kernel: projection GEMM (q/k) -------------------------------
__global__ __launch_bounds__(256, 2) void proj_gemm(
    const fp16* __restrict__ Ah,
    const fp16* __restrict__ Bh, const fp16* __restrict__ Bl,
    fp16* __restrict__ Oh, fp16* __restrict__ Ol)
{
    GEMM_PREAMBLE
    int rowA0 = blockIdx.y * 128, col0 = blockIdx.x * 128;
    GEMM_MAIN(Ah, Bh, Bl, C_, C_, 0, C_ / 32);

    uint32_t* oh = (uint32_t*)Oh;
    uint32_t* ol = (uint32_t*)Ol;
#pragma unroll
    for (int mt = 0; mt < 2; mt++)
#pragma unroll
        for (int nt = 0; nt < 8; nt++) {
            int r = rowA0 + m0 + mt * 16 + g;
            int n = col0 + n0 + nt * 8 + tig * 2;
            uint32_t hw, lw;
            size_t ix0 = ((size_t)r * HF + n) >> 1;
            size_t ix1 = ((size_t)(r + 8) * HF + n) >> 1;
            hsplit2(acc[mt][nt][0], acc[mt][nt][1], hw, lw);
            oh[ix0] = hw;
            if (ol) ol[ix0] = lw;
            hsplit2(acc[mt][nt][2], acc[mt][nt][3], hw, lw);
            oh[ix1] = hw;
            if (ol) ol[ix1] = lw;
        }
}

// ---------------- kernel: yq/yk GEMM, split-K x4 -------------------------------
__global__ __launch_bounds__(256, 2) void y_gemm(
    const fp16* __restrict__ Ah,
    const fp16* __restrict__ B0h, const fp16* __restrict__ B0l,
    const fp16* __restrict__ B1h, const fp16* __restrict__ B1l,
    float* __restrict__ ypart)
{
    GEMM_PREAMBLE
    int z = blockIdx.z;
    const fp16* Bh = (z >= 4) ? B1h : B0h;
    const fp16* Bl = (z >= 4) ? B1l : B0l;
    int kb = (z & 3) * 384;
    int rowA0 = blockIdx.y * 128, col0 = 0;
    GEMM_MAIN(Ah, Bh, Bl, C_, C_, kb, 12);
    float* C = ypart + (size_t)z * M_ * F_;
    EPI_F32(C, F_, 1.0f)
}

// ---------------- kernel: QK GEMM (fp16 out) -----------------------------------
__global__ __launch_bounds__(256, 2) void qk_gemm(
    const fp16* __restrict__ Ahb,
    const fp16* __restrict__ Bhb, const fp16* __restrict__ Blb,
    fp16* __restrict__ Cbase)
{
    GEMM_PREAMBLE
    int z = blockIdx.z, b = z >> 5, h = z & 31;
    const fp16* Ah = Ahb + (size_t)b * P_ * HF + h * F_;
    const fp16* Bh = Bhb + (size_t)b * P_ * HF + h * F_;
    const fp16* Bl = Blb + (size_t)b * P_ * HF + h * F_;
    __half2* C = (__half2*)(Cbase + (size_t)z * P_ * P_);
    int rowA0 = blockIdx.y * 128, col0 = blockIdx.x * 128;
    GEMM_MAIN(Ah, Bh, Bl, HF, HF, 0, 4);

#pragma unroll
    for (int mt = 0; mt < 2; mt++)
#pragma unroll
        for (int nt = 0; nt < 8; nt++) {
            int r = rowA0 + m0 + mt * 16 + g;
            int cix = col0 + n0 + nt * 8 + tig * 2;
            C[((size_t)r * P_ + cix) >> 1] =
                __floats2half2_rn(acc[mt][nt][0], acc[mt][nt][1]);
            C[((size_t)(r + 8) * P_ + cix) >> 1] =
                __floats2half2_rn(acc[mt][nt][2], acc[mt][nt][3]);
        }
}

// ---------------- kernel: Qp+Kp merged band GEMM (fp16 out) --------------------
__global__ __launch_bounds__(256, 2) void qpkp_gemm(
    const fp16* __restrict__ qA, const fp16* __restrict__ kA,
    const fp16* __restrict__ Bh, const fp16* __restrict__ Bl,
    fp16* __restrict__ Qp, fp16* __restrict__ Kp,
    const float* __restrict__ biasT)
{
    GEMM_PREAMBLE
    int z = blockIdx.z;
    int sel = z >> 6, zz = z & 63, b = zz >> 5, h = zz & 31;
    int i = blockIdx.x;
    int ty = i / 5, tx = 3 - ty + (i % 5);
    const fp16* Ahp = (sel ? kA : qA) + (size_t)b * P_ * HF + h * F_;
    const fp16* Bhp = Bh + (size_t)h * F_;   // FIX: head slice of pos_enc
    const fp16* Blp = Bl + (size_t)h * F_;   // FIX: head slice of pos_enc
    __half2* C = (__half2*)((sel ? Kp : Qp) + (size_t)zz * P_ * P2);
    const float* bp = biasT + (size_t)sel * H_ * P2 + (size_t)h * P2;
    int rowA0 = ty * 128, col0 = tx * 128;
    GEMM_MAIN(Ahp, Bhp, Blp, HF, HF, 0, 4);

#pragma unroll
    for (int mt = 0; mt < 2; mt++)
#pragma unroll
        for (int nt = 0; nt < 8; nt++) {
            int r = rowA0 + m0 + mt * 16 + g;
            int cix = col0 + n0 + nt * 8 + tig * 2;
            float2 bb = *(const float2*)(bp + cix);
            C[((size_t)r * P2 + cix) >> 1] =
                __floats2half2_rn(acc[mt][nt][0] * 0.25f + bb.x,
                                  acc[mt][nt][1] * 0.25f + bb.y);
            C[((size_t)(r + 8) * P2 + cix) >> 1] =
                __floats2half2_rn(acc[mt][nt][2] * 0.25f + bb.x,
                                  acc[mt][nt][3] * 0.25f + bb.y);
        }
}

// ---------------- kernel: fused gather + a@Wout epilogue ----------------------
#define A_QSTRIDE 1057
#define A_KSTRIDE 33
#define SMEM_FINAL ((32 * A_QSTRIDE + 2 * 32 * 128) * 4)
#define M128 (M_ * F_)

__global__ __launch_bounds__(256) void final_kernel(
    const fp16* __restrict__ QK, const fp16* __restrict__ Qp,
    const fp16* __restrict__ Kp, const float* __restrict__ ypart,
    const float* __restrict__ Wout, const float* __restrict__ bout,
    float* __restrict__ out)
{
    extern __shared__ float smem[];
    float* a_s  = smem;
    float* yq_s = smem + 32 * A_QSTRIDE;
    float* yk_s = yq_s + 32 * 128;

    int b  = blockIdx.z;
    int qt = blockIdx.y * 32;
    int kt = blockIdx.x * 32;
    int tid = threadIdx.x;

    for (int i = tid; i < 32 * 128; i += 256) {
        int q = i >> 7, f = i & 127;
        size_t rq = ((size_t)(b * P_ + qt + q)) * F_ + f;
        size_t rk = ((size_t)(b * P_ + kt + q)) * F_ + f;
        float vq = 0.f, vk = 0.f;
#pragma unroll
        for (int s = 0; s < 4; s++) {
            vq += ypart[(size_t)s * M128 + rq];
            vk += ypart[(size_t)(4 + s) * M128 + rk];
        }
        yq_s[i] = vq;
        yk_s[i] = vk;
    }

    for (int i = tid; i < 32 * 32 * 32; i += 256) {
        int h = i >> 10, q = (i >> 5) & 31, k = i & 31;
        int gq = qt + q, gk = kt + k;
        size_t zb = (size_t)(b * 32 + h);
        float v = __half2float(QK[(zb * P_ + gq) * P_ + gk])
                + __half2float(Qp[(zb * P_ + gq) * P2 + (P_ + gk - gq)]);
        a_s[q * A_QSTRIDE + k * A_KSTRIDE + h] = v;
    }
    __syncthreads();

    for (int i = tid; i < 32 * 32 * 32; i += 256) {
        int h = i >> 10, k = (i >> 5) & 31, q = i & 31;
        int gq = qt + q, gk = kt + k;
        size_t zb = (size_t)(b * 32 + h);
        a_s[q * A_QSTRIDE + k * A_KSTRIDE + h] +=
            __half2float(Kp[(zb * P_ + gk) * P2 + (P_ + gq - gk)]);
    }
    __syncthreads();

    int lane = tid & 31, warp = tid >> 5;
    float w[32][4];
#pragma unroll
    for (int h = 0; h < 32; h++)
#pragma unroll
        for (int j = 0; j < 4; j++) w[h][j] = Wout[h * F_ + lane + j * 32];
    float bo[4];
#pragma unroll
    for (int j = 0; j < 4; j++) bo[j] = bout[lane + j * 32];

    for (int p = warp; p < 1024; p += 8) {
        int q = p >> 5, k = p & 31;
        const float* ap = a_s + q * A_QSTRIDE + k * A_KSTRIDE;
        float acc[4];
#pragma unroll
        for (int j = 0; j < 4; j++)
            acc[j] = bo[j] + yq_s[q * 128 + lane + j * 32]
                           + yk_s[k * 128 + lane + j * 32];
#pragma unroll
        for (int h = 0; h < 32; h++) {
            float ah = ap[h];
#pragma unroll
            for (int j = 0; j < 4; j++) acc[j] += ah * w[h][j];
        }
        float* orow = out + (((size_t)(b * P_) + qt + q) * P_ + kt + k) * F_ + lane;
#pragma unroll
        for (int j = 0; j < 4; j++) orow[j * 32] = acc[j];
    }
}

// ---------------- launch ------------------------------------------------------
extern "C" void kernel_launch(void* const* d_in, const int* in_sizes, int n_in,
                              void* d_out, int out_size)
{
    const float* x        = (const float*)d_in[0];
    const float* norm_w   = (const float*)d_in[1];
    const float* Wq       = (const float*)d_in[2];
    const float* Wk       = (const float*)d_in[3];
    const float* Wpos     = (const float*)d_in[4];
    const float* bpos     = (const float*)d_in[5];
    const float* q_r_bias = (const float*)d_in[6];
    const float* k_r_bias = (const float*)d_in[7];
    const float* Wyq      = (const float*)d_in[8];
    const float* Wyk      = (const float*)d_in[9];
    const float* Wout     = (const float*)d_in[10];
    const float* bout     = (const float*)d_in[11];
    float* out = (float*)d_out;

    fp16 *p_xnh, *p_xgh;
    fp16 *p_wqth, *p_wqtl, *p_wkth, *p_wktl, *p_wyqh, *p_wyql, *p_wykh, *p_wykl;
    fp16 *p_posh, *p_posl, *p_qh, *p_kh, *p_kl, *p_QK, *p_Qp, *p_Kp;
    float *p_bias, *p_ypart;
    cudaGetSymbolAddress((void**)&p_xnh,  g_xnh);
    cudaGetSymbolAddress((void**)&p_xgh,  g_xgh);
    cudaGetSymbolAddress((void**)&p_wqth, g_wqth);
    cudaGetSymbolAddress((void**)&p_wqtl, g_wqtl);
    cudaGetSymbolAddress((void**)&p_wkth, g_wkth);
    cudaGetSymbolAddress((void**)&p_wktl, g_wktl);
    cudaGetSymbolAddress((void**)&p_wyqh, g_wyqh);
    cudaGetSymbolAddress((void**)&p_wyql, g_wyql);
    cudaGetSymbolAddress((void**)&p_wykh, g_wykh);
    cudaGetSymbolAddress((void**)&p_wykl, g_wykl);
    cudaGetSymbolAddress((void**)&p_posh, g_posh);
    cudaGetSymbolAddress((void**)&p_posl, g_posl);
    cudaGetSymbolAddress((void**)&p_qh,   g_qh);
    cudaGetSymbolAddress((void**)&p_kh,   g_kh);
    cudaGetSymbolAddress((void**)&p_kl,   g_kl);
    cudaGetSymbolAddress((void**)&p_bias, g_bias);
    cudaGetSymbolAddress((void**)&p_ypart, g_ypart);
    cudaGetSymbolAddress((void**)&p_QK,   g_QK);
    cudaGetSymbolAddress((void**)&p_Qp,   g_Qp);
    cudaGetSymbolAddress((void**)&p_Kp,   g_Kp);

    cudaFuncSetAttribute(proj_gemm, cudaFuncAttributeMaxDynamicSharedMemorySize, GEMM_SMEM);
    cudaFuncSetAttribute(y_gemm,    cudaFuncAttributeMaxDynamicSharedMemorySize, GEMM_SMEM);
    cudaFuncSetAttribute(qk_gemm,   cudaFuncAttributeMaxDynamicSharedMemorySize, GEMM_SMEM);
    cudaFuncSetAttribute(qpkp_gemm, cudaFuncAttributeMaxDynamicSharedMemorySize, GEMM_SMEM);
    cudaFuncSetAttribute(final_kernel, cudaFuncAttributeMaxDynamicSharedMemorySize, SMEM_FINAL);

    wconv_kernel<<<dim3(128, 48), 256>>>(Wq, p_wqth, p_wqtl, C_, HF);  // 0
    wconv_kernel<<<dim3(128, 48), 256>>>(Wk, p_wkth, p_wktl, C_, HF);  // 1
    pool_norm_kernel<<<1024, 256>>>(x, norm_w);                        // 2
    proj_gemm<<<dim3(32, 8), 256, GEMM_SMEM>>>(                        // 3
        p_xnh, p_wqth, p_wqtl, p_qh, (fp16*)0);
    proj_gemm<<<dim3(32, 8), 256, GEMM_SMEM>>>(                        // 4
        p_xnh, p_wkth, p_wktl, p_kh, p_kl);

    pos_kernel<<<1024, 128>>>(Wpos, bpos);
    bias_kernel<<<1024, 256>>>(q_r_bias, k_r_bias);
    wconv_kernel<<<dim3(4, 48), 256>>>(Wyq, p_wyqh, p_wyql, C_, F_);
    wconv_kernel<<<dim3(4, 48), 256>>>(Wyk, p_wykh, p_wykl, C_, F_);
    y_gemm<<<dim3(1, 8, 8), 256, GEMM_SMEM>>>(
        p_xgh, p_wyqh, p_wyql, p_wykh, p_wykl, p_ypart);

    qk_gemm<<<dim3(4, 4, 64), 256, GEMM_SMEM>>>(p_qh, p_kh, p_kl, p_QK);
    qpkp_gemm<<<dim3(20, 1, 128), 256, GEMM_SMEM>>>(
        p_qh, p_kh, p_posh, p_posl, p_Qp, p_Kp, p_bias);

    final_kernel<<<dim3(16, 16, 2), 256, SMEM_FINAL>>>(
        p_QK, p_Qp, p_Kp, p_ypart, Wout, bout, out);
}

// round 11
// speedup vs baseline: 1.0568x; 1.0148x over previous
#include <cuda_runtime.h>
#include <cuda_fp16.h>
#include <math.h>
#include <stdint.h>

typedef __half fp16;

#define B_   2
#define S_   8192
#define C_   1536
#define P_   512
#define H_   32
#define F_   128
#define HF   4096
#define P2   1024
#define M_   1024     // B_*P_

// ---------------- scratch (device globals) ------------------------------------
__device__ __align__(16) fp16 g_xnh[M_ * C_];
__device__ __align__(16) fp16 g_xgh[M_ * C_];
__device__ __align__(16) fp16 g_wqth[HF * C_], g_wqtl[HF * C_];
__device__ __align__(16) fp16 g_wkth[HF * C_], g_wktl[HF * C_];
__device__ __align__(16) fp16 g_wyqh[F_ * C_], g_wyql[F_ * C_];
__device__ __align__(16) fp16 g_wykh[F_ * C_], g_wykl[F_ * C_];
__device__ __align__(16) fp16 g_posh[P2 * HF], g_posl[P2 * HF];
__device__ __align__(16) fp16 g_qh [M_ * HF];
__device__ __align__(16) fp16 g_kh [M_ * HF], g_kl[M_ * HF];
__device__ float g_bias [2 * H_ * P2];
__device__ float g_ypart[8 * M_ * F_];
__device__ __align__(16) fp16 g_QK [(size_t)B_ * H_ * P_ * P_];
__device__ __align__(16) fp16 g_Qp [(size_t)B_ * H_ * P_ * P2];
__device__ __align__(16) fp16 g_Kp [(size_t)B_ * H_ * P_ * P2];

// ---------------- helpers ------------------------------------------------------
__device__ __forceinline__ void hsplit2(float x, float y, uint32_t& hw, uint32_t& lw)
{
    __half hx = __float2half(x);
    __half hy = __float2half(y);
    __half lx = __float2half(x - __half2float(hx));
    __half ly = __float2half(y - __half2float(hy));
    __half2 hp = __halves2half2(hx, hy);
    __half2 lp = __halves2half2(lx, ly);
    hw = *reinterpret_cast<uint32_t*>(&hp);
    lw = *reinterpret_cast<uint32_t*>(&lp);
}

__device__ __forceinline__ void cp16(uint32_t* smem_ptr, const fp16* gptr)
{
    uint32_t s = (uint32_t)__cvta_generic_to_shared(smem_ptr);
    asm volatile("cp.async.cg.shared.global [%0], [%1], 16;\n" :: "r"(s), "l"(gptr));
}

#define MMA_FP16(c, a, b)                                                       \
    asm volatile(                                                               \
        "mma.sync.aligned.m16n8k16.row.col.f32.f16.f16.f32 "                    \
        "{%0,%1,%2,%3}, {%4,%5,%6,%7}, {%8,%9}, {%0,%1,%2,%3};\n"               \
        : "+f"((c)[0]), "+f"((c)[1]), "+f"((c)[2]), "+f"((c)[3])                \
        : "r"((a)[0]), "r"((a)[1]), "r"((a)[2]), "r"((a)[3]),                   \
          "r"((b)[0]), "r"((b)[1]))

#define LDSM4(d0, d1, d2, d3, a)                                                \
    asm volatile(                                                               \
        "ldmatrix.sync.aligned.m8n8.x4.shared.b16 {%0,%1,%2,%3}, [%4];\n"       \
        : "=r"(d0), "=r"(d1), "=r"(d2), "=r"(d3) : "r"(a))

// one k16 sub-step, 4(m)x2(n) warp layout: 10 LDSM.x4 + 32 MMAs per warp
#define FRAG_LDSM(sst, j0)                                                      \
    do {                                                                        \
        uint32_t ah[2][4], bh[8][2], bl[8][2];                                  \
        _Pragma("unroll")                                                       \
        for (int mt = 0; mt < 2; mt++) {                                        \
            uint32_t aa = (sst) + aoff + mt * 1280u + (j0) * 4u;                \
            LDSM4(ah[mt][0], ah[mt][1], ah[mt][2], ah[mt][3], aa);              \
        }                                                                       \
        _Pragma("unroll")                                                       \
        for (int tp = 0; tp < 4; tp++) {                                        \
            uint32_t ba = (sst) + boff + tp * 1280u + (j0) * 4u + 10240u;       \
            LDSM4(bh[2*tp][0], bh[2*tp+1][0], bh[2*tp][1], bh[2*tp+1][1], ba);  \
            LDSM4(bl[2*tp][0], bl[2*tp+1][0], bl[2*tp][1], bl[2*tp+1][1],       \
                  ba + 10240u);                                                 \
        }                                                                       \
        _Pragma("unroll")                                                       \
        for (int mt = 0; mt < 2; mt++)                                          \
            _Pragma("unroll")                                                   \
            for (int nt = 0; nt < 8; nt++) {                                    \
                MMA_FP16(acc[mt][nt], ah[mt], bh[nt]);                          \
                MMA_FP16(acc[mt][nt], ah[mt], bl[nt]);                          \
            }                                                                   \
    } while (0)

// stage = [Ah 10240B][Bh 10240B][Bl 10240B] = 30720B; 3 stages
#define LOAD_STAGE(s, kpos, Ah, Bh, Bl, lda, ldb)                               \
    {                                                                           \
        uint32_t* sb = sm + (s) * 7680;                                         \
        _Pragma("unroll")                                                       \
        for (int ci = 0; ci < 2; ci++) {                                        \
            int qq = tid + ci * 256;                                            \
            int rw = qq >> 2, cc = qq & 3;                                      \
            uint32_t so = rw * 20 + cc * 4;                                     \
            size_t ga = (size_t)(rowA0 + rw) * (lda) + (kpos) + cc * 8;         \
            size_t gb = (size_t)(col0 + rw) * (ldb) + (kpos) + cc * 8;          \
            cp16(sb + so,        (Ah) + ga);                                    \
            cp16(sb + 2560 + so, (Bh) + gb);                                    \
            cp16(sb + 5120 + so, (Bl) + gb);                                    \
        }                                                                       \
    }

// 3-stage cp.async pipeline (requires nk >= 2)
#define GEMM_MAIN(Ah, Bh, Bl, lda, ldb, kb, nk)                                 \
    {                                                                           \
        LOAD_STAGE(0, (kb), Ah, Bh, Bl, lda, ldb);                              \
        asm volatile("cp.async.commit_group;\n");                               \
        LOAD_STAGE(1, (kb) + 32, Ah, Bh, Bl, lda, ldb);                         \
        asm volatile("cp.async.commit_group;\n");                               \
        for (int it = 0; it < (nk); it++) {                                     \
            if (it + 2 < (nk)) asm volatile("cp.async.wait_group 1;\n");        \
            else               asm volatile("cp.async.wait_group 0;\n");        \
            __syncthreads();                                                    \
            uint32_t sst = smb + (uint32_t)((it % 3) * 30720);                  \
            FRAG_LDSM(sst, 0);                                                  \
            if (it + 2 < (nk)) {                                                \
                LOAD_STAGE((it + 2) % 3, (kb) + (it + 2) * 32,                  \
                           Ah, Bh, Bl, lda, ldb);                               \
                asm volatile("cp.async.commit_group;\n");                       \
            }                                                                   \
            FRAG_LDSM(sst, 8);                                                  \
        }                                                                       \
    }

// 4(m) x 2(n) warp layout
#define GEMM_PREAMBLE                                                           \
    extern __shared__ uint32_t sm[];                                            \
    uint32_t smb = (uint32_t)__cvta_generic_to_shared(sm);                      \
    int tid = threadIdx.x;                                                      \
    int warp = tid >> 5, lane = tid & 31;                                       \
    int g = lane >> 2, tig = lane & 3;                                          \
    int lr = lane & 15, lh = lane >> 4;                                         \
    int m0 = (warp >> 1) * 32, n0 = (warp & 1) * 64;                            \
    uint32_t aoff = ((m0 + lr) * 20 + lh * 4) * 4;                              \
    uint32_t boff = ((n0 + lr) * 20 + lh * 4) * 4;                              \
    float acc[2][8][4];                                                         \
    _Pragma("unroll")                                                           \
    for (int i = 0; i < 2; i++)                                                 \
        _Pragma("unroll")                                                       \
        for (int j = 0; j < 8; j++)                                             \
            _Pragma("unroll")                                                   \
            for (int l = 0; l < 4; l++) acc[i][j][l] = 0.f;

#define EPI_F32(Cp, ldc, alpha)                                                 \
    _Pragma("unroll")                                                           \
    for (int mt = 0; mt < 2; mt++)                                              \
        _Pragma("unroll")                                                       \
        for (int nt = 0; nt < 8; nt++) {                                        \
            int r = rowA0 + m0 + mt * 16 + g;                                   \
            int cix = col0 + n0 + nt * 8 + tig * 2;                             \
            *(float2*)((Cp) + (size_t)r * (ldc) + cix) =                        \
                make_float2(acc[mt][nt][0] * (alpha), acc[mt][nt][1] * (alpha));\
            *(float2*)((Cp) + (size_t)(r + 8) * (ldc) + cix) =                  \
                make_float2(acc[mt][nt][2] * (alpha), acc[mt][nt][3] * (alpha));\
        }

#define GEMM_SMEM 92160

// ---------------- kernel: pool + RMS norm + GELU (hi fp16 out) ----------------
__global__ __launch_bounds__(256) void pool_norm_kernel(
    const float* __restrict__ x, const float* __restrict__ norm_w)
{
    int bid = blockIdx.x;
    int b = bid >> 9, p = bid & 511;
    int tid = threadIdx.x;

    const float* xrow = x + ((size_t)b * S_ + (size_t)p * 16) * C_;
    float xp[6];
#pragma unroll
    for (int j = 0; j < 6; j++) xp[j] = 0.f;
    for (int r = 0; r < 16; r++) {
        const float* xr = xrow + (size_t)r * C_;
#pragma unroll
        for (int j = 0; j < 6; j++) xp[j] += xr[tid + j * 256];
    }
    float ssq = 0.f;
#pragma unroll
    for (int j = 0; j < 6; j++) { xp[j] *= (1.f / 16.f); ssq += xp[j] * xp[j]; }

    __shared__ float red[256];
    red[tid] = ssq;
    __syncthreads();
    for (int s = 128; s > 0; s >>= 1) {
        if (tid < s) red[tid] += red[tid + s];
        __syncthreads();
    }
    float scale = 1.f / sqrtf(red[0] * (1.f / (float)C_) + 1e-8f);

    size_t base = (size_t)bid * C_;
#pragma unroll
    for (int j = 0; j < 6; j++) {
        int ch = tid + j * 256;
        float v = xp[j] * scale * norm_w[ch];
        float gv = v * 0.5f * (1.f + erff(v * 0.70710678118654752f));
        g_xnh[base + ch] = __float2half(v);
        g_xgh[base + ch] = __float2half(gv);
    }
}

// ---------------- kernel: pos features @ Wpos + bpos (split fp16 out) ---------
__global__ __launch_bounds__(128) void pos_kernel(
    const float* __restrict__ Wpos, const float* __restrict__ bpos)
{
    int d   = blockIdx.x;
    int tid = threadIdx.x;
    __shared__ float feat[32];

    int rel = d - P_;
    if (tid < 16) {
        double geo = exp((double)tid * (log(497.0) / 16.0));
        float center = (float)tid + (float)geo;
        float oh = (center > fabsf((float)rel)) ? 1.f : 0.f;
        float sg = (rel > 0) ? 1.f : ((rel < 0) ? -1.f : 0.f);
        feat[tid]      = oh;
        feat[tid + 16] = oh * sg;
    }
    __syncthreads();

    float f[32];
#pragma unroll
    for (int c = 0; c < 32; c++) f[c] = feat[c];

    for (int n = tid; n < HF; n += 128) {
        float acc = bpos[n];
#pragma unroll
        for (int c = 0; c < 32; c++) acc += f[c] * Wpos[c * HF + n];
        __half h = __float2half(acc);
        g_posh[(size_t)d * HF + n] = h;
        g_posl[(size_t)d * HF + n] = __float2half(acc - __half2float(h));
    }
}

// ---------------- kernel: rel-bias tables Bias[sel][h][d] = 0.25*rb·pos -------
__global__ __launch_bounds__(256) void bias_kernel(
    const float* __restrict__ qrb, const float* __restrict__ krb)
{
    int d = blockIdx.x;
    int lane = threadIdx.x & 31, w = threadIdx.x >> 5;
    for (int h = w; h < H_; h += 8) {
        float sq = 0.f, sk = 0.f;
        size_t pb = (size_t)d * HF + h * F_;
        for (int c = lane; c < F_; c += 32) {
            float pv = __half2float(g_posh[pb + c]) + __half2float(g_posl[pb + c]);
            sq += qrb[h * F_ + c] * pv;
            sk += krb[h * F_ + c] * pv;
        }
#pragma unroll
        for (int o = 16; o; o >>= 1) {
            sq += __shfl_xor_sync(0xffffffffu, sq, o);
            sk += __shfl_xor_sync(0xffffffffu, sk, o);
        }
        if (lane == 0) {
            g_bias[h * P2 + d]           = 0.25f * sq;
            g_bias[H_ * P2 + h * P2 + d] = 0.25f * sk;
        }
    }
}

// ---------------- kernel: weight transpose-convert W[K,N] -> T[N,K] split -----
__global__ __launch_bounds__(256) void wconv_kernel(
    const float* __restrict__ W, fp16* __restrict__ Th, fp16* __restrict__ Tl,
    int K, int N)
{
    __shared__ float t[32][33];
    int nt0 = blockIdx.x * 32, kt0 = blockIdx.y * 32;
    int tx = threadIdx.x & 31, ty = threadIdx.x >> 5;
#pragma unroll
    for (int i = 0; i < 4; i++)
        t[ty + i * 8][tx] = W[(size_t)(kt0 + ty + i * 8) * N + nt0 + tx];
    __syncthreads();
#pragma unroll
    for (int i = 0; i < 4; i++) {
        int n = nt0 + ty + i * 8, k = kt0 + tx;
        float v = t[tx][ty + i * 8];
        __half h = __float2half(v);
        Th[(size_t)n * K + k] = h;
        Tl[(size_t)n * K + k] = __float2half(v - __half2float(h));
    }
}

// ---------------- kernel: projection GEMM (q/k) -------------------------------
__global__ __launch_bounds__(256, 2) void proj_gemm(
    const fp16* __restrict__ Ah,
    const fp16* __restrict__ Bh, const fp16* __restrict__ Bl,
    fp16* __restrict__ Oh, fp16* __restrict__ Ol)
{
    GEMM_PREAMBLE
    int rowA0 = blockIdx.y * 128, col0 = blockIdx.x * 128;
    GEMM_MAIN(Ah, Bh, Bl, C_, C_, 0, C_ / 32);

    uint32_t* oh = (uint32_t*)Oh;
    uint32_t* ol = (uint32_t*)Ol;
#pragma unroll
    for (int mt = 0; mt < 2; mt++)
#pragma unroll
        for (int nt = 0; nt < 8; nt++) {
            int r = rowA0 + m0 + mt * 16 + g;
            int n = col0 + n0 + nt * 8 + tig * 2;
            uint32_t hw, lw;
            size_t ix0 = ((size_t)r * HF + n) >> 1;
            size_t ix1 = ((size_t)(r + 8) * HF + n) >> 1;
            hsplit2(acc[mt][nt][0], acc[mt][nt][1], hw, lw);
            oh[ix0] = hw;
            if (ol) ol[ix0] = lw;
            hsplit2(acc[mt][nt][2], acc[mt][nt][3], hw, lw);
            oh[ix1] = hw;
            if (ol) ol[ix1] = lw;
        }
}

// ---------------- kernel: yq/yk GEMM, split-K x4 -------------------------------
__global__ __launch_bounds__(256, 2) void y_gemm(
    const fp16* __restrict__ Ah,
    const fp16* __restrict__ B0h, const fp16* __restrict__ B0l,
    const fp16* __restrict__ B1h, const fp16* __restrict__ B1l,
    float* __restrict__ ypart)
{
    GEMM_PREAMBLE
    int z = blockIdx.z;
    const fp16* Bh = (z >= 4) ? B1h : B0h;
    const fp16* Bl = (z >= 4) ? B1l : B0l;
    int kb = (z & 3) * 384;
    int rowA0 = blockIdx.y * 128, col0 = 0;
    GEMM_MAIN(Ah, Bh, Bl, C_, C_, kb, 12);
    float* C = ypart + (size_t)z * M_ * F_;
    EPI_F32(C, F_, 1.0f)
}

// ---------------- kernel: QK GEMM (fp16 out) -----------------------------------
__global__ __launch_bounds__(256, 2) void qk_gemm(
    const fp16* __restrict__ Ahb,
    const fp16* __restrict__ Bhb, const fp16* __restrict__ Blb,
    fp16* __restrict__ Cbase)
{
    GEMM_PREAMBLE
    int z = blockIdx.z, b = z >> 5, h = z & 31;
    const fp16* Ah = Ahb + (size_t)b * P_ * HF + h * F_;
    const fp16* Bh = Bhb + (size_t)b * P_ * HF + h * F_;
    const fp16* Bl = Blb + (size_t)b * P_ * HF + h * F_;
    __half2* C = (__half2*)(Cbase + (size_t)z * P_ * P_);
    int rowA0 = blockIdx.y * 128, col0 = blockIdx.x * 128;
    GEMM_MAIN(Ah, Bh, Bl, HF, HF, 0, 4);

#pragma unroll
    for (int mt = 0; mt < 2; mt++)
#pragma unroll
        for (int nt = 0; nt < 8; nt++) {
            int r = rowA0 + m0 + mt * 16 + g;
            int cix = col0 + n0 + nt * 8 + tig * 2;
            C[((size_t)r * P_ + cix) >> 1] =
                __floats2half2_rn(acc[mt][nt][0], acc[mt][nt][1]);
            C[((size_t)(r + 8) * P_ + cix) >> 1] =
                __floats2half2_rn(acc[mt][nt][2], acc[mt][nt][3]);
        }
}

// ---------------- kernel: Qp+Kp merged band GEMM (fp16 out) --------------------
__global__ __launch_bounds__(256, 2) void qpkp_gemm(
    const fp16* __restrict__ qA, const fp16* __restrict__ kA,
    const fp16* __restrict__ Bh, const fp16* __restrict__ Bl,
    fp16* __restrict__ Qp, fp16* __restrict__ Kp,
    const float* __restrict__ biasT)
{
    GEMM_PREAMBLE
    int z = blockIdx.z;
    int sel = z >> 6, zz = z & 63, b = zz >> 5, h = zz & 31;
    int i = blockIdx.x;
    int ty = i / 5, tx = 3 - ty + (i % 5);
    const fp16* Ahp = (sel ? kA : qA) + (size_t)b * P_ * HF + h * F_;
    const fp16* Bhp = Bh + (size_t)h * F_;
    const fp16* Blp = Bl + (size_t)h * F_;
    __half2* C = (__half2*)((sel ? Kp : Qp) + (size_t)zz * P_ * P2);
    const float* bp = biasT + (size_t)sel * H_ * P2 + (size_t)h * P2;
    int rowA0 = ty * 128, col0 = tx * 128;
    GEMM_MAIN(Ahp, Bhp, Blp, HF, HF, 0, 4);

#pragma unroll
    for (int mt = 0; mt < 2; mt++)
#pragma unroll
        for (int nt = 0; nt < 8; nt++) {
            int r = rowA0 + m0 + mt * 16 + g;
            int cix = col0 + n0 + nt * 8 + tig * 2;
            float2 bb = *(const float2*)(bp + cix);
            C[((size_t)r * P2 + cix) >> 1] =
                __floats2half2_rn(acc[mt][nt][0] * 0.25f + bb.x,
                                  acc[mt][nt][1] * 0.25f + bb.y);
            C[((size_t)(r + 8) * P2 + cix) >> 1] =
                __floats2half2_rn(acc[mt][nt][2] * 0.25f + bb.x,
                                  acc[mt][nt][3] * 0.25f + bb.y);
        }
}

// ---------------- kernel: fused gather + HMMA a@Wout epilogue ------------------
// a_s rows = m = q*32+k (1024), cols = h (32), fp16, row stride 40 fp16 (80B)
#define FIN_A   0
#define FIN_YQ  81920
#define FIN_YK  (FIN_YQ + 16384)
#define FIN_WH  (FIN_YK + 16384)
#define FIN_WL  (FIN_WH + 10240)
#define SMEM_FINAL (FIN_WL + 10240)
#define M128 (M_ * F_)

__global__ __launch_bounds__(256) void final_kernel(
    const fp16* __restrict__ QK, const fp16* __restrict__ Qp,
    const fp16* __restrict__ Kp, const float* __restrict__ ypart,
    const float* __restrict__ Wout, const float* __restrict__ bout,
    float* __restrict__ out)
{
    extern __shared__ char smem[];
    __half* a_s  = (__half*)smem;
    float*  yq_s = (float*)(smem + FIN_YQ);
    float*  yk_s = (float*)(smem + FIN_YK);
    __half* wh_s = (__half*)(smem + FIN_WH);
    __half* wl_s = (__half*)(smem + FIN_WL);
    uint32_t smb = (uint32_t)__cvta_generic_to_shared(smem);

    int b  = blockIdx.z;
    int qt = blockIdx.y * 32;
    int kt = blockIdx.x * 32;
    int tid = threadIdx.x;

    // stage Wout^T (f-major) split hi/lo, stride-40 rows for ldmatrix
    for (int i = tid; i < 32 * 128; i += 256) {
        int h = i >> 7, f = i & 127;
        float v = Wout[h * F_ + f];
        __half hi = __float2half(v);
        wh_s[f * 40 + h] = hi;
        wl_s[f * 40 + h] = __float2half(v - __half2float(hi));
    }

    // stage yq (+bout folded) / yk
    for (int i = tid; i < 32 * 128; i += 256) {
        int q = i >> 7, f = i & 127;
        size_t rq = ((size_t)(b * P_ + qt + q)) * F_ + f;
        size_t rk = ((size_t)(b * P_ + kt + q)) * F_ + f;
        float vq = bout[f], vk = 0.f;
#pragma unroll
        for (int s = 0; s < 4; s++) {
            vq += ypart[(size_t)s * M128 + rq];
            vk += ypart[(size_t)(4 + s) * M128 + rk];
        }
        yq_s[i] = vq;
        yk_s[i] = vk;
    }

    // gather phase 1: a = QK + Qp (k innermost; both contiguous in k)
    for (int i = tid; i < 32 * 32 * 32; i += 256) {
        int h = i >> 10, q = (i >> 5) & 31, k = i & 31;
        int gq = qt + q, gk = kt + k;
        size_t zb = (size_t)(b * 32 + h);
        float v = __half2float(QK[(zb * P_ + gq) * P_ + gk])
                + __half2float(Qp[(zb * P_ + gq) * P2 + (P_ + gk - gq)]);
        a_s[(q * 32 + k) * 40 + h] = __float2half(v);
    }
    __syncthreads();

    // gather phase 2: a += Kp (q innermost; Kp contiguous in q)
    for (int i = tid; i < 32 * 32 * 32; i += 256) {
        int h = i >> 10, k = (i >> 5) & 31, q = i & 31;
        int gq = qt + q, gk = kt + k;
        size_t zb = (size_t)(b * 32 + h);
        int ix = (q * 32 + k) * 40 + h;
        float v = __half2float(a_s[ix])
                + __half2float(Kp[(zb * P_ + gk) * P2 + (P_ + gq - gk)]);
        a_s[ix] = __float2half(v);
    }
    __syncthreads();

    // HMMA epilogue: out[m, f] = a[m, h] @ WoutT[f, h]  (M=1024, N=128, K=32)
    int warp = tid >> 5, lane = tid & 31;
    int g = lane >> 2, tig = lane & 3;
    int lr = lane & 15, lh = lane >> 4;
    int warpM = warp * 128;

    // load all A fragments: 8 m16 frags x 2 k16 steps
    uint32_t af[8][2][4];
#pragma unroll
    for (int mf = 0; mf < 8; mf++)
#pragma unroll
        for (int ks = 0; ks < 2; ks++) {
            uint32_t aa = smb + ((warpM + mf * 16 + lr) * 20 + lh * 4 + ks * 8) * 4;
            LDSM4(af[mf][ks][0], af[mf][ks][1], af[mf][ks][2], af[mf][ks][3], aa);
        }

#pragma unroll
    for (int np = 0; np < 4; np++) {      // 4 passes over f (32 cols each)
        float acc[8][4][4];
#pragma unroll
        for (int i = 0; i < 8; i++)
#pragma unroll
            for (int j = 0; j < 4; j++)
#pragma unroll
                for (int l = 0; l < 4; l++) acc[i][j][l] = 0.f;

#pragma unroll
        for (int ks = 0; ks < 2; ks++) {
            uint32_t bh[4][2], bl[4][2];
#pragma unroll
            for (int tp = 0; tp < 2; tp++) {
                uint32_t ba = smb + FIN_WH +
                    ((np * 32 + tp * 16 + lr) * 20 + lh * 4 + ks * 8) * 4;
                LDSM4(bh[2*tp][0], bh[2*tp+1][0], bh[2*tp][1], bh[2*tp+1][1], ba);
                LDSM4(bl[2*tp][0], bl[2*tp+1][0], bl[2*tp][1], bl[2*tp+1][1],
                      ba + 10240u);
            }
#pragma unroll
            for (int mf = 0; mf < 8; mf++)
#pragma unroll
                for (int nf = 0; nf < 4; nf++) {
                    MMA_FP16(acc[mf][nf], af[mf][ks], bh[nf]);
                    MMA_FP16(acc[mf][nf], af[mf][ks], bl[nf]);
                }
        }

        // store pass: add yq+bout and yk, write fp32 out
#pragma unroll
        for (int mf = 0; mf < 8; mf++)
#pragma unroll
            for (int nf = 0; nf < 4; nf++) {
                int f = np * 32 + nf * 8 + tig * 2;
#pragma unroll
                for (int half = 0; half < 2; half++) {
                    int r = warpM + mf * 16 + g + half * 8;
                    int q = r >> 5, k = r & 31;
                    float b0 = yq_s[q * 128 + f]     + yk_s[k * 128 + f];
                    float b1 = yq_s[q * 128 + f + 1] + yk_s[k * 128 + f + 1];
                    float* orow = out +
                        (((size_t)(b * P_) + qt + q) * P_ + kt + k) * F_ + f;
                    *(float2*)orow = make_float2(acc[mf][nf][half * 2] + b0,
                                                 acc[mf][nf][half * 2 + 1] + b1);
                }
            }
    }
}

// ---------------- launch ------------------------------------------------------
extern "C" void kernel_launch(void* const* d_in, const int* in_sizes, int n_in,
                              void* d_out, int out_size)
{
    const float* x        = (const float*)d_in[0];
    const float* norm_w   = (const float*)d_in[1];
    const float* Wq       = (const float*)d_in[2];
    const float* Wk       = (const float*)d_in[3];
    const float* Wpos     = (const float*)d_in[4];
    const float* bpos     = (const float*)d_in[5];
    const float* q_r_bias = (const float*)d_in[6];
    const float* k_r_bias = (const float*)d_in[7];
    const float* Wyq      = (const float*)d_in[8];
    const float* Wyk      = (const float*)d_in[9];
    const float* Wout     = (const float*)d_in[10];
    const float* bout     = (const float*)d_in[11];
    float* out = (float*)d_out;

    fp16 *p_xnh, *p_xgh;
    fp16 *p_wqth, *p_wqtl, *p_wkth, *p_wktl, *p_wyqh, *p_wyql, *p_wykh, *p_wykl;
    fp16 *p_posh, *p_posl, *p_qh, *p_kh, *p_kl, *p_QK, *p_Qp, *p_Kp;
    float *p_bias, *p_ypart;
    cudaGetSymbolAddress((void**)&p_xnh,  g_xnh);
    cudaGetSymbolAddress((void**)&p_xgh,  g_xgh);
    cudaGetSymbolAddress((void**)&p_wqth, g_wqth);
    cudaGetSymbolAddress((void**)&p_wqtl, g_wqtl);
    cudaGetSymbolAddress((void**)&p_wkth, g_wkth);
    cudaGetSymbolAddress((void**)&p_wktl, g_wktl);
    cudaGetSymbolAddress((void**)&p_wyqh, g_wyqh);
    cudaGetSymbolAddress((void**)&p_wyql, g_wyql);
    cudaGetSymbolAddress((void**)&p_wykh, g_wykh);
    cudaGetSymbolAddress((void**)&p_wykl, g_wykl);
    cudaGetSymbolAddress((void**)&p_posh, g_posh);
    cudaGetSymbolAddress((void**)&p_posl, g_posl);
    cudaGetSymbolAddress((void**)&p_qh,   g_qh);
    cudaGetSymbolAddress((void**)&p_kh,   g_kh);
    cudaGetSymbolAddress((void**)&p_kl,   g_kl);
    cudaGetSymbolAddress((void**)&p_bias, g_bias);
    cudaGetSymbolAddress((void**)&p_ypart, g_ypart);
    cudaGetSymbolAddress((void**)&p_QK,   g_QK);
    cudaGetSymbolAddress((void**)&p_Qp,   g_Qp);
    cudaGetSymbolAddress((void**)&p_Kp,   g_Kp);

    cudaFuncSetAttribute(proj_gemm, cudaFuncAttributeMaxDynamicSharedMemorySize, GEMM_SMEM);
    cudaFuncSetAttribute(y_gemm,    cudaFuncAttributeMaxDynamicSharedMemorySize, GEMM_SMEM);
    cudaFuncSetAttribute(qk_gemm,   cudaFuncAttributeMaxDynamicSharedMemorySize, GEMM_SMEM);
    cudaFuncSetAttribute(qpkp_gemm, cudaFuncAttributeMaxDynamicSharedMemorySize, GEMM_SMEM);
    cudaFuncSetAttribute(final_kernel, cudaFuncAttributeMaxDynamicSharedMemorySize, SMEM_FINAL);

    wconv_kernel<<<dim3(128, 48), 256>>>(Wq, p_wqth, p_wqtl, C_, HF);  // 0
    wconv_kernel<<<dim3(128, 48), 256>>>(Wk, p_wkth, p_wktl, C_, HF);  // 1
    pool_norm_kernel<<<1024, 256>>>(x, norm_w);                        // 2
    proj_gemm<<<dim3(32, 8), 256, GEMM_SMEM>>>(                        // 3
        p_xnh, p_wqth, p_wqtl, p_qh, (fp16*)0);
    proj_gemm<<<dim3(32, 8), 256, GEMM_SMEM>>>(                        // 4
        p_xnh, p_wkth, p_wktl, p_kh, p_kl);

    pos_kernel<<<1024, 128>>>(Wpos, bpos);
    bias_kernel<<<1024, 256>>>(q_r_bias, k_r_bias);
    wconv_kernel<<<dim3(4, 48), 256>>>(Wyq, p_wyqh, p_wyql, C_, F_);
    wconv_kernel<<<dim3(4, 48), 256>>>(Wyk, p_wykh, p_wykl, C_, F_);
    y_gemm<<<dim3(1, 8, 8), 256, GEMM_SMEM>>>(
        p_xgh, p_wyqh, p_wyql, p_wykh, p_wykl, p_ypart);

    qk_gemm<<<dim3(4, 4, 64), 256, GEMM_SMEM>>>(p_qh, p_kh, p_kl, p_QK);
    qpkp_gemm<<<dim3(20, 1, 128), 256, GEMM_SMEM>>>(
        p_qh, p_kh, p_posh, p_posl, p_Qp, p_Kp, p_bias);

    final_kernel<<<dim3(16, 16, 2), 256, SMEM_FINAL>>>(
        p_QK, p_Qp, p_Kp, p_ypart, Wout, bout, out);
}

// round 13
// speedup vs baseline: 1.1348x; 1.0739x over previous
#include <cuda_runtime.h>
#include <cuda_fp16.h>
#include <math.h>
#include <stdint.h>

typedef __half fp16;

#define B_   2
#define S_   8192
#define C_   1536
#define P_   512
#define H_   32
#define F_   128
#define HF   4096
#define P2   1024
#define P2S  1056     // padded row width for shifted Qp/Kp storage
#define M_   1024     // B_*P_

// ---------------- scratch (device globals) ------------------------------------
__device__ __align__(16) fp16 g_xnh[M_ * C_];
__device__ __align__(16) fp16 g_xgh[M_ * C_];
__device__ __align__(16) fp16 g_wqth[HF * C_], g_wqtl[HF * C_];
__device__ __align__(16) fp16 g_wkth[HF * C_], g_wktl[HF * C_];
__device__ __align__(16) fp16 g_wyqh[F_ * C_], g_wyql[F_ * C_];
__device__ __align__(16) fp16 g_wykh[F_ * C_], g_wykl[F_ * C_];
__device__ __align__(16) fp16 g_posh[P2 * HF], g_posl[P2 * HF];
__device__ __align__(16) fp16 g_qh [M_ * HF];
__device__ __align__(16) fp16 g_kh [M_ * HF], g_kl[M_ * HF];
__device__ float g_bias [2 * H_ * P2];
__device__ float g_ypart[8 * M_ * F_];
__device__ __align__(16) fp16 g_QK [(size_t)B_ * H_ * P_ * P_];
__device__ __align__(16) fp16 g_Qp [(size_t)B_ * H_ * P_ * P2S];  // shifted rows
__device__ __align__(16) fp16 g_Kp [(size_t)B_ * H_ * P_ * P2S];  // shifted rows

// ---------------- helpers ------------------------------------------------------
__device__ __forceinline__ void hsplit2(float x, float y, uint32_t& hw, uint32_t& lw)
{
    __half hx = __float2half(x);
    __half hy = __float2half(y);
    __half lx = __float2half(x - __half2float(hx));
    __half ly = __float2half(y - __half2float(hy));
    __half2 hp = __halves2half2(hx, hy);
    __half2 lp = __halves2half2(lx, ly);
    hw = *reinterpret_cast<uint32_t*>(&hp);
    lw = *reinterpret_cast<uint32_t*>(&lp);
}

__device__ __forceinline__ void cp16(uint32_t* smem_ptr, const fp16* gptr)
{
    uint32_t s = (uint32_t)__cvta_generic_to_shared(smem_ptr);
    asm volatile("cp.async.cg.shared.global [%0], [%1], 16;\n" :: "r"(s), "l"(gptr));
}

#define MMA_FP16(c, a, b)                                                       \
    asm volatile(                                                               \
        "mma.sync.aligned.m16n8k16.row.col.f32.f16.f16.f32 "                    \
        "{%0,%1,%2,%3}, {%4,%5,%6,%7}, {%8,%9}, {%0,%1,%2,%3};\n"               \
        : "+f"((c)[0]), "+f"((c)[1]), "+f"((c)[2]), "+f"((c)[3])                \
        : "r"((a)[0]), "r"((a)[1]), "r"((a)[2]), "r"((a)[3]),                   \
          "r"((b)[0]), "r"((b)[1]))

#define LDSM4(d0, d1, d2, d3, a)                                                \
    asm volatile(                                                               \
        "ldmatrix.sync.aligned.m8n8.x4.shared.b16 {%0,%1,%2,%3}, [%4];\n"       \
        : "=r"(d0), "=r"(d1), "=r"(d2), "=r"(d3) : "r"(a))

// one k16 sub-step, 4(m)x2(n) warp layout: 10 LDSM.x4 + 32 MMAs per warp
#define FRAG_LDSM(sst, j0)                                                      \
    do {                                                                        \
        uint32_t ah[2][4], bh[8][2], bl[8][2];                                  \
        _Pragma("unroll")                                                       \
        for (int mt = 0; mt < 2; mt++) {                                        \
            uint32_t aa = (sst) + aoff + mt * 1280u + (j0) * 4u;                \
            LDSM4(ah[mt][0], ah[mt][1], ah[mt][2], ah[mt][3], aa);              \
        }                                                                       \
        _Pragma("unroll")                                                       \
        for (int tp = 0; tp < 4; tp++) {                                        \
            uint32_t ba = (sst) + boff + tp * 1280u + (j0) * 4u + 10240u;       \
            LDSM4(bh[2*tp][0], bh[2*tp+1][0], bh[2*tp][1], bh[2*tp+1][1], ba);  \
            LDSM4(bl[2*tp][0], bl[2*tp+1][0], bl[2*tp][1], bl[2*tp+1][1],       \
                  ba + 10240u);                                                 \
        }                                                                       \
        _Pragma("unroll")                                                       \
        for (int mt = 0; mt < 2; mt++)                                          \
            _Pragma("unroll")                                                   \
            for (int nt = 0; nt < 8; nt++) {                                    \
                MMA_FP16(acc[mt][nt], ah[mt], bh[nt]);                          \
                MMA_FP16(acc[mt][nt], ah[mt], bl[nt]);                          \
            }                                                                   \
    } while (0)

// stage = [Ah 10240B][Bh 10240B][Bl 10240B] = 30720B; 3 stages
#define LOAD_STAGE(s, kpos, Ah, Bh, Bl, lda, ldb)                               \
    {                                                                           \
        uint32_t* sb = sm + (s) * 7680;                                         \
        _Pragma("unroll")                                                       \
        for (int ci = 0; ci < 2; ci++) {                                        \
            int qq = tid + ci * 256;                                            \
            int rw = qq >> 2, cc = qq & 3;                                      \
            uint32_t so = rw * 20 + cc * 4;                                     \
            size_t ga = (size_t)(rowA0 + rw) * (lda) + (kpos) + cc * 8;         \
            size_t gb = (size_t)(col0 + rw) * (ldb) + (kpos) + cc * 8;          \
            cp16(sb + so,        (Ah) + ga);                                    \
            cp16(sb + 2560 + so, (Bh) + gb);                                    \
            cp16(sb + 5120 + so, (Bl) + gb);                                    \
        }                                                                       \
    }

// 3-stage cp.async pipeline (requires nk >= 2)
#define GEMM_MAIN(Ah, Bh, Bl, lda, ldb, kb, nk)                                 \
    {                                                                           \
        LOAD_STAGE(0, (kb), Ah, Bh, Bl, lda, ldb);                              \
        asm volatile("cp.async.commit_group;\n");                               \
        LOAD_STAGE(1, (kb) + 32, Ah, Bh, Bl, lda, ldb);                         \
        asm volatile("cp.async.commit_group;\n");                               \
        for (int it = 0; it < (nk); it++) {                                     \
            if (it + 2 < (nk)) asm volatile("cp.async.wait_group 1;\n");        \
            else               asm volatile("cp.async.wait_group 0;\n");        \
            __syncthreads();                                                    \
            uint32_t sst = smb + (uint32_t)((it % 3) * 30720);                  \
            FRAG_LDSM(sst, 0);                                                  \
            if (it + 2 < (nk)) {                                                \
                LOAD_STAGE((it + 2) % 3, (kb) + (it + 2) * 32,                  \
                           Ah, Bh, Bl, lda, ldb);                               \
                asm volatile("cp.async.commit_group;\n");                       \
            }                                                                   \
            FRAG_LDSM(sst, 8);                                                  \
        }                                                                       \
    }

// 4(m) x 2(n) warp layout
#define GEMM_PREAMBLE                                                           \
    extern __shared__ uint32_t sm[];                                            \
    uint32_t smb = (uint32_t)__cvta_generic_to_shared(sm);                      \
    int tid = threadIdx.x;                                                      \
    int warp = tid >> 5, lane = tid & 31;                                       \
    int g = lane >> 2, tig = lane & 3;                                          \
    int lr = lane & 15, lh = lane >> 4;                                         \
    int m0 = (warp >> 1) * 32, n0 = (warp & 1) * 64;                            \
    uint32_t aoff = ((m0 + lr) * 20 + lh * 4) * 4;                              \
    uint32_t boff = ((n0 + lr) * 20 + lh * 4) * 4;                              \
    float acc[2][8][4];                                                         \
    _Pragma("unroll")                                                           \
    for (int i = 0; i < 2; i++)                                                 \
        _Pragma("unroll")                                                       \
        for (int j = 0; j < 8; j++)                                             \
            _Pragma("unroll")                                                   \
            for (int l = 0; l < 4; l++) acc[i][j][l] = 0.f;

#define EPI_F32(Cp, ldc, alpha)                                                 \
    _Pragma("unroll")                                                           \
    for (int mt = 0; mt < 2; mt++)                                              \
        _Pragma("unroll")                                                       \
        for (int nt = 0; nt < 8; nt++) {                                        \
            int r = rowA0 + m0 + mt * 16 + g;                                   \
            int cix = col0 + n0 + nt * 8 + tig * 2;                             \
            *(float2*)((Cp) + (size_t)r * (ldc) + cix) =                        \
                make_float2(acc[mt][nt][0] * (alpha), acc[mt][nt][1] * (alpha));\
            *(float2*)((Cp) + (size_t)(r + 8) * (ldc) + cix) =                  \
                make_float2(acc[mt][nt][2] * (alpha), acc[mt][nt][3] * (alpha));\
        }

#define GEMM_SMEM 92160

// ---------------- kernel: pool + RMS norm + GELU (hi fp16 out) ----------------
__global__ __launch_bounds__(256) void pool_norm_kernel(
    const float* __restrict__ x, const float* __restrict__ norm_w)
{
    int bid = blockIdx.x;
    int b = bid >> 9, p = bid & 511;
    int tid = threadIdx.x;

    const float* xrow = x + ((size_t)b * S_ + (size_t)p * 16) * C_;
    float xp[6];
#pragma unroll
    for (int j = 0; j < 6; j++) xp[j] = 0.f;
    for (int r = 0; r < 16; r++) {
        const float* xr = xrow + (size_t)r * C_;
#pragma unroll
        for (int j = 0; j < 6; j++) xp[j] += xr[tid + j * 256];
    }
    float ssq = 0.f;
#pragma unroll
    for (int j = 0; j < 6; j++) { xp[j] *= (1.f / 16.f); ssq += xp[j] * xp[j]; }

    __shared__ float red[256];
    red[tid] = ssq;
    __syncthreads();
    for (int s = 128; s > 0; s >>= 1) {
        if (tid < s) red[tid] += red[tid + s];
        __syncthreads();
    }
    float scale = 1.f / sqrtf(red[0] * (1.f / (float)C_) + 1e-8f);

    size_t base = (size_t)bid * C_;
#pragma unroll
    for (int j = 0; j < 6; j++) {
        int ch = tid + j * 256;
        float v = xp[j] * scale * norm_w[ch];
        float gv = v * 0.5f * (1.f + erff(v * 0.70710678118654752f));
        g_xnh[base + ch] = __float2half(v);
        g_xgh[base + ch] = __float2half(gv);
    }
}

// ---------------- kernel: pos features @ Wpos + bpos (split fp16 out) ---------
__global__ __launch_bounds__(128) void pos_kernel(
    const float* __restrict__ Wpos, const float* __restrict__ bpos)
{
    int d   = blockIdx.x;
    int tid = threadIdx.x;
    __shared__ float feat[32];

    int rel = d - P_;
    if (tid < 16) {
        double geo = exp((double)tid * (log(497.0) / 16.0));
        float center = (float)tid + (float)geo;
        float oh = (center > fabsf((float)rel)) ? 1.f : 0.f;
        float sg = (rel > 0) ? 1.f : ((rel < 0) ? -1.f : 0.f);
        feat[tid]      = oh;
        feat[tid + 16] = oh * sg;
    }
    __syncthreads();

    float f[32];
#pragma unroll
    for (int c = 0; c < 32; c++) f[c] = feat[c];

    for (int n = tid; n < HF; n += 128) {
        float acc = bpos[n];
#pragma unroll
        for (int c = 0; c < 32; c++) acc += f[c] * Wpos[c * HF + n];
        __half h = __float2half(acc);
        g_posh[(size_t)d * HF + n] = h;
        g_posl[(size_t)d * HF + n] = __float2half(acc - __half2float(h));
    }
}

// ---------------- kernel: rel-bias tables Bias[sel][h][d] = 0.25*rb·pos -------
__global__ __launch_bounds__(256) void bias_kernel(
    const float* __restrict__ qrb, const float* __restrict__ krb)
{
    int d = blockIdx.x;
    int lane = threadIdx.x & 31, w = threadIdx.x >> 5;
    for (int h = w; h < H_; h += 8) {
        float sq = 0.f, sk = 0.f;
        size_t pb = (size_t)d * HF + h * F_;
        for (int c = lane; c < F_; c += 32) {
            float pv = __half2float(g_posh[pb + c]) + __half2float(g_posl[pb + c]);
            sq += qrb[h * F_ + c] * pv;
            sk += krb[h * F_ + c] * pv;
        }
#pragma unroll
        for (int o = 16; o; o >>= 1) {
            sq += __shfl_xor_sync(0xffffffffu, sq, o);
            sk += __shfl_xor_sync(0xffffffffu, sk, o);
        }
        if (lane == 0) {
            g_bias[h * P2 + d]           = 0.25f * sq;
            g_bias[H_ * P2 + h * P2 + d] = 0.25f * sk;
        }
    }
}

// ---------------- kernel: weight transpose-convert W[K,N] -> T[N,K] split -----
__global__ __launch_bounds__(256) void wconv_kernel(
    const float* __restrict__ W, fp16* __restrict__ Th, fp16* __restrict__ Tl,
    int K, int N)
{
    __shared__ float t[32][33];
    int nt0 = blockIdx.x * 32, kt0 = blockIdx.y * 32;
    int tx = threadIdx.x & 31, ty = threadIdx.x >> 5;
#pragma unroll
    for (int i = 0; i < 4; i++)
        t[ty + i * 8][tx] = W[(size_t)(kt0 + ty + i * 8) * N + nt0 + tx];
    __syncthreads();
#pragma unroll
    for (int i = 0; i < 4; i++) {
        int n = nt0 + ty + i * 8, k = kt0 + tx;
        float v = t[tx][ty + i * 8];
        __half h = __float2half(v);
        Th[(size_t)n * K + k] = h;
        Tl[(size_t)n * K + k] = __float2half(v - __half2float(h));
    }
}

// ---------------- kernel: projection GEMM (q/k) -------------------------------
__global__ __launch_bounds__(256, 2) void proj_gemm(
    const fp16* __restrict__ Ah,
    const fp16* __restrict__ Bh, const fp16* __restrict__ Bl,
    fp16* __restrict__ Oh, fp16* __restrict__ Ol)
{
    GEMM_PREAMBLE
    int rowA0 = blockIdx.y * 128, col0 = blockIdx.x * 128;
    GEMM_MAIN(Ah, Bh, Bl, C_, C_, 0, C_ / 32);

    uint32_t* oh = (uint32_t*)Oh;
    uint32_t* ol = (uint32_t*)Ol;
#pragma unroll
    for (int mt = 0; mt < 2; mt++)
#pragma unroll
        for (int nt = 0; nt < 8; nt++) {
            int r = rowA0 + m0 + mt * 16 + g;
            int n = col0 + n0 + nt * 8 + tig * 2;
            uint32_t hw, lw;
            size_t ix0 = ((size_t)r * HF + n) >> 1;
            size_t ix1 = ((size_t)(r + 8) * HF + n) >> 1;
            hsplit2(acc[mt][nt][0], acc[mt][nt][1], hw, lw);
            oh[ix0] = hw;
            if (ol) ol[ix0] = lw;
            hsplit2(acc[mt][nt][2], acc[mt][nt][3], hw, lw);
            oh[ix1] = hw;
            if (ol) ol[ix1] = lw;
        }
}

// ---------------- kernel: yq/yk GEMM, split-K x4 -------------------------------
__global__ __launch_bounds__(256, 2) void y_gemm(
    const fp16* __restrict__ Ah,
    const fp16* __restrict__ B0h, const fp16* __restrict__ B0l,
    const fp16* __restrict__ B1h, const fp16* __restrict__ B1l,
    float* __restrict__ ypart)
{
    GEMM_PREAMBLE
    int z = blockIdx.z;
    const fp16* Bh = (z >= 4) ? B1h : B0h;
    const fp16* Bl = (z >= 4) ? B1l : B0l;
    int kb = (z & 3) * 384;
    int rowA0 = blockIdx.y * 128, col0 = 0;
    GEMM_MAIN(Ah, Bh, Bl, C_, C_, kb, 12);
    float* C = ypart + (size_t)z * M_ * F_;
    EPI_F32(C, F_, 1.0f)
}

// ---------------- kernel: QK GEMM (fp16 out) -----------------------------------
__global__ __launch_bounds__(256, 2) void qk_gemm(
    const fp16* __restrict__ Ahb,
    const fp16* __restrict__ Bhb, const fp16* __restrict__ Blb,
    fp16* __restrict__ Cbase)
{
    GEMM_PREAMBLE
    int z = blockIdx.z, b = z >> 5, h = z & 31;
    const fp16* Ah = Ahb + (size_t)b * P_ * HF + h * F_;
    const fp16* Bh = Bhb + (size_t)b * P_ * HF + h * F_;
    const fp16* Bl = Blb + (size_t)b * P_ * HF + h * F_;
    __half2* C = (__half2*)(Cbase + (size_t)z * P_ * P_);
    int rowA0 = blockIdx.y * 128, col0 = blockIdx.x * 128;
    GEMM_MAIN(Ah, Bh, Bl, HF, HF, 0, 4);

#pragma unroll
    for (int mt = 0; mt < 2; mt++)
#pragma unroll
        for (int nt = 0; nt < 8; nt++) {
            int r = rowA0 + m0 + mt * 16 + g;
            int cix = col0 + n0 + nt * 8 + tig * 2;
            C[((size_t)r * P_ + cix) >> 1] =
                __floats2half2_rn(acc[mt][nt][0], acc[mt][nt][1]);
            C[((size_t)(r + 8) * P_ + cix) >> 1] =
                __floats2half2_rn(acc[mt][nt][2], acc[mt][nt][3]);
        }
}

// ---------------- kernel: Qp+Kp merged band GEMM (fp16, SHIFTED rows) ----------
// row r stored shifted by (r&31): element (r, j) lives at stored col j + (r&31)
__global__ __launch_bounds__(256, 2) void qpkp_gemm(
    const fp16* __restrict__ qA, const fp16* __restrict__ kA,
    const fp16* __restrict__ Bh, const fp16* __restrict__ Bl,
    fp16* __restrict__ Qp, fp16* __restrict__ Kp,
    const float* __restrict__ biasT)
{
    GEMM_PREAMBLE
    int z = blockIdx.z;
    int sel = z >> 6, zz = z & 63, b = zz >> 5, h = zz & 31;
    int i = blockIdx.x;
    int ty = i / 5, tx = 3 - ty + (i % 5);
    const fp16* Ahp = (sel ? kA : qA) + (size_t)b * P_ * HF + h * F_;
    const fp16* Bhp = Bh + (size_t)h * F_;
    const fp16* Blp = Bl + (size_t)h * F_;
    fp16* C = (sel ? Kp : Qp) + (size_t)zz * P_ * P2S;
    const float* bp = biasT + (size_t)sel * H_ * P2 + (size_t)h * P2;
    int rowA0 = ty * 128, col0 = tx * 128;
    GEMM_MAIN(Ahp, Bhp, Blp, HF, HF, 0, 4);

#pragma unroll
    for (int mt = 0; mt < 2; mt++)
#pragma unroll
        for (int nt = 0; nt < 8; nt++) {
            int cix = col0 + n0 + nt * 8 + tig * 2;
            float2 bb = *(const float2*)(bp + cix);
#pragma unroll
            for (int half = 0; half < 2; half++) {
                int r = rowA0 + m0 + mt * 16 + g + half * 8;
                int sh = r & 31;
                size_t base = (size_t)r * P2S + cix + sh;
                C[base]     = __float2half(acc[mt][nt][half * 2]     * 0.25f + bb.x);
                C[base + 1] = __float2half(acc[mt][nt][half * 2 + 1] * 0.25f + bb.y);
            }
        }
}

// ---------------- kernel: fused gather (vectorized) + HMMA a@Wout (R11 epi) ----
#define FIN_A   0
#define FIN_YQ  81920
#define FIN_YK  (FIN_YQ + 16384)
#define FIN_WH  (FIN_YK + 16384)
#define FIN_WL  (FIN_WH + 10240)
#define SMEM_FINAL (FIN_WL + 10240)
#define M128 (M_ * F_)

__global__ __launch_bounds__(256) void final_kernel(
    const fp16* __restrict__ QK, const fp16* __restrict__ Qp,
    const fp16* __restrict__ Kp, const float* __restrict__ ypart,
    const float* __restrict__ Wout, const float* __restrict__ bout,
    float* __restrict__ out)
{
    extern __shared__ char smem[];
    __half* a_s  = (__half*)smem;
    float*  yq_s = (float*)(smem + FIN_YQ);
    float*  yk_s = (float*)(smem + FIN_YK);
    __half* wh_s = (__half*)(smem + FIN_WH);
    __half* wl_s = (__half*)(smem + FIN_WL);
    uint32_t smb = (uint32_t)__cvta_generic_to_shared(smem);

    int b  = blockIdx.z;
    int qt = blockIdx.y * 32;
    int kt = blockIdx.x * 32;
    int tid = threadIdx.x;

    // stage Wout^T split hi/lo, stride-40-half rows (rows = f)
    for (int i = tid; i < 32 * 128; i += 256) {
        int h = i >> 7, f = i & 127;
        float v = Wout[h * F_ + f];
        __half hi = __float2half(v);
        wh_s[f * 40 + h] = hi;
        wl_s[f * 40 + h] = __float2half(v - __half2float(hi));
    }

    // stage yq (+bout) / yk, float4 vectorized
    for (int i = tid; i < 1024; i += 256) {
        int q = i >> 5, f = (i & 31) * 4;
        size_t rq = ((size_t)(b * P_ + qt + q)) * F_ + f;
        size_t rk = ((size_t)(b * P_ + kt + q)) * F_ + f;
        float4 vq = *(const float4*)(bout + f);
        float4 vk = make_float4(0.f, 0.f, 0.f, 0.f);
#pragma unroll
        for (int s = 0; s < 4; s++) {
            float4 a = *(const float4*)(ypart + (size_t)s * M128 + rq);
            float4 c = *(const float4*)(ypart + (size_t)(4 + s) * M128 + rk);
            vq.x += a.x; vq.y += a.y; vq.z += a.z; vq.w += a.w;
            vk.x += c.x; vk.y += c.y; vk.z += c.z; vk.w += c.w;
        }
        *(float4*)(yq_s + q * 128 + f) = vq;
        *(float4*)(yk_s + q * 128 + f) = vk;
    }

    // gather phase 1: a = QK + Qp (uint4 loads; shifted Qp layout)
    for (int i = tid; i < 4096; i += 256) {
        int h = i >> 7, q = (i >> 2) & 31, k0 = (i & 3) * 8;
        int gq = qt + q;
        size_t zb = (size_t)(b * 32 + h);
        uint4 vqk = *(const uint4*)(QK + (zb * P_ + gq) * P_ + kt + k0);
        uint4 vqp = *(const uint4*)(Qp + (zb * P_ + gq) * P2S + (P_ + kt - qt + k0));
        const __half2* hqk = (const __half2*)&vqk;
        const __half2* hqp = (const __half2*)&vqp;
        int m = q * 32 + k0;
#pragma unroll
        for (int j = 0; j < 4; j++) {
            __half2 s = __hadd2(hqk[j], hqp[j]);
            a_s[(m + 2 * j)     * 40 + h] = __low2half(s);
            a_s[(m + 2 * j + 1) * 40 + h] = __high2half(s);
        }
    }
    __syncthreads();

    // gather phase 2: a += Kp (uint4 loads; shifted layout; q contiguous)
    for (int i = tid; i < 4096; i += 256) {
        int h = i >> 7, k = (i >> 2) & 31, q0 = (i & 3) * 8;
        int gk = kt + k;
        size_t zb = (size_t)(b * 32 + h);
        uint4 vkp = *(const uint4*)(Kp + (zb * P_ + gk) * P2S + (P_ + qt - kt + q0));
        const __half* hk = (const __half*)&vkp;
#pragma unroll
        for (int j = 0; j < 8; j++) {
            int ix = ((q0 + j) * 32 + k) * 40 + h;
            a_s[ix] = __hadd(a_s[ix], hk[j]);
        }
    }
    __syncthreads();

    // HMMA: out[m,f] = a[m,h] @ WoutT[f,h], M=1024 N=128 K=32  (R11-proven)
    int warp = tid >> 5, lane = tid & 31;
    int g = lane >> 2, tig = lane & 3;
    int lr = lane & 15, lh = lane >> 4;
    int warpM = warp * 128;

    uint32_t af[8][2][4];
#pragma unroll
    for (int mf = 0; mf < 8; mf++)
#pragma unroll
        for (int ks = 0; ks < 2; ks++) {
            uint32_t aa = smb + ((warpM + mf * 16 + lr) * 20 + lh * 4 + ks * 8) * 4;
            LDSM4(af[mf][ks][0], af[mf][ks][1], af[mf][ks][2], af[mf][ks][3], aa);
        }

#pragma unroll
    for (int np = 0; np < 4; np++) {      // 4 passes over f (32 cols each)
        float acc[8][4][4];
#pragma unroll
        for (int i = 0; i < 8; i++)
#pragma unroll
            for (int j = 0; j < 4; j++)
#pragma unroll
                for (int l = 0; l < 4; l++) acc[i][j][l] = 0.f;

#pragma unroll
        for (int ks = 0; ks < 2; ks++) {
            uint32_t bh[4][2], bl[4][2];
#pragma unroll
            for (int tp = 0; tp < 2; tp++) {
                uint32_t ba = smb + FIN_WH +
                    ((np * 32 + tp * 16 + lr) * 20 + lh * 4 + ks * 8) * 4;
                LDSM4(bh[2*tp][0], bh[2*tp+1][0], bh[2*tp][1], bh[2*tp+1][1], ba);
                LDSM4(bl[2*tp][0], bl[2*tp+1][0], bl[2*tp][1], bl[2*tp+1][1],
                      ba + 10240u);
            }
#pragma unroll
            for (int mf = 0; mf < 8; mf++)
#pragma unroll
                for (int nf = 0; nf < 4; nf++) {
                    MMA_FP16(acc[mf][nf], af[mf][ks], bh[nf]);
                    MMA_FP16(acc[mf][nf], af[mf][ks], bl[nf]);
                }
        }

        // store pass: add yq+bout and yk, write fp32 out (R11-proven)
#pragma unroll
        for (int mf = 0; mf < 8; mf++)
#pragma unroll
            for (int nf = 0; nf < 4; nf++) {
                int f = np * 32 + nf * 8 + tig * 2;
#pragma unroll
                for (int half = 0; half < 2; half++) {
                    int r = warpM + mf * 16 + g + half * 8;
                    int q = r >> 5, k = r & 31;
                    float b0 = yq_s[q * 128 + f]     + yk_s[k * 128 + f];
                    float b1 = yq_s[q * 128 + f + 1] + yk_s[k * 128 + f + 1];
                    float* orow = out +
                        (((size_t)(b * P_) + qt + q) * P_ + kt + k) * F_ + f;
                    *(float2*)orow = make_float2(acc[mf][nf][half * 2] + b0,
                                                 acc[mf][nf][half * 2 + 1] + b1);
                }
            }
    }
}

// ---------------- launch ------------------------------------------------------
extern "C" void kernel_launch(void* const* d_in, const int* in_sizes, int n_in,
                              void* d_out, int out_size)
{
    const float* x        = (const float*)d_in[0];
    const float* norm_w   = (const float*)d_in[1];
    const float* Wq       = (const float*)d_in[2];
    const float* Wk       = (const float*)d_in[3];
    const float* Wpos     = (const float*)d_in[4];
    const float* bpos     = (const float*)d_in[5];
    const float* q_r_bias = (const float*)d_in[6];
    const float* k_r_bias = (const float*)d_in[7];
    const float* Wyq      = (const float*)d_in[8];
    const float* Wyk      = (const float*)d_in[9];
    const float* Wout     = (const float*)d_in[10];
    const float* bout     = (const float*)d_in[11];
    float* out = (float*)d_out;

    fp16 *p_xnh, *p_xgh;
    fp16 *p_wqth, *p_wqtl, *p_wkth, *p_wktl, *p_wyqh, *p_wyql, *p_wykh, *p_wykl;
    fp16 *p_posh, *p_posl, *p_qh, *p_kh, *p_kl, *p_QK, *p_Qp, *p_Kp;
    float *p_bias, *p_ypart;
    cudaGetSymbolAddress((void**)&p_xnh,  g_xnh);
    cudaGetSymbolAddress((void**)&p_xgh,  g_xgh);
    cudaGetSymbolAddress((void**)&p_wqth, g_wqth);
    cudaGetSymbolAddress((void**)&p_wqtl, g_wqtl);
    cudaGetSymbolAddress((void**)&p_wkth, g_wkth);
    cudaGetSymbolAddress((void**)&p_wktl, g_wktl);
    cudaGetSymbolAddress((void**)&p_wyqh, g_wyqh);
    cudaGetSymbolAddress((void**)&p_wyql, g_wyql);
    cudaGetSymbolAddress((void**)&p_wykh, g_wykh);
    cudaGetSymbolAddress((void**)&p_wykl, g_wykl);
    cudaGetSymbolAddress((void**)&p_posh, g_posh);
    cudaGetSymbolAddress((void**)&p_posl, g_posl);
    cudaGetSymbolAddress((void**)&p_qh,   g_qh);
    cudaGetSymbolAddress((void**)&p_kh,   g_kh);
    cudaGetSymbolAddress((void**)&p_kl,   g_kl);
    cudaGetSymbolAddress((void**)&p_bias, g_bias);
    cudaGetSymbolAddress((void**)&p_ypart, g_ypart);
    cudaGetSymbolAddress((void**)&p_QK,   g_QK);
    cudaGetSymbolAddress((void**)&p_Qp,   g_Qp);
    cudaGetSymbolAddress((void**)&p_Kp,   g_Kp);

    cudaFuncSetAttribute(proj_gemm, cudaFuncAttributeMaxDynamicSharedMemorySize, GEMM_SMEM);
    cudaFuncSetAttribute(y_gemm,    cudaFuncAttributeMaxDynamicSharedMemorySize, GEMM_SMEM);
    cudaFuncSetAttribute(qk_gemm,   cudaFuncAttributeMaxDynamicSharedMemorySize, GEMM_SMEM);
    cudaFuncSetAttribute(qpkp_gemm, cudaFuncAttributeMaxDynamicSharedMemorySize, GEMM_SMEM);
    cudaFuncSetAttribute(final_kernel, cudaFuncAttributeMaxDynamicSharedMemorySize, SMEM_FINAL);

    wconv_kernel<<<dim3(128, 48), 256>>>(Wq, p_wqth, p_wqtl, C_, HF);  // 0
    wconv_kernel<<<dim3(128, 48), 256>>>(Wk, p_wkth, p_wktl, C_, HF);  // 1
    pool_norm_kernel<<<1024, 256>>>(x, norm_w);                        // 2
    proj_gemm<<<dim3(32, 8), 256, GEMM_SMEM>>>(                        // 3
        p_xnh, p_wqth, p_wqtl, p_qh, (fp16*)0);
    proj_gemm<<<dim3(32, 8), 256, GEMM_SMEM>>>(                        // 4
        p_xnh, p_wkth, p_wktl, p_kh, p_kl);

    pos_kernel<<<1024, 128>>>(Wpos, bpos);
    bias_kernel<<<1024, 256>>>(q_r_bias, k_r_bias);
    wconv_kernel<<<dim3(4, 48), 256>>>(Wyq, p_wyqh, p_wyql, C_, F_);
    wconv_kernel<<<dim3(4, 48), 256>>>(Wyk, p_wykh, p_wykl, C_, F_);
    y_gemm<<<dim3(1, 8, 8), 256, GEMM_SMEM>>>(
        p_xgh, p_wyqh, p_wyql, p_wykh, p_wykl, p_ypart);

    qk_gemm<<<dim3(4, 4, 64), 256, GEMM_SMEM>>>(p_qh, p_kh, p_kl, p_QK);
    qpkp_gemm<<<dim3(20, 1, 128), 256, GEMM_SMEM>>>(
        p_qh, p_kh, p_posh, p_posl, p_Qp, p_Kp, p_bias);

    final_kernel<<<dim3(16, 16, 2), 256, SMEM_FINAL>>>(
        p_QK, p_Qp, p_Kp, p_ypart, Wout, bout, out);
}

// round 14
// speedup vs baseline: 1.1598x; 1.0220x over previous
#include <cuda_runtime.h>
#include <cuda_fp16.h>
#include <math.h>
#include <stdint.h>

typedef __half fp16;

#define B_   2
#define S_   8192
#define C_   1536
#define P_   512
#define H_   32
#define F_   128
#define HF   4096
#define P2   1024
#define P2S  1056     // padded row width for shifted Qp/Kp storage
#define M_   1024     // B_*P_

// ---------------- scratch (device globals) ------------------------------------
__device__ __align__(16) fp16 g_xnh[M_ * C_];
__device__ __align__(16) fp16 g_xgh[M_ * C_];
__device__ __align__(16) fp16 g_wqth[HF * C_], g_wqtl[HF * C_];
__device__ __align__(16) fp16 g_wkth[HF * C_], g_wktl[HF * C_];
__device__ __align__(16) fp16 g_wyqh[F_ * C_], g_wyql[F_ * C_];
__device__ __align__(16) fp16 g_wykh[F_ * C_], g_wykl[F_ * C_];
__device__ __align__(16) fp16 g_posh[P2 * HF], g_posl[P2 * HF];
__device__ __align__(16) fp16 g_qh [M_ * HF];
__device__ __align__(16) fp16 g_kh [M_ * HF], g_kl[M_ * HF];
__device__ float g_bias [2 * H_ * P2];
__device__ float g_ypart[8 * M_ * F_];
__device__ __align__(16) fp16 g_QK [(size_t)B_ * H_ * P_ * P_];
__device__ __align__(16) fp16 g_Qp [(size_t)B_ * H_ * P_ * P2S];  // shifted rows
__device__ __align__(16) fp16 g_Kp [(size_t)B_ * H_ * P_ * P2S];  // shifted rows

// ---------------- helpers ------------------------------------------------------
__device__ __forceinline__ void hsplit2(float x, float y, uint32_t& hw, uint32_t& lw)
{
    __half hx = __float2half(x);
    __half hy = __float2half(y);
    __half lx = __float2half(x - __half2float(hx));
    __half ly = __float2half(y - __half2float(hy));
    __half2 hp = __halves2half2(hx, hy);
    __half2 lp = __halves2half2(lx, ly);
    hw = *reinterpret_cast<uint32_t*>(&hp);
    lw = *reinterpret_cast<uint32_t*>(&lp);
}

__device__ __forceinline__ void cp16(uint32_t* smem_ptr, const fp16* gptr)
{
    uint32_t s = (uint32_t)__cvta_generic_to_shared(smem_ptr);
    asm volatile("cp.async.cg.shared.global [%0], [%1], 16;\n" :: "r"(s), "l"(gptr));
}

#define MMA_FP16(c, a, b)                                                       \
    asm volatile(                                                               \
        "mma.sync.aligned.m16n8k16.row.col.f32.f16.f16.f32 "                    \
        "{%0,%1,%2,%3}, {%4,%5,%6,%7}, {%8,%9}, {%0,%1,%2,%3};\n"               \
        : "+f"((c)[0]), "+f"((c)[1]), "+f"((c)[2]), "+f"((c)[3])                \
        : "r"((a)[0]), "r"((a)[1]), "r"((a)[2]), "r"((a)[3]),                   \
          "r"((b)[0]), "r"((b)[1]))

#define LDSM4(d0, d1, d2, d3, a)                                                \
    asm volatile(                                                               \
        "ldmatrix.sync.aligned.m8n8.x4.shared.b16 {%0,%1,%2,%3}, [%4];\n"       \
        : "=r"(d0), "=r"(d1), "=r"(d2), "=r"(d3) : "r"(a))

// one k16 sub-step, 4(m)x2(n) warp layout: 10 LDSM.x4 + 32 MMAs per warp
#define FRAG_LDSM(sst, j0)                                                      \
    do {                                                                        \
        uint32_t ah[2][4], bh[8][2], bl[8][2];                                  \
        _Pragma("unroll")                                                       \
        for (int mt = 0; mt < 2; mt++) {                                        \
            uint32_t aa = (sst) + aoff + mt * 1280u + (j0) * 4u;                \
            LDSM4(ah[mt][0], ah[mt][1], ah[mt][2], ah[mt][3], aa);              \
        }                                                                       \
        _Pragma("unroll")                                                       \
        for (int tp = 0; tp < 4; tp++) {                                        \
            uint32_t ba = (sst) + boff + tp * 1280u + (j0) * 4u + 10240u;       \
            LDSM4(bh[2*tp][0], bh[2*tp+1][0], bh[2*tp][1], bh[2*tp+1][1], ba);  \
            LDSM4(bl[2*tp][0], bl[2*tp+1][0], bl[2*tp][1], bl[2*tp+1][1],       \
                  ba + 10240u);                                                 \
        }                                                                       \
        _Pragma("unroll")                                                       \
        for (int mt = 0; mt < 2; mt++)                                          \
            _Pragma("unroll")                                                   \
            for (int nt = 0; nt < 8; nt++) {                                    \
                MMA_FP16(acc[mt][nt], ah[mt], bh[nt]);                          \
                MMA_FP16(acc[mt][nt], ah[mt], bl[nt]);                          \
            }                                                                   \
    } while (0)

// stage = [Ah 10240B][Bh 10240B][Bl 10240B] = 30720B; 3 stages
#define LOAD_STAGE(s, kpos, Ah, Bh, Bl, lda, ldb)                               \
    {                                                                           \
        uint32_t* sb = sm + (s) * 7680;                                         \
        _Pragma("unroll")                                                       \
        for (int ci = 0; ci < 2; ci++) {                                        \
            int qq = tid + ci * 256;                                            \
            int rw = qq >> 2, cc = qq & 3;                                      \
            uint32_t so = rw * 20 + cc * 4;                                     \
            size_t ga = (size_t)(rowA0 + rw) * (lda) + (kpos) + cc * 8;         \
            size_t gb = (size_t)(col0 + rw) * (ldb) + (kpos) + cc * 8;          \
            cp16(sb + so,        (Ah) + ga);                                    \
            cp16(sb + 2560 + so, (Bh) + gb);                                    \
            cp16(sb + 5120 + so, (Bl) + gb);                                    \
        }                                                                       \
    }

// 3-stage cp.async pipeline (requires nk >= 2)
#define GEMM_MAIN(Ah, Bh, Bl, lda, ldb, kb, nk)                                 \
    {                                                                           \
        LOAD_STAGE(0, (kb), Ah, Bh, Bl, lda, ldb);                              \
        asm volatile("cp.async.commit_group;\n");                               \
        LOAD_STAGE(1, (kb) + 32, Ah, Bh, Bl, lda, ldb);                         \
        asm volatile("cp.async.commit_group;\n");                               \
        for (int it = 0; it < (nk); it++) {                                     \
            if (it + 2 < (nk)) asm volatile("cp.async.wait_group 1;\n");        \
            else               asm volatile("cp.async.wait_group 0;\n");        \
            __syncthreads();                                                    \
            uint32_t sst = smb + (uint32_t)((it % 3) * 30720);                  \
            FRAG_LDSM(sst, 0);                                                  \
            if (it + 2 < (nk)) {                                                \
                LOAD_STAGE((it + 2) % 3, (kb) + (it + 2) * 32,                  \
                           Ah, Bh, Bl, lda, ldb);                               \
                asm volatile("cp.async.commit_group;\n");                       \
            }                                                                   \
            FRAG_LDSM(sst, 8);                                                  \
        }                                                                       \
    }

// 4(m) x 2(n) warp layout
#define GEMM_PREAMBLE                                                           \
    extern __shared__ uint32_t sm[];                                            \
    uint32_t smb = (uint32_t)__cvta_generic_to_shared(sm);                      \
    int tid = threadIdx.x;                                                      \
    int warp = tid >> 5, lane = tid & 31;                                       \
    int g = lane >> 2, tig = lane & 3;                                          \
    int lr = lane & 15, lh = lane >> 4;                                         \
    int m0 = (warp >> 1) * 32, n0 = (warp & 1) * 64;                            \
    uint32_t aoff = ((m0 + lr) * 20 + lh * 4) * 4;                              \
    uint32_t boff = ((n0 + lr) * 20 + lh * 4) * 4;                              \
    float acc[2][8][4];                                                         \
    _Pragma("unroll")                                                           \
    for (int i = 0; i < 2; i++)                                                 \
        _Pragma("unroll")                                                       \
        for (int j = 0; j < 8; j++)                                             \
            _Pragma("unroll")                                                   \
            for (int l = 0; l < 4; l++) acc[i][j][l] = 0.f;

#define EPI_F32(Cp, ldc, alpha)                                                 \
    _Pragma("unroll")                                                           \
    for (int mt = 0; mt < 2; mt++)                                              \
        _Pragma("unroll")                                                       \
        for (int nt = 0; nt < 8; nt++) {                                        \
            int r = rowA0 + m0 + mt * 16 + g;                                   \
            int cix = col0 + n0 + nt * 8 + tig * 2;                             \
            *(float2*)((Cp) + (size_t)r * (ldc) + cix) =                        \
                make_float2(acc[mt][nt][0] * (alpha), acc[mt][nt][1] * (alpha));\
            *(float2*)((Cp) + (size_t)(r + 8) * (ldc) + cix) =                  \
                make_float2(acc[mt][nt][2] * (alpha), acc[mt][nt][3] * (alpha));\
        }

#define GEMM_SMEM 92160

// ---------------- kernel: pool + RMS norm + GELU (hi fp16 out) ----------------
__global__ __launch_bounds__(256) void pool_norm_kernel(
    const float* __restrict__ x, const float* __restrict__ norm_w)
{
    int bid = blockIdx.x;
    int b = bid >> 9, p = bid & 511;
    int tid = threadIdx.x;

    const float* xrow = x + ((size_t)b * S_ + (size_t)p * 16) * C_;
    float xp[6];
#pragma unroll
    for (int j = 0; j < 6; j++) xp[j] = 0.f;
    for (int r = 0; r < 16; r++) {
        const float* xr = xrow + (size_t)r * C_;
#pragma unroll
        for (int j = 0; j < 6; j++) xp[j] += xr[tid + j * 256];
    }
    float ssq = 0.f;
#pragma unroll
    for (int j = 0; j < 6; j++) { xp[j] *= (1.f / 16.f); ssq += xp[j] * xp[j]; }

    __shared__ float red[256];
    red[tid] = ssq;
    __syncthreads();
    for (int s = 128; s > 0; s >>= 1) {
        if (tid < s) red[tid] += red[tid + s];
        __syncthreads();
    }
    float scale = 1.f / sqrtf(red[0] * (1.f / (float)C_) + 1e-8f);

    size_t base = (size_t)bid * C_;
#pragma unroll
    for (int j = 0; j < 6; j++) {
        int ch = tid + j * 256;
        float v = xp[j] * scale * norm_w[ch];
        float gv = v * 0.5f * (1.f + erff(v * 0.70710678118654752f));
        g_xnh[base + ch] = __float2half(v);
        g_xgh[base + ch] = __float2half(gv);
    }
}

// ---------------- kernel: pos features @ Wpos + bpos (split fp16 out) ---------
__global__ __launch_bounds__(128) void pos_kernel(
    const float* __restrict__ Wpos, const float* __restrict__ bpos)
{
    int d   = blockIdx.x;
    int tid = threadIdx.x;
    __shared__ float feat[32];

    int rel = d - P_;
    if (tid < 16) {
        double geo = exp((double)tid * (log(497.0) / 16.0));
        float center = (float)tid + (float)geo;
        float oh = (center > fabsf((float)rel)) ? 1.f : 0.f;
        float sg = (rel > 0) ? 1.f : ((rel < 0) ? -1.f : 0.f);
        feat[tid]      = oh;
        feat[tid + 16] = oh * sg;
    }
    __syncthreads();

    float f[32];
#pragma unroll
    for (int c = 0; c < 32; c++) f[c] = feat[c];

    for (int n = tid; n < HF; n += 128) {
        float acc = bpos[n];
#pragma unroll
        for (int c = 0; c < 32; c++) acc += f[c] * Wpos[c * HF + n];
        __half h = __float2half(acc);
        g_posh[(size_t)d * HF + n] = h;
        g_posl[(size_t)d * HF + n] = __float2half(acc - __half2float(h));
    }
}

// ---------------- kernel: rel-bias tables Bias[sel][h][d] = 0.25*rb·pos -------
__global__ __launch_bounds__(256) void bias_kernel(
    const float* __restrict__ qrb, const float* __restrict__ krb)
{
    int d = blockIdx.x;
    int lane = threadIdx.x & 31, w = threadIdx.x >> 5;
    for (int h = w; h < H_; h += 8) {
        float sq = 0.f, sk = 0.f;
        size_t pb = (size_t)d * HF + h * F_;
        for (int c = lane; c < F_; c += 32) {
            float pv = __half2float(g_posh[pb + c]) + __half2float(g_posl[pb + c]);
            sq += qrb[h * F_ + c] * pv;
            sk += krb[h * F_ + c] * pv;
        }
#pragma unroll
        for (int o = 16; o; o >>= 1) {
            sq += __shfl_xor_sync(0xffffffffu, sq, o);
            sk += __shfl_xor_sync(0xffffffffu, sk, o);
        }
        if (lane == 0) {
            g_bias[h * P2 + d]           = 0.25f * sq;
            g_bias[H_ * P2 + h * P2 + d] = 0.25f * sk;
        }
    }
}

// ---------------- kernel: weight transpose-convert W[K,N] -> T[N,K] split -----
__global__ __launch_bounds__(256) void wconv_kernel(
    const float* __restrict__ W, fp16* __restrict__ Th, fp16* __restrict__ Tl,
    int K, int N)
{
    __shared__ float t[32][33];
    int nt0 = blockIdx.x * 32, kt0 = blockIdx.y * 32;
    int tx = threadIdx.x & 31, ty = threadIdx.x >> 5;
#pragma unroll
    for (int i = 0; i < 4; i++)
        t[ty + i * 8][tx] = W[(size_t)(kt0 + ty + i * 8) * N + nt0 + tx];
    __syncthreads();
#pragma unroll
    for (int i = 0; i < 4; i++) {
        int n = nt0 + ty + i * 8, k = kt0 + tx;
        float v = t[tx][ty + i * 8];
        __half h = __float2half(v);
        Th[(size_t)n * K + k] = h;
        Tl[(size_t)n * K + k] = __float2half(v - __half2float(h));
    }
}

// ---------------- kernel: projection GEMM (q/k) -------------------------------
__global__ __launch_bounds__(256, 2) void proj_gemm(
    const fp16* __restrict__ Ah,
    const fp16* __restrict__ Bh, const fp16* __restrict__ Bl,
    fp16* __restrict__ Oh, fp16* __restrict__ Ol)
{
    GEMM_PREAMBLE
    int rowA0 = blockIdx.y * 128, col0 = blockIdx.x * 128;
    GEMM_MAIN(Ah, Bh, Bl, C_, C_, 0, C_ / 32);

    uint32_t* oh = (uint32_t*)Oh;
    uint32_t* ol = (uint32_t*)Ol;
#pragma unroll
    for (int mt = 0; mt < 2; mt++)
#pragma unroll
        for (int nt = 0; nt < 8; nt++) {
            int r = rowA0 + m0 + mt * 16 + g;
            int n = col0 + n0 + nt * 8 + tig * 2;
            uint32_t hw, lw;
            size_t ix0 = ((size_t)r * HF + n) >> 1;
            size_t ix1 = ((size_t)(r + 8) * HF + n) >> 1;
            hsplit2(acc[mt][nt][0], acc[mt][nt][1], hw, lw);
            oh[ix0] = hw;
            if (ol) ol[ix0] = lw;
            hsplit2(acc[mt][nt][2], acc[mt][nt][3], hw, lw);
            oh[ix1] = hw;
            if (ol) ol[ix1] = lw;
        }
}

// ---------------- kernel: yq/yk GEMM, split-K x4 -------------------------------
__global__ __launch_bounds__(256, 2) void y_gemm(
    const fp16* __restrict__ Ah,
    const fp16* __restrict__ B0h, const fp16* __restrict__ B0l,
    const fp16* __restrict__ B1h, const fp16* __restrict__ B1l,
    float* __restrict__ ypart)
{
    GEMM_PREAMBLE
    int z = blockIdx.z;
    const fp16* Bh = (z >= 4) ? B1h : B0h;
    const fp16* Bl = (z >= 4) ? B1l : B0l;
    int kb = (z & 3) * 384;
    int rowA0 = blockIdx.y * 128, col0 = 0;
    GEMM_MAIN(Ah, Bh, Bl, C_, C_, kb, 12);
    float* C = ypart + (size_t)z * M_ * F_;
    EPI_F32(C, F_, 1.0f)
}

// ---------------- kernel: QK GEMM (fp16 out) -----------------------------------
__global__ __launch_bounds__(256, 2) void qk_gemm(
    const fp16* __restrict__ Ahb,
    const fp16* __restrict__ Bhb, const fp16* __restrict__ Blb,
    fp16* __restrict__ Cbase)
{
    GEMM_PREAMBLE
    int z = blockIdx.z, b = z >> 5, h = z & 31;
    const fp16* Ah = Ahb + (size_t)b * P_ * HF + h * F_;
    const fp16* Bh = Bhb + (size_t)b * P_ * HF + h * F_;
    const fp16* Bl = Blb + (size_t)b * P_ * HF + h * F_;
    __half2* C = (__half2*)(Cbase + (size_t)z * P_ * P_);
    int rowA0 = blockIdx.y * 128, col0 = blockIdx.x * 128;
    GEMM_MAIN(Ah, Bh, Bl, HF, HF, 0, 4);

#pragma unroll
    for (int mt = 0; mt < 2; mt++)
#pragma unroll
        for (int nt = 0; nt < 8; nt++) {
            int r = rowA0 + m0 + mt * 16 + g;
            int cix = col0 + n0 + nt * 8 + tig * 2;
            C[((size_t)r * P_ + cix) >> 1] =
                __floats2half2_rn(acc[mt][nt][0], acc[mt][nt][1]);
            C[((size_t)(r + 8) * P_ + cix) >> 1] =
                __floats2half2_rn(acc[mt][nt][2], acc[mt][nt][3]);
        }
}

// ---------------- kernel: Qp+Kp merged band GEMM (fp16, SHIFTED rows) ----------
// row r stored shifted by (r&31): element (r, j) lives at stored col j + (r&31)
__global__ __launch_bounds__(256, 2) void qpkp_gemm(
    const fp16* __restrict__ qA, const fp16* __restrict__ kA,
    const fp16* __restrict__ Bh, const fp16* __restrict__ Bl,
    fp16* __restrict__ Qp, fp16* __restrict__ Kp,
    const float* __restrict__ biasT)
{
    GEMM_PREAMBLE
    int z = blockIdx.z;
    int sel = z >> 6, zz = z & 63, b = zz >> 5, h = zz & 31;
    int i = blockIdx.x;
    int ty = i / 5, tx = 3 - ty + (i % 5);
    const fp16* Ahp = (sel ? kA : qA) + (size_t)b * P_ * HF + h * F_;
    const fp16* Bhp = Bh + (size_t)h * F_;
    const fp16* Blp = Bl + (size_t)h * F_;
    fp16* C = (sel ? Kp : Qp) + (size_t)zz * P_ * P2S;
    const float* bp = biasT + (size_t)sel * H_ * P2 + (size_t)h * P2;
    int rowA0 = ty * 128, col0 = tx * 128;
    GEMM_MAIN(Ahp, Bhp, Blp, HF, HF, 0, 4);

#pragma unroll
    for (int mt = 0; mt < 2; mt++)
#pragma unroll
        for (int nt = 0; nt < 8; nt++) {
            int cix = col0 + n0 + nt * 8 + tig * 2;
            float2 bb = *(const float2*)(bp + cix);
#pragma unroll
            for (int half = 0; half < 2; half++) {
                int r = rowA0 + m0 + mt * 16 + g + half * 8;
                int sh = r & 31;
                size_t base = (size_t)r * P2S + cix + sh;
                C[base]     = __float2half(acc[mt][nt][half * 2]     * 0.25f + bb.x);
                C[base + 1] = __float2half(acc[mt][nt][half * 2 + 1] * 0.25f + bb.y);
            }
        }
}

// ---------------- kernel: fused gather (bank-spread) + HMMA a@Wout -------------
#define FIN_A   0
#define FIN_YQ  81920
#define FIN_YK  (FIN_YQ + 16384)
#define FIN_WH  (FIN_YK + 16384)
#define FIN_WL  (FIN_WH + 10240)
#define SMEM_FINAL (FIN_WL + 10240)
#define M128 (M_ * F_)

__global__ __launch_bounds__(256) void final_kernel(
    const fp16* __restrict__ QK, const fp16* __restrict__ Qp,
    const fp16* __restrict__ Kp, const float* __restrict__ ypart,
    const float* __restrict__ Wout, const float* __restrict__ bout,
    float* __restrict__ out)
{
    extern __shared__ char smem[];
    __half* a_s  = (__half*)smem;
    float*  yq_s = (float*)(smem + FIN_YQ);
    float*  yk_s = (float*)(smem + FIN_YK);
    __half* wh_s = (__half*)(smem + FIN_WH);
    __half* wl_s = (__half*)(smem + FIN_WL);
    uint32_t smb = (uint32_t)__cvta_generic_to_shared(smem);

    int b  = blockIdx.z;
    int qt = blockIdx.y * 32;
    int kt = blockIdx.x * 32;
    int tid = threadIdx.x;

    // stage Wout^T split hi/lo, stride-40-half rows (rows = f)
    for (int i = tid; i < 32 * 128; i += 256) {
        int h = i >> 7, f = i & 127;
        float v = Wout[h * F_ + f];
        __half hi = __float2half(v);
        wh_s[f * 40 + h] = hi;
        wl_s[f * 40 + h] = __float2half(v - __half2float(hi));
    }

    // stage yq (+bout) / yk, float4 vectorized
    for (int i = tid; i < 1024; i += 256) {
        int q = i >> 5, f = (i & 31) * 4;
        size_t rq = ((size_t)(b * P_ + qt + q)) * F_ + f;
        size_t rk = ((size_t)(b * P_ + kt + q)) * F_ + f;
        float4 vq = *(const float4*)(bout + f);
        float4 vk = make_float4(0.f, 0.f, 0.f, 0.f);
#pragma unroll
        for (int s = 0; s < 4; s++) {
            float4 a = *(const float4*)(ypart + (size_t)s * M128 + rq);
            float4 c = *(const float4*)(ypart + (size_t)(4 + s) * M128 + rk);
            vq.x += a.x; vq.y += a.y; vq.z += a.z; vq.w += a.w;
            vk.x += c.x; vk.y += c.y; vk.z += c.z; vk.w += c.w;
        }
        *(float4*)(yq_s + q * 128 + f) = vq;
        *(float4*)(yk_s + q * 128 + f) = vk;
    }

    // gather phase 1: a = QK + Qp.  Lane mapping spreads h across lanes
    // (bits: [3:0]=h_lo, [5:4]=k0 group, [10:6]=q, [11]=h_hi) so STS hits
    // 8 banks instead of 1; k0 lane pairs stay 32B-sector coalesced on LDG.
    for (int i = tid; i < 4096; i += 256) {
        int h  = (i & 15) | ((i >> 7) & 16);
        int k0 = ((i >> 4) & 3) * 8;
        int q  = (i >> 6) & 31;
        int gq = qt + q;
        size_t zb = (size_t)(b * 32 + h);
        uint4 vqk = *(const uint4*)(QK + (zb * P_ + gq) * P_ + kt + k0);
        uint4 vqp = *(const uint4*)(Qp + (zb * P_ + gq) * P2S + (P_ + kt - qt + k0));
        const __half2* hqk = (const __half2*)&vqk;
        const __half2* hqp = (const __half2*)&vqp;
        int m = q * 32 + k0;
#pragma unroll
        for (int j = 0; j < 4; j++) {
            __half2 s = __hadd2(hqk[j], hqp[j]);
            a_s[(m + 2 * j)     * 40 + h] = __low2half(s);
            a_s[(m + 2 * j + 1) * 40 + h] = __high2half(s);
        }
    }
    __syncthreads();

    // gather phase 2: a += Kp (same h-spread lane mapping)
    for (int i = tid; i < 4096; i += 256) {
        int h  = (i & 15) | ((i >> 7) & 16);
        int q0 = ((i >> 4) & 3) * 8;
        int k  = (i >> 6) & 31;
        int gk = kt + k;
        size_t zb = (size_t)(b * 32 + h);
        uint4 vkp = *(const uint4*)(Kp + (zb * P_ + gk) * P2S + (P_ + qt - kt + q0));
        const __half* hk = (const __half*)&vkp;
#pragma unroll
        for (int j = 0; j < 8; j++) {
            int ix = ((q0 + j) * 32 + k) * 40 + h;
            a_s[ix] = __hadd(a_s[ix], hk[j]);
        }
    }
    __syncthreads();

    // HMMA: out[m,f] = a[m,h] @ WoutT[f,h], M=1024 N=128 K=32  (R11-proven)
    int warp = tid >> 5, lane = tid & 31;
    int g = lane >> 2, tig = lane & 3;
    int lr = lane & 15, lh = lane >> 4;
    int warpM = warp * 128;

    uint32_t af[8][2][4];
#pragma unroll
    for (int mf = 0; mf < 8; mf++)
#pragma unroll
        for (int ks = 0; ks < 2; ks++) {
            uint32_t aa = smb + ((warpM + mf * 16 + lr) * 20 + lh * 4 + ks * 8) * 4;
            LDSM4(af[mf][ks][0], af[mf][ks][1], af[mf][ks][2], af[mf][ks][3], aa);
        }

#pragma unroll
    for (int np = 0; np < 4; np++) {      // 4 passes over f (32 cols each)
        float acc[8][4][4];
#pragma unroll
        for (int i = 0; i < 8; i++)
#pragma unroll
            for (int j = 0; j < 4; j++)
#pragma unroll
                for (int l = 0; l < 4; l++) acc[i][j][l] = 0.f;

#pragma unroll
        for (int ks = 0; ks < 2; ks++) {
            uint32_t bh[4][2], bl[4][2];
#pragma unroll
            for (int tp = 0; tp < 2; tp++) {
                uint32_t ba = smb + FIN_WH +
                    ((np * 32 + tp * 16 + lr) * 20 + lh * 4 + ks * 8) * 4;
                LDSM4(bh[2*tp][0], bh[2*tp+1][0], bh[2*tp][1], bh[2*tp+1][1], ba);
                LDSM4(bl[2*tp][0], bl[2*tp+1][0], bl[2*tp][1], bl[2*tp+1][1],
                      ba + 10240u);
            }
#pragma unroll
            for (int mf = 0; mf < 8; mf++)
#pragma unroll
                for (int nf = 0; nf < 4; nf++) {
                    MMA_FP16(acc[mf][nf], af[mf][ks], bh[nf]);
                    MMA_FP16(acc[mf][nf], af[mf][ks], bl[nf]);
                }
        }

        // store pass: add yq+bout and yk, write fp32 out (R11-proven)
#pragma unroll
        for (int mf = 0; mf < 8; mf++)
#pragma unroll
            for (int nf = 0; nf < 4; nf++) {
                int f = np * 32 + nf * 8 + tig * 2;
#pragma unroll
                for (int half = 0; half < 2; half++) {
                    int r = warpM + mf * 16 + g + half * 8;
                    int q = r >> 5, k = r & 31;
                    float b0 = yq_s[q * 128 + f]     + yk_s[k * 128 + f];
                    float b1 = yq_s[q * 128 + f + 1] + yk_s[k * 128 + f + 1];
                    float* orow = out +
                        (((size_t)(b * P_) + qt + q) * P_ + kt + k) * F_ + f;
                    *(float2*)orow = make_float2(acc[mf][nf][half * 2] + b0,
                                                 acc[mf][nf][half * 2 + 1] + b1);
                }
            }
    }
}

// ---------------- launch ------------------------------------------------------
extern "C" void kernel_launch(void* const* d_in, const int* in_sizes, int n_in,
                              void* d_out, int out_size)
{
    const float* x        = (const float*)d_in[0];
    const float* norm_w   = (const float*)d_in[1];
    const float* Wq       = (const float*)d_in[2];
    const float* Wk       = (const float*)d_in[3];
    const float* Wpos     = (const float*)d_in[4];
    const float* bpos     = (const float*)d_in[5];
    const float* q_r_bias = (const float*)d_in[6];
    const float* k_r_bias = (const float*)d_in[7];
    const float* Wyq      = (const float*)d_in[8];
    const float* Wyk      = (const float*)d_in[9];
    const float* Wout     = (const float*)d_in[10];
    const float* bout     = (const float*)d_in[11];
    float* out = (float*)d_out;

    fp16 *p_xnh, *p_xgh;
    fp16 *p_wqth, *p_wqtl, *p_wkth, *p_wktl, *p_wyqh, *p_wyql, *p_wykh, *p_wykl;
    fp16 *p_posh, *p_posl, *p_qh, *p_kh, *p_kl, *p_QK, *p_Qp, *p_Kp;
    float *p_bias, *p_ypart;
    cudaGetSymbolAddress((void**)&p_xnh,  g_xnh);
    cudaGetSymbolAddress((void**)&p_xgh,  g_xgh);
    cudaGetSymbolAddress((void**)&p_wqth, g_wqth);
    cudaGetSymbolAddress((void**)&p_wqtl, g_wqtl);
    cudaGetSymbolAddress((void**)&p_wkth, g_wkth);
    cudaGetSymbolAddress((void**)&p_wktl, g_wktl);
    cudaGetSymbolAddress((void**)&p_wyqh, g_wyqh);
    cudaGetSymbolAddress((void**)&p_wyql, g_wyql);
    cudaGetSymbolAddress((void**)&p_wykh, g_wykh);
    cudaGetSymbolAddress((void**)&p_wykl, g_wykl);
    cudaGetSymbolAddress((void**)&p_posh, g_posh);
    cudaGetSymbolAddress((void**)&p_posl, g_posl);
    cudaGetSymbolAddress((void**)&p_qh,   g_qh);
    cudaGetSymbolAddress((void**)&p_kh,   g_kh);
    cudaGetSymbolAddress((void**)&p_kl,   g_kl);
    cudaGetSymbolAddress((void**)&p_bias, g_bias);
    cudaGetSymbolAddress((void**)&p_ypart, g_ypart);
    cudaGetSymbolAddress((void**)&p_QK,   g_QK);
    cudaGetSymbolAddress((void**)&p_Qp,   g_Qp);
    cudaGetSymbolAddress((void**)&p_Kp,   g_Kp);

    cudaFuncSetAttribute(proj_gemm, cudaFuncAttributeMaxDynamicSharedMemorySize, GEMM_SMEM);
    cudaFuncSetAttribute(y_gemm,    cudaFuncAttributeMaxDynamicSharedMemorySize, GEMM_SMEM);
    cudaFuncSetAttribute(qk_gemm,   cudaFuncAttributeMaxDynamicSharedMemorySize, GEMM_SMEM);
    cudaFuncSetAttribute(qpkp_gemm, cudaFuncAttributeMaxDynamicSharedMemorySize, GEMM_SMEM);
    cudaFuncSetAttribute(final_kernel, cudaFuncAttributeMaxDynamicSharedMemorySize, SMEM_FINAL);

    wconv_kernel<<<dim3(128, 48), 256>>>(Wq, p_wqth, p_wqtl, C_, HF);  // 0
    wconv_kernel<<<dim3(128, 48), 256>>>(Wk, p_wkth, p_wktl, C_, HF);  // 1
    pool_norm_kernel<<<1024, 256>>>(x, norm_w);                        // 2
    proj_gemm<<<dim3(32, 8), 256, GEMM_SMEM>>>(                        // 3
        p_xnh, p_wqth, p_wqtl, p_qh, (fp16*)0);
    proj_gemm<<<dim3(32, 8), 256, GEMM_SMEM>>>(                        // 4
        p_xnh, p_wkth, p_wktl, p_kh, p_kl);

    pos_kernel<<<1024, 128>>>(Wpos, bpos);
    bias_kernel<<<1024, 256>>>(q_r_bias, k_r_bias);
    wconv_kernel<<<dim3(4, 48), 256>>>(Wyq, p_wyqh, p_wyql, C_, F_);
    wconv_kernel<<<dim3(4, 48), 256>>>(Wyk, p_wykh, p_wykl, C_, F_);
    y_gemm<<<dim3(1, 8, 8), 256, GEMM_SMEM>>>(
        p_xgh, p_wyqh, p_wyql, p_wykh, p_wykl, p_ypart);

    qk_gemm<<<dim3(4, 4, 64), 256, GEMM_SMEM>>>(p_qh, p_kh, p_kl, p_QK);
    qpkp_gemm<<<dim3(20, 1, 128), 256, GEMM_SMEM>>>(
        p_qh, p_kh, p_posh, p_posl, p_Qp, p_Kp, p_bias);

    final_kernel<<<dim3(16, 16, 2), 256, SMEM_FINAL>>>(
        p_QK, p_Qp, p_Kp, p_ypart, Wout, bout, out);
}

// round 15
// speedup vs baseline: 1.2362x; 1.0658x over previous
#include <cuda_runtime.h>
#include <cuda_fp16.h>
#include <math.h>
#include <stdint.h>

typedef __half fp16;

#define B_   2
#define S_   8192
#define C_   1536
#define P_   512
#define H_   32
#define F_   128
#define HF   4096
#define P2   1024
#define P2S  1056     // padded row width for shifted Qp/Kp storage
#define M_   1024     // B_*P_

// ---------------- scratch (device globals) ------------------------------------
__device__ __align__(16) fp16 g_xnh[M_ * C_];
__device__ __align__(16) fp16 g_xgh[M_ * C_];
__device__ __align__(16) fp16 g_wqth[HF * C_], g_wqtl[HF * C_];
__device__ __align__(16) fp16 g_wkth[HF * C_], g_wktl[HF * C_];
__device__ __align__(16) fp16 g_wyqh[F_ * C_], g_wyql[F_ * C_];
__device__ __align__(16) fp16 g_wykh[F_ * C_], g_wykl[F_ * C_];
__device__ __align__(16) fp16 g_posh[P2 * HF], g_posl[P2 * HF];
__device__ __align__(16) fp16 g_qh [M_ * HF];
__device__ __align__(16) fp16 g_kh [M_ * HF], g_kl[M_ * HF];
__device__ float g_bias [2 * H_ * P2];
__device__ float g_ypart[8 * M_ * F_];
__device__ __align__(16) fp16 g_QK [(size_t)B_ * H_ * P_ * P_];
__device__ __align__(16) fp16 g_Qp [(size_t)B_ * H_ * P_ * P2S];  // shifted rows
__device__ __align__(16) fp16 g_Kp [(size_t)B_ * H_ * P_ * P2S];  // shifted rows

// ---------------- helpers ------------------------------------------------------
__device__ __forceinline__ void hsplit2(float x, float y, uint32_t& hw, uint32_t& lw)
{
    __half hx = __float2half(x);
    __half hy = __float2half(y);
    __half lx = __float2half(x - __half2float(hx));
    __half ly = __float2half(y - __half2float(hy));
    __half2 hp = __halves2half2(hx, hy);
    __half2 lp = __halves2half2(lx, ly);
    hw = *reinterpret_cast<uint32_t*>(&hp);
    lw = *reinterpret_cast<uint32_t*>(&lp);
}

__device__ __forceinline__ void cp16(uint32_t* smem_ptr, const fp16* gptr)
{
    uint32_t s = (uint32_t)__cvta_generic_to_shared(smem_ptr);
    asm volatile("cp.async.cg.shared.global [%0], [%1], 16;\n" :: "r"(s), "l"(gptr));
}

#define MMA_FP16(c, a, b)                                                       \
    asm volatile(                                                               \
        "mma.sync.aligned.m16n8k16.row.col.f32.f16.f16.f32 "                    \
        "{%0,%1,%2,%3}, {%4,%5,%6,%7}, {%8,%9}, {%0,%1,%2,%3};\n"               \
        : "+f"((c)[0]), "+f"((c)[1]), "+f"((c)[2]), "+f"((c)[3])                \
        : "r"((a)[0]), "r"((a)[1]), "r"((a)[2]), "r"((a)[3]),                   \
          "r"((b)[0]), "r"((b)[1]))

#define LDSM4(d0, d1, d2, d3, a)                                                \
    asm volatile(                                                               \
        "ldmatrix.sync.aligned.m8n8.x4.shared.b16 {%0,%1,%2,%3}, [%4];\n"       \
        : "=r"(d0), "=r"(d1), "=r"(d2), "=r"(d3) : "r"(a))

// one k16 sub-step, 4(m)x2(n) warp layout.
// hi-sweep then lo-sweep: per-acc order unchanged (bitwise identical), but
// adjacent MMAs now hit different accumulators -> no dependent back-to-back.
#define FRAG_LDSM(sst, j0)                                                      \
    do {                                                                        \
        uint32_t ah[2][4], bh[8][2], bl[8][2];                                  \
        _Pragma("unroll")                                                       \
        for (int mt = 0; mt < 2; mt++) {                                        \
            uint32_t aa = (sst) + aoff + mt * 1280u + (j0) * 4u;                \
            LDSM4(ah[mt][0], ah[mt][1], ah[mt][2], ah[mt][3], aa);              \
        }                                                                       \
        _Pragma("unroll")                                                       \
        for (int tp = 0; tp < 4; tp++) {                                        \
            uint32_t ba = (sst) + boff + tp * 1280u + (j0) * 4u + 10240u;       \
            LDSM4(bh[2*tp][0], bh[2*tp+1][0], bh[2*tp][1], bh[2*tp+1][1], ba);  \
            LDSM4(bl[2*tp][0], bl[2*tp+1][0], bl[2*tp][1], bl[2*tp+1][1],       \
                  ba + 10240u);                                                 \
        }                                                                       \
        _Pragma("unroll")                                                       \
        for (int mt = 0; mt < 2; mt++)                                          \
            _Pragma("unroll")                                                   \
            for (int nt = 0; nt < 8; nt++)                                      \
                MMA_FP16(acc[mt][nt], ah[mt], bh[nt]);                          \
        _Pragma("unroll")                                                       \
        for (int mt = 0; mt < 2; mt++)                                          \
            _Pragma("unroll")                                                   \
            for (int nt = 0; nt < 8; nt++)                                      \
                MMA_FP16(acc[mt][nt], ah[mt], bl[nt]);                          \
    } while (0)

// stage = [Ah 10240B][Bh 10240B][Bl 10240B] = 30720B; 3 stages
#define LOAD_STAGE(s, kpos, Ah, Bh, Bl, lda, ldb)                               \
    {                                                                           \
        uint32_t* sb = sm + (s) * 7680;                                         \
        _Pragma("unroll")                                                       \
        for (int ci = 0; ci < 2; ci++) {                                        \
            int qq = tid + ci * 256;                                            \
            int rw = qq >> 2, cc = qq & 3;                                      \
            uint32_t so = rw * 20 + cc * 4;                                     \
            size_t ga = (size_t)(rowA0 + rw) * (lda) + (kpos) + cc * 8;         \
            size_t gb = (size_t)(col0 + rw) * (ldb) + (kpos) + cc * 8;          \
            cp16(sb + so,        (Ah) + ga);                                    \
            cp16(sb + 2560 + so, (Bh) + gb);                                    \
            cp16(sb + 5120 + so, (Bl) + gb);                                    \
        }                                                                       \
    }

// 3-stage cp.async pipeline (requires nk >= 2)
#define GEMM_MAIN(Ah, Bh, Bl, lda, ldb, kb, nk)                                 \
    {                                                                           \
        LOAD_STAGE(0, (kb), Ah, Bh, Bl, lda, ldb);                              \
        asm volatile("cp.async.commit_group;\n");                               \
        LOAD_STAGE(1, (kb) + 32, Ah, Bh, Bl, lda, ldb);                         \
        asm volatile("cp.async.commit_group;\n");                               \
        for (int it = 0; it < (nk); it++) {                                     \
            if (it + 2 < (nk)) asm volatile("cp.async.wait_group 1;\n");        \
            else               asm volatile("cp.async.wait_group 0;\n");        \
            __syncthreads();                                                    \
            uint32_t sst = smb + (uint32_t)((it % 3) * 30720);                  \
            FRAG_LDSM(sst, 0);                                                  \
            if (it + 2 < (nk)) {                                                \
                LOAD_STAGE((it + 2) % 3, (kb) + (it + 2) * 32,                  \
                           Ah, Bh, Bl, lda, ldb);                               \
                asm volatile("cp.async.commit_group;\n");                       \
            }                                                                   \
            FRAG_LDSM(sst, 8);                                                  \
        }                                                                       \
    }

// 4(m) x 2(n) warp layout
#define GEMM_PREAMBLE                                                           \
    extern __shared__ uint32_t sm[];                                            \
    uint32_t smb = (uint32_t)__cvta_generic_to_shared(sm);                      \
    int tid = threadIdx.x;                                                      \
    int warp = tid >> 5, lane = tid & 31;                                       \
    int g = lane >> 2, tig = lane & 3;                                          \
    int lr = lane & 15, lh = lane >> 4;                                         \
    int m0 = (warp >> 1) * 32, n0 = (warp & 1) * 64;                            \
    uint32_t aoff = ((m0 + lr) * 20 + lh * 4) * 4;                              \
    uint32_t boff = ((n0 + lr) * 20 + lh * 4) * 4;                              \
    float acc[2][8][4];                                                         \
    _Pragma("unroll")                                                           \
    for (int i = 0; i < 2; i++)                                                 \
        _Pragma("unroll")                                                       \
        for (int j = 0; j < 8; j++)                                             \
            _Pragma("unroll")                                                   \
            for (int l = 0; l < 4; l++) acc[i][j][l] = 0.f;

#define EPI_F32(Cp, ldc, alpha)                                                 \
    _Pragma("unroll")                                                           \
    for (int mt = 0; mt < 2; mt++)                                              \
        _Pragma("unroll")                                                       \
        for (int nt = 0; nt < 8; nt++) {                                        \
            int r = rowA0 + m0 + mt * 16 + g;                                   \
            int cix = col0 + n0 + nt * 8 + tig * 2;                             \
            *(float2*)((Cp) + (size_t)r * (ldc) + cix) =                        \
                make_float2(acc[mt][nt][0] * (alpha), acc[mt][nt][1] * (alpha));\
            *(float2*)((Cp) + (size_t)(r + 8) * (ldc) + cix) =                  \
                make_float2(acc[mt][nt][2] * (alpha), acc[mt][nt][3] * (alpha));\
        }

#define GEMM_SMEM 92160

// ---------------- kernel: pool + RMS norm + GELU (hi fp16 out) ----------------
__global__ __launch_bounds__(256) void pool_norm_kernel(
    const float* __restrict__ x, const float* __restrict__ norm_w)
{
    int bid = blockIdx.x;
    int b = bid >> 9, p = bid & 511;
    int tid = threadIdx.x;

    const float* xrow = x + ((size_t)b * S_ + (size_t)p * 16) * C_;
    float xp[6];
#pragma unroll
    for (int j = 0; j < 6; j++) xp[j] = 0.f;
    for (int r = 0; r < 16; r++) {
        const float* xr = xrow + (size_t)r * C_;
#pragma unroll
        for (int j = 0; j < 6; j++) xp[j] += xr[tid + j * 256];
    }
    float ssq = 0.f;
#pragma unroll
    for (int j = 0; j < 6; j++) { xp[j] *= (1.f / 16.f); ssq += xp[j] * xp[j]; }

    __shared__ float red[256];
    red[tid] = ssq;
    __syncthreads();
    for (int s = 128; s > 0; s >>= 1) {
        if (tid < s) red[tid] += red[tid + s];
        __syncthreads();
    }
    float scale = 1.f / sqrtf(red[0] * (1.f / (float)C_) + 1e-8f);

    size_t base = (size_t)bid * C_;
#pragma unroll
    for (int j = 0; j < 6; j++) {
        int ch = tid + j * 256;
        float v = xp[j] * scale * norm_w[ch];
        float gv = v * 0.5f * (1.f + erff(v * 0.70710678118654752f));
        g_xnh[base + ch] = __float2half(v);
        g_xgh[base + ch] = __float2half(gv);
    }
}

// ---------------- kernel: pos features @ Wpos + bpos (split fp16 out) ---------
__global__ __launch_bounds__(128) void pos_kernel(
    const float* __restrict__ Wpos, const float* __restrict__ bpos)
{
    int d   = blockIdx.x;
    int tid = threadIdx.x;
    __shared__ float feat[32];

    int rel = d - P_;
    if (tid < 16) {
        double geo = exp((double)tid * (log(497.0) / 16.0));
        float center = (float)tid + (float)geo;
        float oh = (center > fabsf((float)rel)) ? 1.f : 0.f;
        float sg = (rel > 0) ? 1.f : ((rel < 0) ? -1.f : 0.f);
        feat[tid]      = oh;
        feat[tid + 16] = oh * sg;
    }
    __syncthreads();

    float f[32];
#pragma unroll
    for (int c = 0; c < 32; c++) f[c] = feat[c];

    for (int n = tid; n < HF; n += 128) {
        float acc = bpos[n];
#pragma unroll
        for (int c = 0; c < 32; c++) acc += f[c] * Wpos[c * HF + n];
        __half h = __float2half(acc);
        g_posh[(size_t)d * HF + n] = h;
        g_posl[(size_t)d * HF + n] = __float2half(acc - __half2float(h));
    }
}

// ---------------- kernel: rel-bias tables Bias[sel][h][d] = 0.25*rb·pos -------
__global__ __launch_bounds__(256) void bias_kernel(
    const float* __restrict__ qrb, const float* __restrict__ krb)
{
    int d = blockIdx.x;
    int lane = threadIdx.x & 31, w = threadIdx.x >> 5;
    for (int h = w; h < H_; h += 8) {
        float sq = 0.f, sk = 0.f;
        size_t pb = (size_t)d * HF + h * F_;
        for (int c = lane; c < F_; c += 32) {
            float pv = __half2float(g_posh[pb + c]) + __half2float(g_posl[pb + c]);
            sq += qrb[h * F_ + c] * pv;
            sk += krb[h * F_ + c] * pv;
        }
#pragma unroll
        for (int o = 16; o; o >>= 1) {
            sq += __shfl_xor_sync(0xffffffffu, sq, o);
            sk += __shfl_xor_sync(0xffffffffu, sk, o);
        }
        if (lane == 0) {
            g_bias[h * P2 + d]           = 0.25f * sq;
            g_bias[H_ * P2 + h * P2 + d] = 0.25f * sk;
        }
    }
}

// ---------------- kernel: weight transpose-convert W[K,N] -> T[N,K] split -----
__global__ __launch_bounds__(256) void wconv_kernel(
    const float* __restrict__ W, fp16* __restrict__ Th, fp16* __restrict__ Tl,
    int K, int N)
{
    __shared__ float t[32][33];
    int nt0 = blockIdx.x * 32, kt0 = blockIdx.y * 32;
    int tx = threadIdx.x & 31, ty = threadIdx.x >> 5;
#pragma unroll
    for (int i = 0; i < 4; i++)
        t[ty + i * 8][tx] = W[(size_t)(kt0 + ty + i * 8) * N + nt0 + tx];
    __syncthreads();
#pragma unroll
    for (int i = 0; i < 4; i++) {
        int n = nt0 + ty + i * 8, k = kt0 + tx;
        float v = t[tx][ty + i * 8];
        __half h = __float2half(v);
        Th[(size_t)n * K + k] = h;
        Tl[(size_t)n * K + k] = __float2half(v - __half2float(h));
    }
}

// ---------------- kernel: projection GEMM (q/k) -------------------------------
__global__ __launch_bounds__(256, 2) void proj_gemm(
    const fp16* __restrict__ Ah,
    const fp16* __restrict__ Bh, const fp16* __restrict__ Bl,
    fp16* __restrict__ Oh, fp16* __restrict__ Ol)
{
    GEMM_PREAMBLE
    int rowA0 = blockIdx.y * 128, col0 = blockIdx.x * 128;
    GEMM_MAIN(Ah, Bh, Bl, C_, C_, 0, C_ / 32);

    uint32_t* oh = (uint32_t*)Oh;
    uint32_t* ol = (uint32_t*)Ol;
#pragma unroll
    for (int mt = 0; mt < 2; mt++)
#pragma unroll
        for (int nt = 0; nt < 8; nt++) {
            int r = rowA0 + m0 + mt * 16 + g;
            int n = col0 + n0 + nt * 8 + tig * 2;
            uint32_t hw, lw;
            size_t ix0 = ((size_t)r * HF + n) >> 1;
            size_t ix1 = ((size_t)(r + 8) * HF + n) >> 1;
            hsplit2(acc[mt][nt][0], acc[mt][nt][1], hw, lw);
            oh[ix0] = hw;
            if (ol) ol[ix0] = lw;
            hsplit2(acc[mt][nt][2], acc[mt][nt][3], hw, lw);
            oh[ix1] = hw;
            if (ol) ol[ix1] = lw;
        }
}

// ---------------- kernel: yq/yk GEMM, split-K x4 -------------------------------
__global__ __launch_bounds__(256, 2) void y_gemm(
    const fp16* __restrict__ Ah,
    const fp16* __restrict__ B0h, const fp16* __restrict__ B0l,
    const fp16* __restrict__ B1h, const fp16* __restrict__ B1l,
    float* __restrict__ ypart)
{
    GEMM_PREAMBLE
    int z = blockIdx.z;
    const fp16* Bh = (z >= 4) ? B1h : B0h;
    const fp16* Bl = (z >= 4) ? B1l : B0l;
    int kb = (z & 3) * 384;
    int rowA0 = blockIdx.y * 128, col0 = 0;
    GEMM_MAIN(Ah, Bh, Bl, C_, C_, kb, 12);
    float* C = ypart + (size_t)z * M_ * F_;
    EPI_F32(C, F_, 1.0f)
}

// ---------------- kernel: QK GEMM (fp16 out) -----------------------------------
__global__ __launch_bounds__(256, 2) void qk_gemm(
    const fp16* __restrict__ Ahb,
    const fp16* __restrict__ Bhb, const fp16* __restrict__ Blb,
    fp16* __restrict__ Cbase)
{
    GEMM_PREAMBLE
    int z = blockIdx.z, b = z >> 5, h = z & 31;
    const fp16* Ah = Ahb + (size_t)b * P_ * HF + h * F_;
    const fp16* Bh = Bhb + (size_t)b * P_ * HF + h * F_;
    const fp16* Bl = Blb + (size_t)b * P_ * HF + h * F_;
    __half2* C = (__half2*)(Cbase + (size_t)z * P_ * P_);
    int rowA0 = blockIdx.y * 128, col0 = blockIdx.x * 128;
    GEMM_MAIN(Ah, Bh, Bl, HF, HF, 0, 4);

#pragma unroll
    for (int mt = 0; mt < 2; mt++)
#pragma unroll
        for (int nt = 0; nt < 8; nt++) {
            int r = rowA0 + m0 + mt * 16 + g;
            int cix = col0 + n0 + nt * 8 + tig * 2;
            C[((size_t)r * P_ + cix) >> 1] =
                __floats2half2_rn(acc[mt][nt][0], acc[mt][nt][1]);
            C[((size_t)(r + 8) * P_ + cix) >> 1] =
                __floats2half2_rn(acc[mt][nt][2], acc[mt][nt][3]);
        }
}

// ---------------- kernel: Qp+Kp merged band GEMM (fp16, SHIFTED rows) ----------
// row r stored shifted by (r&31): element (r, j) lives at stored col j + (r&31)
__global__ __launch_bounds__(256, 2) void qpkp_gemm(
    const fp16* __restrict__ qA, const fp16* __restrict__ kA,
    const fp16* __restrict__ Bh, const fp16* __restrict__ Bl,
    fp16* __restrict__ Qp, fp16* __restrict__ Kp,
    const float* __restrict__ biasT)
{
    GEMM_PREAMBLE
    int z = blockIdx.z;
    int sel = z >> 6, zz = z & 63, b = zz >> 5, h = zz & 31;
    int i = blockIdx.x;
    int ty = i / 5, tx = 3 - ty + (i % 5);
    const fp16* Ahp = (sel ? kA : qA) + (size_t)b * P_ * HF + h * F_;
    const fp16* Bhp = Bh + (size_t)h * F_;
    const fp16* Blp = Bl + (size_t)h * F_;
    fp16* C = (sel ? Kp : Qp) + (size_t)zz * P_ * P2S;
    const float* bp = biasT + (size_t)sel * H_ * P2 + (size_t)h * P2;
    int rowA0 = ty * 128, col0 = tx * 128;
    GEMM_MAIN(Ahp, Bhp, Blp, HF, HF, 0, 4);

#pragma unroll
    for (int mt = 0; mt < 2; mt++)
#pragma unroll
        for (int nt = 0; nt < 8; nt++) {
            int cix = col0 + n0 + nt * 8 + tig * 2;
            float2 bb = *(const float2*)(bp + cix);
#pragma unroll
            for (int half = 0; half < 2; half++) {
                int r = rowA0 + m0 + mt * 16 + g + half * 8;
                int sh = r & 31;
                size_t base = (size_t)r * P2S + cix + sh;
                C[base]     = __float2half(acc[mt][nt][half * 2]     * 0.25f + bb.x);
                C[base + 1] = __float2half(acc[mt][nt][half * 2 + 1] * 0.25f + bb.y);
            }
        }
}

// ---------------- kernel: fused gather + HMMA a@Wout (512 threads) -------------
#define FIN_A   0
#define FIN_YQ  81920
#define FIN_YK  (FIN_YQ + 16384)
#define FIN_WH  (FIN_YK + 16384)
#define FIN_WL  (FIN_WH + 10240)
#define SMEM_FINAL (FIN_WL + 10240)
#define M128 (M_ * F_)

__global__ __launch_bounds__(512) void final_kernel(
    const fp16* __restrict__ QK, const fp16* __restrict__ Qp,
    const fp16* __restrict__ Kp, const float* __restrict__ ypart,
    const float* __restrict__ Wout, const float* __restrict__ bout,
    float* __restrict__ out)
{
    extern __shared__ char smem[];
    __half* a_s  = (__half*)smem;
    float*  yq_s = (float*)(smem + FIN_YQ);
    float*  yk_s = (float*)(smem + FIN_YK);
    __half* wh_s = (__half*)(smem + FIN_WH);
    __half* wl_s = (__half*)(smem + FIN_WL);
    uint32_t smb = (uint32_t)__cvta_generic_to_shared(smem);

    int b  = blockIdx.z;
    int qt = blockIdx.y * 32;
    int kt = blockIdx.x * 32;
    int tid = threadIdx.x;

    // stage Wout^T split hi/lo, stride-40-half rows (rows = f)
    for (int i = tid; i < 32 * 128; i += 512) {
        int h = i >> 7, f = i & 127;
        float v = Wout[h * F_ + f];
        __half hi = __float2half(v);
        wh_s[f * 40 + h] = hi;
        wl_s[f * 40 + h] = __float2half(v - __half2float(hi));
    }

    // stage yq (+bout) / yk, float4 vectorized
    for (int i = tid; i < 1024; i += 512) {
        int q = i >> 5, f = (i & 31) * 4;
        size_t rq = ((size_t)(b * P_ + qt + q)) * F_ + f;
        size_t rk = ((size_t)(b * P_ + kt + q)) * F_ + f;
        float4 vq = *(const float4*)(bout + f);
        float4 vk = make_float4(0.f, 0.f, 0.f, 0.f);
#pragma unroll
        for (int s = 0; s < 4; s++) {
            float4 a = *(const float4*)(ypart + (size_t)s * M128 + rq);
            float4 c = *(const float4*)(ypart + (size_t)(4 + s) * M128 + rk);
            vq.x += a.x; vq.y += a.y; vq.z += a.z; vq.w += a.w;
            vk.x += c.x; vk.y += c.y; vk.z += c.z; vk.w += c.w;
        }
        *(float4*)(yq_s + q * 128 + f) = vq;
        *(float4*)(yk_s + q * 128 + f) = vk;
    }

    // gather phase 1: a = QK + Qp (h spread across lanes for bank spread)
    for (int i = tid; i < 4096; i += 512) {
        int h  = (i & 15) | ((i >> 7) & 16);
        int k0 = ((i >> 4) & 3) * 8;
        int q  = (i >> 6) & 31;
        int gq = qt + q;
        size_t zb = (size_t)(b * 32 + h);
        uint4 vqk = *(const uint4*)(QK + (zb * P_ + gq) * P_ + kt + k0);
        uint4 vqp = *(const uint4*)(Qp + (zb * P_ + gq) * P2S + (P_ + kt - qt + k0));
        const __half2* hqk = (const __half2*)&vqk;
        const __half2* hqp = (const __half2*)&vqp;
        int m = q * 32 + k0;
#pragma unroll
        for (int j = 0; j < 4; j++) {
            __half2 s = __hadd2(hqk[j], hqp[j]);
            a_s[(m + 2 * j)     * 40 + h] = __low2half(s);
            a_s[(m + 2 * j + 1) * 40 + h] = __high2half(s);
        }
    }
    __syncthreads();

    // gather phase 2: a += Kp (same h-spread lane mapping)
    for (int i = tid; i < 4096; i += 512) {
        int h  = (i & 15) | ((i >> 7) & 16);
        int q0 = ((i >> 4) & 3) * 8;
        int k  = (i >> 6) & 31;
        int gk = kt + k;
        size_t zb = (size_t)(b * 32 + h);
        uint4 vkp = *(const uint4*)(Kp + (zb * P_ + gk) * P2S + (P_ + qt - kt + q0));
        const __half* hk = (const __half*)&vkp;
#pragma unroll
        for (int j = 0; j < 8; j++) {
            int ix = ((q0 + j) * 32 + k) * 40 + h;
            a_s[ix] = __hadd(a_s[ix], hk[j]);
        }
    }
    __syncthreads();

    // HMMA: out[m,f] = a[m,h] @ WoutT[f,h], M=1024 N=128 K=32; 16 warps x 64 rows
    int warp = tid >> 5, lane = tid & 31;
    int g = lane >> 2, tig = lane & 3;
    int lr = lane & 15, lh = lane >> 4;
    int warpM = warp * 64;

    uint32_t af[4][2][4];
#pragma unroll
    for (int mf = 0; mf < 4; mf++)
#pragma unroll
        for (int ks = 0; ks < 2; ks++) {
            uint32_t aa = smb + ((warpM + mf * 16 + lr) * 20 + lh * 4 + ks * 8) * 4;
            LDSM4(af[mf][ks][0], af[mf][ks][1], af[mf][ks][2], af[mf][ks][3], aa);
        }

#pragma unroll
    for (int np = 0; np < 4; np++) {      // 4 passes over f (32 cols each)
        float acc[4][4][4];
#pragma unroll
        for (int i = 0; i < 4; i++)
#pragma unroll
            for (int j = 0; j < 4; j++)
#pragma unroll
                for (int l = 0; l < 4; l++) acc[i][j][l] = 0.f;

#pragma unroll
        for (int ks = 0; ks < 2; ks++) {
            uint32_t bh[4][2], bl[4][2];
#pragma unroll
            for (int tp = 0; tp < 2; tp++) {
                uint32_t ba = smb + FIN_WH +
                    ((np * 32 + tp * 16 + lr) * 20 + lh * 4 + ks * 8) * 4;
                LDSM4(bh[2*tp][0], bh[2*tp+1][0], bh[2*tp][1], bh[2*tp+1][1], ba);
                LDSM4(bl[2*tp][0], bl[2*tp+1][0], bl[2*tp][1], bl[2*tp+1][1],
                      ba + 10240u);
            }
#pragma unroll
            for (int mf = 0; mf < 4; mf++)
#pragma unroll
                for (int nf = 0; nf < 4; nf++)
                    MMA_FP16(acc[mf][nf], af[mf][ks], bh[nf]);
#pragma unroll
            for (int mf = 0; mf < 4; mf++)
#pragma unroll
                for (int nf = 0; nf < 4; nf++)
                    MMA_FP16(acc[mf][nf], af[mf][ks], bl[nf]);
        }

        // store pass: add yq+bout and yk, write fp32 out
#pragma unroll
        for (int mf = 0; mf < 4; mf++)
#pragma unroll
            for (int nf = 0; nf < 4; nf++) {
                int f = np * 32 + nf * 8 + tig * 2;
#pragma unroll
                for (int half = 0; half < 2; half++) {
                    int r = warpM + mf * 16 + g + half * 8;
                    int q = r >> 5, k = r & 31;
                    float b0 = yq_s[q * 128 + f]     + yk_s[k * 128 + f];
                    float b1 = yq_s[q * 128 + f + 1] + yk_s[k * 128 + f + 1];
                    float* orow = out +
                        (((size_t)(b * P_) + qt + q) * P_ + kt + k) * F_ + f;
                    *(float2*)orow = make_float2(acc[mf][nf][half * 2] + b0,
                                                 acc[mf][nf][half * 2 + 1] + b1);
                }
            }
    }
}

// ---------------- launch ------------------------------------------------------
extern "C" void kernel_launch(void* const* d_in, const int* in_sizes, int n_in,
                              void* d_out, int out_size)
{
    const float* x        = (const float*)d_in[0];
    const float* norm_w   = (const float*)d_in[1];
    const float* Wq       = (const float*)d_in[2];
    const float* Wk       = (const float*)d_in[3];
    const float* Wpos     = (const float*)d_in[4];
    const float* bpos     = (const float*)d_in[5];
    const float* q_r_bias = (const float*)d_in[6];
    const float* k_r_bias = (const float*)d_in[7];
    const float* Wyq      = (const float*)d_in[8];
    const float* Wyk      = (const float*)d_in[9];
    const float* Wout     = (const float*)d_in[10];
    const float* bout     = (const float*)d_in[11];
    float* out = (float*)d_out;

    fp16 *p_xnh, *p_xgh;
    fp16 *p_wqth, *p_wqtl, *p_wkth, *p_wktl, *p_wyqh, *p_wyql, *p_wykh, *p_wykl;
    fp16 *p_posh, *p_posl, *p_qh, *p_kh, *p_kl, *p_QK, *p_Qp, *p_Kp;
    float *p_bias, *p_ypart;
    cudaGetSymbolAddress((void**)&p_xnh,  g_xnh);
    cudaGetSymbolAddress((void**)&p_xgh,  g_xgh);
    cudaGetSymbolAddress((void**)&p_wqth, g_wqth);
    cudaGetSymbolAddress((void**)&p_wqtl, g_wqtl);
    cudaGetSymbolAddress((void**)&p_wkth, g_wkth);
    cudaGetSymbolAddress((void**)&p_wktl, g_wktl);
    cudaGetSymbolAddress((void**)&p_wyqh, g_wyqh);
    cudaGetSymbolAddress((void**)&p_wyql, g_wyql);
    cudaGetSymbolAddress((void**)&p_wykh, g_wykh);
    cudaGetSymbolAddress((void**)&p_wykl, g_wykl);
    cudaGetSymbolAddress((void**)&p_posh, g_posh);
    cudaGetSymbolAddress((void**)&p_posl, g_posl);
    cudaGetSymbolAddress((void**)&p_qh,   g_qh);
    cudaGetSymbolAddress((void**)&p_kh,   g_kh);
    cudaGetSymbolAddress((void**)&p_kl,   g_kl);
    cudaGetSymbolAddress((void**)&p_bias, g_bias);
    cudaGetSymbolAddress((void**)&p_ypart, g_ypart);
    cudaGetSymbolAddress((void**)&p_QK,   g_QK);
    cudaGetSymbolAddress((void**)&p_Qp,   g_Qp);
    cudaGetSymbolAddress((void**)&p_Kp,   g_Kp);

    cudaFuncSetAttribute(proj_gemm, cudaFuncAttributeMaxDynamicSharedMemorySize, GEMM_SMEM);
    cudaFuncSetAttribute(y_gemm,    cudaFuncAttributeMaxDynamicSharedMemorySize, GEMM_SMEM);
    cudaFuncSetAttribute(qk_gemm,   cudaFuncAttributeMaxDynamicSharedMemorySize, GEMM_SMEM);
    cudaFuncSetAttribute(qpkp_gemm, cudaFuncAttributeMaxDynamicSharedMemorySize, GEMM_SMEM);
    cudaFuncSetAttribute(final_kernel, cudaFuncAttributeMaxDynamicSharedMemorySize, SMEM_FINAL);

    wconv_kernel<<<dim3(128, 48), 256>>>(Wq, p_wqth, p_wqtl, C_, HF);  // 0
    wconv_kernel<<<dim3(128, 48), 256>>>(Wk, p_wkth, p_wktl, C_, HF);  // 1
    pool_norm_kernel<<<1024, 256>>>(x, norm_w);                        // 2
    proj_gemm<<<dim3(32, 8), 256, GEMM_SMEM>>>(                        // 3
        p_xnh, p_wqth, p_wqtl, p_qh, (fp16*)0);
    proj_gemm<<<dim3(32, 8), 256, GEMM_SMEM>>>(                        // 4
        p_xnh, p_wkth, p_wktl, p_kh, p_kl);

    pos_kernel<<<1024, 128>>>(Wpos, bpos);
    bias_kernel<<<1024, 256>>>(q_r_bias, k_r_bias);
    wconv_kernel<<<dim3(4, 48), 256>>>(Wyq, p_wyqh, p_wyql, C_, F_);
    wconv_kernel<<<dim3(4, 48), 256>>>(Wyk, p_wykh, p_wykl, C_, F_);
    y_gemm<<<dim3(1, 8, 8), 256, GEMM_SMEM>>>(
        p_xgh, p_wyqh, p_wyql, p_wykh, p_wykl, p_ypart);

    qk_gemm<<<dim3(4, 4, 64), 256, GEMM_SMEM>>>(p_qh, p_kh, p_kl, p_QK);
    qpkp_gemm<<<dim3(20, 1, 128), 256, GEMM_SMEM>>>(
        p_qh, p_kh, p_posh, p_posl, p_Qp, p_Kp, p_bias);

    final_kernel<<<dim3(16, 16, 2), 512, SMEM_FINAL>>>(
        p_QK, p_Qp, p_Kp, p_ypart, Wout, bout, out);
}

// round 16
// speedup vs baseline: 1.2818x; 1.0369x over previous
#include <cuda_runtime.h>
#include <cuda_fp16.h>
#include <math.h>
#include <stdint.h>

typedef __half fp16;

#define B_   2
#define S_   8192
#define C_   1536
#define P_   512
#define H_   32
#define F_   128
#define HF   4096
#define P2   1024
#define P2S  1056     // padded row width for shifted Qp/Kp storage
#define M_   1024     // B_*P_

// ---------------- scratch (device globals) ------------------------------------
__device__ __align__(16) fp16 g_xnh[M_ * C_];
__device__ __align__(16) fp16 g_xgh[M_ * C_];
__device__ __align__(16) fp16 g_wqth[HF * C_], g_wqtl[HF * C_];
__device__ __align__(16) fp16 g_wkth[HF * C_], g_wktl[HF * C_];
__device__ __align__(16) fp16 g_wyqh[F_ * C_], g_wyql[F_ * C_];
__device__ __align__(16) fp16 g_wykh[F_ * C_], g_wykl[F_ * C_];
__device__ __align__(16) fp16 g_posh[P2 * HF], g_posl[P2 * HF];
__device__ __align__(16) fp16 g_qh [M_ * HF];
__device__ __align__(16) fp16 g_kh [M_ * HF], g_kl[M_ * HF];
__device__ float g_bias [2 * H_ * P2];
__device__ float g_ypart[8 * M_ * F_];
__device__ __align__(16) fp16 g_QK [(size_t)B_ * H_ * P_ * P_];
__device__ __align__(16) fp16 g_Qp [(size_t)B_ * H_ * P_ * P2S];  // shifted rows
__device__ __align__(16) fp16 g_Kp [(size_t)B_ * H_ * P_ * P2S];  // shifted rows

// ---------------- helpers ------------------------------------------------------
__device__ __forceinline__ void hsplit2(float x, float y, uint32_t& hw, uint32_t& lw)
{
    __half hx = __float2half(x);
    __half hy = __float2half(y);
    __half lx = __float2half(x - __half2float(hx));
    __half ly = __float2half(y - __half2float(hy));
    __half2 hp = __halves2half2(hx, hy);
    __half2 lp = __halves2half2(lx, ly);
    hw = *reinterpret_cast<uint32_t*>(&hp);
    lw = *reinterpret_cast<uint32_t*>(&lp);
}

__device__ __forceinline__ void cp16(uint32_t* smem_ptr, const fp16* gptr)
{
    uint32_t s = (uint32_t)__cvta_generic_to_shared(smem_ptr);
    asm volatile("cp.async.cg.shared.global [%0], [%1], 16;\n" :: "r"(s), "l"(gptr));
}

#define MMA_FP16(c, a, b)                                                       \
    asm volatile(                                                               \
        "mma.sync.aligned.m16n8k16.row.col.f32.f16.f16.f32 "                    \
        "{%0,%1,%2,%3}, {%4,%5,%6,%7}, {%8,%9}, {%0,%1,%2,%3};\n"               \
        : "+f"((c)[0]), "+f"((c)[1]), "+f"((c)[2]), "+f"((c)[3])                \
        : "r"((a)[0]), "r"((a)[1]), "r"((a)[2]), "r"((a)[3]),                   \
          "r"((b)[0]), "r"((b)[1]))

#define LDSM4(d0, d1, d2, d3, a)                                                \
    asm volatile(                                                               \
        "ldmatrix.sync.aligned.m8n8.x4.shared.b16 {%0,%1,%2,%3}, [%4];\n"       \
        : "=r"(d0), "=r"(d1), "=r"(d2), "=r"(d3) : "r"(a))

// one k16 sub-step, 4(m)x2(n) warp layout; hi-sweep then lo-sweep
#define FRAG_LDSM(sst, j0)                                                      \
    do {                                                                        \
        uint32_t ah[2][4], bh[8][2], bl[8][2];                                  \
        _Pragma("unroll")                                                       \
        for (int mt = 0; mt < 2; mt++) {                                        \
            uint32_t aa = (sst) + aoff + mt * 1280u + (j0) * 4u;                \
            LDSM4(ah[mt][0], ah[mt][1], ah[mt][2], ah[mt][3], aa);              \
        }                                                                       \
        _Pragma("unroll")                                                       \
        for (int tp = 0; tp < 4; tp++) {                                        \
            uint32_t ba = (sst) + boff + tp * 1280u + (j0) * 4u + 10240u;       \
            LDSM4(bh[2*tp][0], bh[2*tp+1][0], bh[2*tp][1], bh[2*tp+1][1], ba);  \
            LDSM4(bl[2*tp][0], bl[2*tp+1][0], bl[2*tp][1], bl[2*tp+1][1],       \
                  ba + 10240u);                                                 \
        }                                                                       \
        _Pragma("unroll")                                                       \
        for (int mt = 0; mt < 2; mt++)                                          \
            _Pragma("unroll")                                                   \
            for (int nt = 0; nt < 8; nt++)                                      \
                MMA_FP16(acc[mt][nt], ah[mt], bh[nt]);                          \
        _Pragma("unroll")                                                       \
        for (int mt = 0; mt < 2; mt++)                                          \
            _Pragma("unroll")                                                   \
            for (int nt = 0; nt < 8; nt++)                                      \
                MMA_FP16(acc[mt][nt], ah[mt], bl[nt]);                          \
    } while (0)

// stage = [Ah 10240B][Bh 10240B][Bl 10240B] = 30720B; 3 stages
#define LOAD_STAGE(s, kpos, Ah, Bh, Bl, lda, ldb)                               \
    {                                                                           \
        uint32_t* sb = sm + (s) * 7680;                                         \
        _Pragma("unroll")                                                       \
        for (int ci = 0; ci < 2; ci++) {                                        \
            int qq = tid + ci * 256;                                            \
            int rw = qq >> 2, cc = qq & 3;                                      \
            uint32_t so = rw * 20 + cc * 4;                                     \
            size_t ga = (size_t)(rowA0 + rw) * (lda) + (kpos) + cc * 8;         \
            size_t gb = (size_t)(col0 + rw) * (ldb) + (kpos) + cc * 8;          \
            cp16(sb + so,        (Ah) + ga);                                    \
            cp16(sb + 2560 + so, (Bh) + gb);                                    \
            cp16(sb + 5120 + so, (Bl) + gb);                                    \
        }                                                                       \
    }

// 3-stage cp.async pipeline (requires nk >= 2)
#define GEMM_MAIN(Ah, Bh, Bl, lda, ldb, kb, nk)                                 \
    {                                                                           \
        LOAD_STAGE(0, (kb), Ah, Bh, Bl, lda, ldb);                              \
        asm volatile("cp.async.commit_group;\n");                               \
        LOAD_STAGE(1, (kb) + 32, Ah, Bh, Bl, lda, ldb);                         \
        asm volatile("cp.async.commit_group;\n");                               \
        for (int it = 0; it < (nk); it++) {                                     \
            if (it + 2 < (nk)) asm volatile("cp.async.wait_group 1;\n");        \
            else               asm volatile("cp.async.wait_group 0;\n");        \
            __syncthreads();                                                    \
            uint32_t sst = smb + (uint32_t)((it % 3) * 30720);                  \
            FRAG_LDSM(sst, 0);                                                  \
            if (it + 2 < (nk)) {                                                \
                LOAD_STAGE((it + 2) % 3, (kb) + (it + 2) * 32,                  \
                           Ah, Bh, Bl, lda, ldb);                               \
                asm volatile("cp.async.commit_group;\n");                       \
            }                                                                   \
            FRAG_LDSM(sst, 8);                                                  \
        }                                                                       \
    }

// 4(m) x 2(n) warp layout
#define GEMM_PREAMBLE                                                           \
    extern __shared__ uint32_t sm[];                                            \
    uint32_t smb = (uint32_t)__cvta_generic_to_shared(sm);                      \
    int tid = threadIdx.x;                                                      \
    int warp = tid >> 5, lane = tid & 31;                                       \
    int g = lane >> 2, tig = lane & 3;                                          \
    int lr = lane & 15, lh = lane >> 4;                                         \
    int m0 = (warp >> 1) * 32, n0 = (warp & 1) * 64;                            \
    uint32_t aoff = ((m0 + lr) * 20 + lh * 4) * 4;                              \
    uint32_t boff = ((n0 + lr) * 20 + lh * 4) * 4;                              \
    float acc[2][8][4];                                                         \
    _Pragma("unroll")                                                           \
    for (int i = 0; i < 2; i++)                                                 \
        _Pragma("unroll")                                                       \
        for (int j = 0; j < 8; j++)                                             \
            _Pragma("unroll")                                                   \
            for (int l = 0; l < 4; l++) acc[i][j][l] = 0.f;

#define EPI_F32(Cp, ldc, alpha)                                                 \
    _Pragma("unroll")                                                           \
    for (int mt = 0; mt < 2; mt++)                                              \
        _Pragma("unroll")                                                       \
        for (int nt = 0; nt < 8; nt++) {                                        \
            int r = rowA0 + m0 + mt * 16 + g;                                   \
            int cix = col0 + n0 + nt * 8 + tig * 2;                             \
            *(float2*)((Cp) + (size_t)r * (ldc) + cix) =                        \
                make_float2(acc[mt][nt][0] * (alpha), acc[mt][nt][1] * (alpha));\
            *(float2*)((Cp) + (size_t)(r + 8) * (ldc) + cix) =                  \
                make_float2(acc[mt][nt][2] * (alpha), acc[mt][nt][3] * (alpha));\
        }

#define GEMM_SMEM 92160

// ---------------- kernel: pool + RMS norm + GELU (hi fp16 out) ----------------
__global__ __launch_bounds__(256) void pool_norm_kernel(
    const float* __restrict__ x, const float* __restrict__ norm_w)
{
    int bid = blockIdx.x;
    int b = bid >> 9, p = bid & 511;
    int tid = threadIdx.x;

    const float* xrow = x + ((size_t)b * S_ + (size_t)p * 16) * C_;
    float xp[6];
#pragma unroll
    for (int j = 0; j < 6; j++) xp[j] = 0.f;
    for (int r = 0; r < 16; r++) {
        const float* xr = xrow + (size_t)r * C_;
#pragma unroll
        for (int j = 0; j < 6; j++) xp[j] += xr[tid + j * 256];
    }
    float ssq = 0.f;
#pragma unroll
    for (int j = 0; j < 6; j++) { xp[j] *= (1.f / 16.f); ssq += xp[j] * xp[j]; }

    __shared__ float red[256];
    red[tid] = ssq;
    __syncthreads();
    for (int s = 128; s > 0; s >>= 1) {
        if (tid < s) red[tid] += red[tid + s];
        __syncthreads();
    }
    float scale = 1.f / sqrtf(red[0] * (1.f / (float)C_) + 1e-8f);

    size_t base = (size_t)bid * C_;
#pragma unroll
    for (int j = 0; j < 6; j++) {
        int ch = tid + j * 256;
        float v = xp[j] * scale * norm_w[ch];
        float gv = v * 0.5f * (1.f + erff(v * 0.70710678118654752f));
        g_xnh[base + ch] = __float2half(v);
        g_xgh[base + ch] = __float2half(gv);
    }
}

// ---------------- kernel: pos features @ Wpos + bpos (split fp16 out) ---------
__global__ __launch_bounds__(128) void pos_kernel(
    const float* __restrict__ Wpos, const float* __restrict__ bpos)
{
    int d   = blockIdx.x;
    int tid = threadIdx.x;
    __shared__ float feat[32];

    int rel = d - P_;
    if (tid < 16) {
        double geo = exp((double)tid * (log(497.0) / 16.0));
        float center = (float)tid + (float)geo;
        float oh = (center > fabsf((float)rel)) ? 1.f : 0.f;
        float sg = (rel > 0) ? 1.f : ((rel < 0) ? -1.f : 0.f);
        feat[tid]      = oh;
        feat[tid + 16] = oh * sg;
    }
    __syncthreads();

    float f[32];
#pragma unroll
    for (int c = 0; c < 32; c++) f[c] = feat[c];

    for (int n = tid; n < HF; n += 128) {
        float acc = bpos[n];
#pragma unroll
        for (int c = 0; c < 32; c++) acc += f[c] * Wpos[c * HF + n];
        __half h = __float2half(acc);
        g_posh[(size_t)d * HF + n] = h;
        g_posl[(size_t)d * HF + n] = __float2half(acc - __half2float(h));
    }
}

// ---------------- kernel: rel-bias tables Bias[sel][h][d] = 0.25*rb·pos -------
__global__ __launch_bounds__(256) void bias_kernel(
    const float* __restrict__ qrb, const float* __restrict__ krb)
{
    int d = blockIdx.x;
    int lane = threadIdx.x & 31, w = threadIdx.x >> 5;
    for (int h = w; h < H_; h += 8) {
        float sq = 0.f, sk = 0.f;
        size_t pb = (size_t)d * HF + h * F_;
        for (int c = lane; c < F_; c += 32) {
            float pv = __half2float(g_posh[pb + c]) + __half2float(g_posl[pb + c]);
            sq += qrb[h * F_ + c] * pv;
            sk += krb[h * F_ + c] * pv;
        }
#pragma unroll
        for (int o = 16; o; o >>= 1) {
            sq += __shfl_xor_sync(0xffffffffu, sq, o);
            sk += __shfl_xor_sync(0xffffffffu, sk, o);
        }
        if (lane == 0) {
            g_bias[h * P2 + d]           = 0.25f * sq;
            g_bias[H_ * P2 + h * P2 + d] = 0.25f * sk;
        }
    }
}

// ---------------- kernel: paired weight transpose-convert (z selects W) --------
__global__ __launch_bounds__(256) void wconv2_kernel(
    const float* __restrict__ W0, fp16* __restrict__ T0h, fp16* __restrict__ T0l,
    const float* __restrict__ W1, fp16* __restrict__ T1h, fp16* __restrict__ T1l,
    int K, int N)
{
    const float* W = blockIdx.z ? W1 : W0;
    fp16* Th = blockIdx.z ? T1h : T0h;
    fp16* Tl = blockIdx.z ? T1l : T0l;

    __shared__ float t[32][33];
    int nt0 = blockIdx.x * 32, kt0 = blockIdx.y * 32;
    int tx = threadIdx.x & 31, ty = threadIdx.x >> 5;
#pragma unroll
    for (int i = 0; i < 4; i++)
        t[ty + i * 8][tx] = W[(size_t)(kt0 + ty + i * 8) * N + nt0 + tx];
    __syncthreads();
#pragma unroll
    for (int i = 0; i < 4; i++) {
        int n = nt0 + ty + i * 8, k = kt0 + tx;
        float v = t[tx][ty + i * 8];
        __half h = __float2half(v);
        Th[(size_t)n * K + k] = h;
        Tl[(size_t)n * K + k] = __float2half(v - __half2float(h));
    }
}

// ---------------- kernel: merged q+k projection GEMM (z selects) ---------------
__global__ __launch_bounds__(256, 2) void proj_gemm(
    const fp16* __restrict__ Ah,
    const fp16* __restrict__ Bqh, const fp16* __restrict__ Bql,
    const fp16* __restrict__ Bkh, const fp16* __restrict__ Bkl,
    fp16* __restrict__ Oqh, fp16* __restrict__ Okh, fp16* __restrict__ Okl)
{
    GEMM_PREAMBLE
    int sel = blockIdx.z;
    const fp16* Bh = sel ? Bkh : Bqh;
    const fp16* Bl = sel ? Bkl : Bql;
    fp16* Oh = sel ? Okh : Oqh;
    fp16* Ol = sel ? Okl : (fp16*)0;
    int rowA0 = blockIdx.y * 128, col0 = blockIdx.x * 128;
    GEMM_MAIN(Ah, Bh, Bl, C_, C_, 0, C_ / 32);

    uint32_t* oh = (uint32_t*)Oh;
    uint32_t* ol = (uint32_t*)Ol;
#pragma unroll
    for (int mt = 0; mt < 2; mt++)
#pragma unroll
        for (int nt = 0; nt < 8; nt++) {
            int r = rowA0 + m0 + mt * 16 + g;
            int n = col0 + n0 + nt * 8 + tig * 2;
            uint32_t hw, lw;
            size_t ix0 = ((size_t)r * HF + n) >> 1;
            size_t ix1 = ((size_t)(r + 8) * HF + n) >> 1;
            hsplit2(acc[mt][nt][0], acc[mt][nt][1], hw, lw);
            oh[ix0] = hw;
            if (ol) ol[ix0] = lw;
            hsplit2(acc[mt][nt][2], acc[mt][nt][3], hw, lw);
            oh[ix1] = hw;
            if (ol) ol[ix1] = lw;
        }
}

// ---------------- kernel: yq/yk GEMM, split-K x4 -------------------------------
__global__ __launch_bounds__(256, 2) void y_gemm(
    const fp16* __restrict__ Ah,
    const fp16* __restrict__ B0h, const fp16* __restrict__ B0l,
    const fp16* __restrict__ B1h, const fp16* __restrict__ B1l,
    float* __restrict__ ypart)
{
    GEMM_PREAMBLE
    int z = blockIdx.z;
    const fp16* Bh = (z >= 4) ? B1h : B0h;
    const fp16* Bl = (z >= 4) ? B1l : B0l;
    int kb = (z & 3) * 384;
    int rowA0 = blockIdx.y * 128, col0 = 0;
    GEMM_MAIN(Ah, Bh, Bl, C_, C_, kb, 12);
    float* C = ypart + (size_t)z * M_ * F_;
    EPI_F32(C, F_, 1.0f)
}

// ---------------- kernel: QK GEMM (fp16 out) -----------------------------------
__global__ __launch_bounds__(256, 2) void qk_gemm(
    const fp16* __restrict__ Ahb,
    const fp16* __restrict__ Bhb, const fp16* __restrict__ Blb,
    fp16* __restrict__ Cbase)
{
    GEMM_PREAMBLE
    int z = blockIdx.z, b = z >> 5, h = z & 31;
    const fp16* Ah = Ahb + (size_t)b * P_ * HF + h * F_;
    const fp16* Bh = Bhb + (size_t)b * P_ * HF + h * F_;
    const fp16* Bl = Blb + (size_t)b * P_ * HF + h * F_;
    __half2* C = (__half2*)(Cbase + (size_t)z * P_ * P_);
    int rowA0 = blockIdx.y * 128, col0 = blockIdx.x * 128;
    GEMM_MAIN(Ah, Bh, Bl, HF, HF, 0, 4);

#pragma unroll
    for (int mt = 0; mt < 2; mt++)
#pragma unroll
        for (int nt = 0; nt < 8; nt++) {
            int r = rowA0 + m0 + mt * 16 + g;
            int cix = col0 + n0 + nt * 8 + tig * 2;
            C[((size_t)r * P_ + cix) >> 1] =
                __floats2half2_rn(acc[mt][nt][0], acc[mt][nt][1]);
            C[((size_t)(r + 8) * P_ + cix) >> 1] =
                __floats2half2_rn(acc[mt][nt][2], acc[mt][nt][3]);
        }
}

// ---------------- kernel: Qp+Kp merged band GEMM (fp16, SHIFTED rows) ----------
__global__ __launch_bounds__(256, 2) void qpkp_gemm(
    const fp16* __restrict__ qA, const fp16* __restrict__ kA,
    const fp16* __restrict__ Bh, const fp16* __restrict__ Bl,
    fp16* __restrict__ Qp, fp16* __restrict__ Kp,
    const float* __restrict__ biasT)
{
    GEMM_PREAMBLE
    int z = blockIdx.z;
    int sel = z >> 6, zz = z & 63, b = zz >> 5, h = zz & 31;
    int i = blockIdx.x;
    int ty = i / 5, tx = 3 - ty + (i % 5);
    const fp16* Ahp = (sel ? kA : qA) + (size_t)b * P_ * HF + h * F_;
    const fp16* Bhp = Bh + (size_t)h * F_;
    const fp16* Blp = Bl + (size_t)h * F_;
    fp16* C = (sel ? Kp : Qp) + (size_t)zz * P_ * P2S;
    const float* bp = biasT + (size_t)sel * H_ * P2 + (size_t)h * P2;
    int rowA0 = ty * 128, col0 = tx * 128;
    GEMM_MAIN(Ahp, Bhp, Blp, HF, HF, 0, 4);

#pragma unroll
    for (int mt = 0; mt < 2; mt++)
#pragma unroll
        for (int nt = 0; nt < 8; nt++) {
            int cix = col0 + n0 + nt * 8 + tig * 2;
            float2 bb = *(const float2*)(bp + cix);
#pragma unroll
            for (int half = 0; half < 2; half++) {
                int r = rowA0 + m0 + mt * 16 + g + half * 8;
                int sh = r & 31;
                size_t base = (size_t)r * P2S + cix + sh;
                C[base]     = __float2half(acc[mt][nt][half * 2]     * 0.25f + bb.x);
                C[base + 1] = __float2half(acc[mt][nt][half * 2 + 1] * 0.25f + bb.y);
            }
        }
}

// ---------------- kernel: fused gather + HMMA a@Wout (512 threads) -------------
#define FIN_A   0
#define FIN_YQ  81920
#define FIN_YK  (FIN_YQ + 16384)
#define FIN_WH  (FIN_YK + 16384)
#define FIN_WL  (FIN_WH + 10240)
#define SMEM_FINAL (FIN_WL + 10240)
#define M128 (M_ * F_)

__global__ __launch_bounds__(512) void final_kernel(
    const fp16* __restrict__ QK, const fp16* __restrict__ Qp,
    const fp16* __restrict__ Kp, const float* __restrict__ ypart,
    const float* __restrict__ Wout, const float* __restrict__ bout,
    float* __restrict__ out)
{
    extern __shared__ char smem[];
    __half* a_s  = (__half*)smem;
    float*  yq_s = (float*)(smem + FIN_YQ);
    float*  yk_s = (float*)(smem + FIN_YK);
    __half* wh_s = (__half*)(smem + FIN_WH);
    __half* wl_s = (__half*)(smem + FIN_WL);
    uint32_t smb = (uint32_t)__cvta_generic_to_shared(smem);

    int b  = blockIdx.z;
    int qt = blockIdx.y * 32;
    int kt = blockIdx.x * 32;
    int tid = threadIdx.x;

    // hoisted phase-2 Kp loads (independent of phase 1) -> high MLP
    uint4 kpre[8];
#pragma unroll
    for (int u = 0; u < 8; u++) {
        int i = tid + u * 512;
        int h  = (i & 15) | ((i >> 7) & 16);
        int q0 = ((i >> 4) & 3) * 8;
        int k  = (i >> 6) & 31;
        size_t zb = (size_t)(b * 32 + h);
        kpre[u] = *(const uint4*)(Kp + (zb * P_ + kt + k) * P2S + (P_ + qt - kt + q0));
    }

    // stage Wout^T split hi/lo, stride-40-half rows (rows = f)
    for (int i = tid; i < 32 * 128; i += 512) {
        int h = i >> 7, f = i & 127;
        float v = Wout[h * F_ + f];
        __half hi = __float2half(v);
        wh_s[f * 40 + h] = hi;
        wl_s[f * 40 + h] = __float2half(v - __half2float(hi));
    }

    // stage yq (+bout) / yk, float4 vectorized
#pragma unroll
    for (int u = 0; u < 2; u++) {
        int i = tid + u * 512;
        int q = i >> 5, f = (i & 31) * 4;
        size_t rq = ((size_t)(b * P_ + qt + q)) * F_ + f;
        size_t rk = ((size_t)(b * P_ + kt + q)) * F_ + f;
        float4 vq = *(const float4*)(bout + f);
        float4 vk = make_float4(0.f, 0.f, 0.f, 0.f);
#pragma unroll
        for (int s = 0; s < 4; s++) {
            float4 a = *(const float4*)(ypart + (size_t)s * M128 + rq);
            float4 c = *(const float4*)(ypart + (size_t)(4 + s) * M128 + rk);
            vq.x += a.x; vq.y += a.y; vq.z += a.z; vq.w += a.w;
            vk.x += c.x; vk.y += c.y; vk.z += c.z; vk.w += c.w;
        }
        *(float4*)(yq_s + q * 128 + f) = vq;
        *(float4*)(yk_s + q * 128 + f) = vk;
    }

    // gather phase 1: a = QK + Qp (h spread across lanes, fully unrolled)
#pragma unroll
    for (int u = 0; u < 8; u++) {
        int i = tid + u * 512;
        int h  = (i & 15) | ((i >> 7) & 16);
        int k0 = ((i >> 4) & 3) * 8;
        int q  = (i >> 6) & 31;
        int gq = qt + q;
        size_t zb = (size_t)(b * 32 + h);
        uint4 vqk = *(const uint4*)(QK + (zb * P_ + gq) * P_ + kt + k0);
        uint4 vqp = *(const uint4*)(Qp + (zb * P_ + gq) * P2S + (P_ + kt - qt + k0));
        const __half2* hqk = (const __half2*)&vqk;
        const __half2* hqp = (const __half2*)&vqp;
        int m = q * 32 + k0;
#pragma unroll
        for (int j = 0; j < 4; j++) {
            __half2 s = __hadd2(hqk[j], hqp[j]);
            a_s[(m + 2 * j)     * 40 + h] = __low2half(s);
            a_s[(m + 2 * j + 1) * 40 + h] = __high2half(s);
        }
    }
    __syncthreads();

    // gather phase 2: a += Kp using preloaded registers
#pragma unroll
    for (int u = 0; u < 8; u++) {
        int i = tid + u * 512;
        int h  = (i & 15) | ((i >> 7) & 16);
        int q0 = ((i >> 4) & 3) * 8;
        int k  = (i >> 6) & 31;
        const __half* hk = (const __half*)&kpre[u];
#pragma unroll
        for (int j = 0; j < 8; j++) {
            int ix = ((q0 + j) * 32 + k) * 40 + h;
            a_s[ix] = __hadd(a_s[ix], hk[j]);
        }
    }
    __syncthreads();

    // HMMA: out[m,f] = a[m,h] @ WoutT[f,h], 16 warps x 64 rows
    int warp = tid >> 5, lane = tid & 31;
    int g = lane >> 2, tig = lane & 3;
    int lr = lane & 15, lh = lane >> 4;
    int warpM = warp * 64;

    uint32_t af[4][2][4];
#pragma unroll
    for (int mf = 0; mf < 4; mf++)
#pragma unroll
        for (int ks = 0; ks < 2; ks++) {
            uint32_t aa = smb + ((warpM + mf * 16 + lr) * 20 + lh * 4 + ks * 8) * 4;
            LDSM4(af[mf][ks][0], af[mf][ks][1], af[mf][ks][2], af[mf][ks][3], aa);
        }

#pragma unroll
    for (int np = 0; np < 4; np++) {      // 4 passes over f (32 cols each)
        float acc[4][4][4];
#pragma unroll
        for (int i = 0; i < 4; i++)
#pragma unroll
            for (int j = 0; j < 4; j++)
#pragma unroll
                for (int l = 0; l < 4; l++) acc[i][j][l] = 0.f;

#pragma unroll
        for (int ks = 0; ks < 2; ks++) {
            uint32_t bh[4][2], bl[4][2];
#pragma unroll
            for (int tp = 0; tp < 2; tp++) {
                uint32_t ba = smb + FIN_WH +
                    ((np * 32 + tp * 16 + lr) * 20 + lh * 4 + ks * 8) * 4;
                LDSM4(bh[2*tp][0], bh[2*tp+1][0], bh[2*tp][1], bh[2*tp+1][1], ba);
                LDSM4(bl[2*tp][0], bl[2*tp+1][0], bl[2*tp][1], bl[2*tp+1][1],
                      ba + 10240u);
            }
#pragma unroll
            for (int mf = 0; mf < 4; mf++)
#pragma unroll
                for (int nf = 0; nf < 4; nf++)
                    MMA_FP16(acc[mf][nf], af[mf][ks], bh[nf]);
#pragma unroll
            for (int mf = 0; mf < 4; mf++)
#pragma unroll
                for (int nf = 0; nf < 4; nf++)
                    MMA_FP16(acc[mf][nf], af[mf][ks], bl[nf]);
        }

        // store pass: add yq+bout and yk, write fp32 out
#pragma unroll
        for (int mf = 0; mf < 4; mf++)
#pragma unroll
            for (int nf = 0; nf < 4; nf++) {
                int f = np * 32 + nf * 8 + tig * 2;
#pragma unroll
                for (int half = 0; half < 2; half++) {
                    int r = warpM + mf * 16 + g + half * 8;
                    int q = r >> 5, k = r & 31;
                    float b0 = yq_s[q * 128 + f]     + yk_s[k * 128 + f];
                    float b1 = yq_s[q * 128 + f + 1] + yk_s[k * 128 + f + 1];
                    float* orow = out +
                        (((size_t)(b * P_) + qt + q) * P_ + kt + k) * F_ + f;
                    *(float2*)orow = make_float2(acc[mf][nf][half * 2] + b0,
                                                 acc[mf][nf][half * 2 + 1] + b1);
                }
            }
    }
}

// ---------------- launch ------------------------------------------------------
extern "C" void kernel_launch(void* const* d_in, const int* in_sizes, int n_in,
                              void* d_out, int out_size)
{
    const float* x        = (const float*)d_in[0];
    const float* norm_w   = (const float*)d_in[1];
    const float* Wq       = (const float*)d_in[2];
    const float* Wk       = (const float*)d_in[3];
    const float* Wpos     = (const float*)d_in[4];
    const float* bpos     = (const float*)d_in[5];
    const float* q_r_bias = (const float*)d_in[6];
    const float* k_r_bias = (const float*)d_in[7];
    const float* Wyq      = (const float*)d_in[8];
    const float* Wyk      = (const float*)d_in[9];
    const float* Wout     = (const float*)d_in[10];
    const float* bout     = (const float*)d_in[11];
    float* out = (float*)d_out;

    fp16 *p_xnh, *p_xgh;
    fp16 *p_wqth, *p_wqtl, *p_wkth, *p_wktl, *p_wyqh, *p_wyql, *p_wykh, *p_wykl;
    fp16 *p_posh, *p_posl, *p_qh, *p_kh, *p_kl, *p_QK, *p_Qp, *p_Kp;
    float *p_bias, *p_ypart;
    cudaGetSymbolAddress((void**)&p_xnh,  g_xnh);
    cudaGetSymbolAddress((void**)&p_xgh,  g_xgh);
    cudaGetSymbolAddress((void**)&p_wqth, g_wqth);
    cudaGetSymbolAddress((void**)&p_wqtl, g_wqtl);
    cudaGetSymbolAddress((void**)&p_wkth, g_wkth);
    cudaGetSymbolAddress((void**)&p_wktl, g_wktl);
    cudaGetSymbolAddress((void**)&p_wyqh, g_wyqh);
    cudaGetSymbolAddress((void**)&p_wyql, g_wyql);
    cudaGetSymbolAddress((void**)&p_wykh, g_wykh);
    cudaGetSymbolAddress((void**)&p_wykl, g_wykl);
    cudaGetSymbolAddress((void**)&p_posh, g_posh);
    cudaGetSymbolAddress((void**)&p_posl, g_posl);
    cudaGetSymbolAddress((void**)&p_qh,   g_qh);
    cudaGetSymbolAddress((void**)&p_kh,   g_kh);
    cudaGetSymbolAddress((void**)&p_kl,   g_kl);
    cudaGetSymbolAddress((void**)&p_bias, g_bias);
    cudaGetSymbolAddress((void**)&p_ypart, g_ypart);
    cudaGetSymbolAddress((void**)&p_QK,   g_QK);
    cudaGetSymbolAddress((void**)&p_Qp,   g_Qp);
    cudaGetSymbolAddress((void**)&p_Kp,   g_Kp);

    cudaFuncSetAttribute(proj_gemm, cudaFuncAttributeMaxDynamicSharedMemorySize, GEMM_SMEM);
    cudaFuncSetAttribute(y_gemm,    cudaFuncAttributeMaxDynamicSharedMemorySize, GEMM_SMEM);
    cudaFuncSetAttribute(qk_gemm,   cudaFuncAttributeMaxDynamicSharedMemorySize, GEMM_SMEM);
    cudaFuncSetAttribute(qpkp_gemm, cudaFuncAttributeMaxDynamicSharedMemorySize, GEMM_SMEM);
    cudaFuncSetAttribute(final_kernel, cudaFuncAttributeMaxDynamicSharedMemorySize, SMEM_FINAL);

    wconv2_kernel<<<dim3(128, 48, 2), 256>>>(
        Wq, p_wqth, p_wqtl, Wk, p_wkth, p_wktl, C_, HF);
    pool_norm_kernel<<<1024, 256>>>(x, norm_w);
    proj_gemm<<<dim3(32, 8, 2), 256, GEMM_SMEM>>>(
        p_xnh, p_wqth, p_wqtl, p_wkth, p_wktl, p_qh, p_kh, p_kl);

    pos_kernel<<<1024, 128>>>(Wpos, bpos);
    bias_kernel<<<1024, 256>>>(q_r_bias, k_r_bias);
    wconv2_kernel<<<dim3(4, 48, 2), 256>>>(
        Wyq, p_wyqh, p_wyql, Wyk, p_wykh, p_wykl, C_, F_);
    y_gemm<<<dim3(1, 8, 8), 256, GEMM_SMEM>>>(
        p_xgh, p_wyqh, p_wyql, p_wykh, p_wykl, p_ypart);

    qk_gemm<<<dim3(4, 4, 64), 256, GEMM_SMEM>>>(p_qh, p_kh, p_kl, p_QK);
    qpkp_gemm<<<dim3(20, 1, 128), 256, GEMM_SMEM>>>(
        p_qh, p_kh, p_posh, p_posl, p_Qp, p_Kp, p_bias);

    final_kernel<<<dim3(16, 16, 2), 512, SMEM_FINAL>>>(
        p_QK, p_Qp, p_Kp, p_ypart, Wout, bout, out);
}

// round 17
// speedup vs baseline: 1.4190x; 1.1070x over previous
#include <cuda_runtime.h>
#include <cuda_fp16.h>
#include <math.h>
#include <stdint.h>

typedef __half fp16;

#define B_   2
#define S_   8192
#define C_   1536
#define P_   512
#define H_   32
#define F_   128
#define HF   4096
#define P2   1024
#define P2S  1056     // padded row width for shifted Qp/Kp storage
#define M_   1024     // B_*P_

// ---------------- scratch (device globals) ------------------------------------
__device__ __align__(16) fp16 g_xnh[M_ * C_];
__device__ __align__(16) fp16 g_xgh[M_ * C_];
__device__ __align__(16) fp16 g_wqth[HF * C_], g_wqtl[HF * C_];
__device__ __align__(16) fp16 g_wkth[HF * C_], g_wktl[HF * C_];
__device__ __align__(16) fp16 g_wyqh[F_ * C_], g_wyql[F_ * C_];
__device__ __align__(16) fp16 g_wykh[F_ * C_], g_wykl[F_ * C_];
__device__ __align__(16) fp16 g_posh[P2 * HF], g_posl[P2 * HF];
__device__ __align__(16) fp16 g_qh [M_ * HF];
__device__ __align__(16) fp16 g_kh [M_ * HF], g_kl[M_ * HF];
__device__ float g_bias [2 * H_ * P2];
__device__ float g_ypart[8 * M_ * F_];
__device__ __align__(16) fp16 g_QK [(size_t)B_ * H_ * P_ * P_];
__device__ __align__(16) fp16 g_Qp [(size_t)B_ * H_ * P_ * P2S];  // shifted rows
__device__ __align__(16) fp16 g_Kp [(size_t)B_ * H_ * P_ * P2S];  // shifted rows

// ---------------- helpers ------------------------------------------------------
__device__ __forceinline__ void hsplit2(float x, float y, uint32_t& hw, uint32_t& lw)
{
    __half hx = __float2half(x);
    __half hy = __float2half(y);
    __half lx = __float2half(x - __half2float(hx));
    __half ly = __float2half(y - __half2float(hy));
    __half2 hp = __halves2half2(hx, hy);
    __half2 lp = __halves2half2(lx, ly);
    hw = *reinterpret_cast<uint32_t*>(&hp);
    lw = *reinterpret_cast<uint32_t*>(&lp);
}

__device__ __forceinline__ void cp16(uint32_t* smem_ptr, const fp16* gptr)
{
    uint32_t s = (uint32_t)__cvta_generic_to_shared(smem_ptr);
    asm volatile("cp.async.cg.shared.global [%0], [%1], 16;\n" :: "r"(s), "l"(gptr));
}

#define MMA_FP16(c, a, b)                                                       \
    asm volatile(                                                               \
        "mma.sync.aligned.m16n8k16.row.col.f32.f16.f16.f32 "                    \
        "{%0,%1,%2,%3}, {%4,%5,%6,%7}, {%8,%9}, {%0,%1,%2,%3};\n"               \
        : "+f"((c)[0]), "+f"((c)[1]), "+f"((c)[2]), "+f"((c)[3])                \
        : "r"((a)[0]), "r"((a)[1]), "r"((a)[2]), "r"((a)[3]),                   \
          "r"((b)[0]), "r"((b)[1]))

#define LDSM4(d0, d1, d2, d3, a)                                                \
    asm volatile(                                                               \
        "ldmatrix.sync.aligned.m8n8.x4.shared.b16 {%0,%1,%2,%3}, [%4];\n"       \
        : "=r"(d0), "=r"(d1), "=r"(d2), "=r"(d3) : "r"(a))

// one k16 sub-step, 4(m)x2(n) warp layout; hi-sweep then lo-sweep
#define FRAG_LDSM(sst, j0)                                                      \
    do {                                                                        \
        uint32_t ah[2][4], bh[8][2], bl[8][2];                                  \
        _Pragma("unroll")                                                       \
        for (int mt = 0; mt < 2; mt++) {                                        \
            uint32_t aa = (sst) + aoff + mt * 1280u + (j0) * 4u;                \
            LDSM4(ah[mt][0], ah[mt][1], ah[mt][2], ah[mt][3], aa);              \
        }                                                                       \
        _Pragma("unroll")                                                       \
        for (int tp = 0; tp < 4; tp++) {                                        \
            uint32_t ba = (sst) + boff + tp * 1280u + (j0) * 4u + 10240u;       \
            LDSM4(bh[2*tp][0], bh[2*tp+1][0], bh[2*tp][1], bh[2*tp+1][1], ba);  \
            LDSM4(bl[2*tp][0], bl[2*tp+1][0], bl[2*tp][1], bl[2*tp+1][1],       \
                  ba + 10240u);                                                 \
        }                                                                       \
        _Pragma("unroll")                                                       \
        for (int mt = 0; mt < 2; mt++)                                          \
            _Pragma("unroll")                                                   \
            for (int nt = 0; nt < 8; nt++)                                      \
                MMA_FP16(acc[mt][nt], ah[mt], bh[nt]);                          \
        _Pragma("unroll")                                                       \
        for (int mt = 0; mt < 2; mt++)                                          \
            _Pragma("unroll")                                                   \
            for (int nt = 0; nt < 8; nt++)                                      \
                MMA_FP16(acc[mt][nt], ah[mt], bl[nt]);                          \
    } while (0)

// stage = [Ah 10240B][Bh 10240B][Bl 10240B] = 30720B; 3 stages
#define LOAD_STAGE(s, kpos, Ah, Bh, Bl, lda, ldb)                               \
    {                                                                           \
        uint32_t* sb = sm + (s) * 7680;                                         \
        _Pragma("unroll")                                                       \
        for (int ci = 0; ci < 2; ci++) {                                        \
            int qq = tid + ci * 256;                                            \
            int rw = qq >> 2, cc = qq & 3;                                      \
            uint32_t so = rw * 20 + cc * 4;                                     \
            size_t ga = (size_t)(rowA0 + rw) * (lda) + (kpos) + cc * 8;         \
            size_t gb = (size_t)(col0 + rw) * (ldb) + (kpos) + cc * 8;          \
            cp16(sb + so,        (Ah) + ga);                                    \
            cp16(sb + 2560 + so, (Bh) + gb);                                    \
            cp16(sb + 5120 + so, (Bl) + gb);                                    \
        }                                                                       \
    }

// 3-stage cp.async pipeline (requires nk >= 2)
#define GEMM_MAIN(Ah, Bh, Bl, lda, ldb, kb, nk)                                 \
    {                                                                           \
        LOAD_STAGE(0, (kb), Ah, Bh, Bl, lda, ldb);                              \
        asm volatile("cp.async.commit_group;\n");                               \
        LOAD_STAGE(1, (kb) + 32, Ah, Bh, Bl, lda, ldb);                         \
        asm volatile("cp.async.commit_group;\n");                               \
        for (int it = 0; it < (nk); it++) {                                     \
            if (it + 2 < (nk)) asm volatile("cp.async.wait_group 1;\n");        \
            else               asm volatile("cp.async.wait_group 0;\n");        \
            __syncthreads();                                                    \
            uint32_t sst = smb + (uint32_t)((it % 3) * 30720);                  \
            FRAG_LDSM(sst, 0);                                                  \
            if (it + 2 < (nk)) {                                                \
                LOAD_STAGE((it + 2) % 3, (kb) + (it + 2) * 32,                  \
                           Ah, Bh, Bl, lda, ldb);                               \
                asm volatile("cp.async.commit_group;\n");                       \
            }                                                                   \
            FRAG_LDSM(sst, 8);                                                  \
        }                                                                       \
    }

// 4(m) x 2(n) warp layout
#define GEMM_PREAMBLE                                                           \
    extern __shared__ uint32_t sm[];                                            \
    uint32_t smb = (uint32_t)__cvta_generic_to_shared(sm);                      \
    int tid = threadIdx.x;                                                      \
    int warp = tid >> 5, lane = tid & 31;                                       \
    int g = lane >> 2, tig = lane & 3;                                          \
    int lr = lane & 15, lh = lane >> 4;                                         \
    int m0 = (warp >> 1) * 32, n0 = (warp & 1) * 64;                            \
    uint32_t aoff = ((m0 + lr) * 20 + lh * 4) * 4;                              \
    uint32_t boff = ((n0 + lr) * 20 + lh * 4) * 4;                              \
    float acc[2][8][4];                                                         \
    _Pragma("unroll")                                                           \
    for (int i = 0; i < 2; i++)                                                 \
        _Pragma("unroll")                                                       \
        for (int j = 0; j < 8; j++)                                             \
            _Pragma("unroll")                                                   \
            for (int l = 0; l < 4; l++) acc[i][j][l] = 0.f;

#define EPI_F32(Cp, ldc, alpha)                                                 \
    _Pragma("unroll")                                                           \
    for (int mt = 0; mt < 2; mt++)                                              \
        _Pragma("unroll")                                                       \
        for (int nt = 0; nt < 8; nt++) {                                        \
            int r = rowA0 + m0 + mt * 16 + g;                                   \
            int cix = col0 + n0 + nt * 8 + tig * 2;                             \
            *(float2*)((Cp) + (size_t)r * (ldc) + cix) =                        \
                make_float2(acc[mt][nt][0] * (alpha), acc[mt][nt][1] * (alpha));\
            *(float2*)((Cp) + (size_t)(r + 8) * (ldc) + cix) =                  \
                make_float2(acc[mt][nt][2] * (alpha), acc[mt][nt][3] * (alpha));\
        }

#define GEMM_SMEM 92160

// ---------------- kernel: pool + RMS norm + GELU (hi fp16 out) ----------------
__global__ __launch_bounds__(256) void pool_norm_kernel(
    const float* __restrict__ x, const float* __restrict__ norm_w)
{
    int bid = blockIdx.x;
    int b = bid >> 9, p = bid & 511;
    int tid = threadIdx.x;

    const float* xrow = x + ((size_t)b * S_ + (size_t)p * 16) * C_;
    float xp[6];
#pragma unroll
    for (int j = 0; j < 6; j++) xp[j] = 0.f;
    for (int r = 0; r < 16; r++) {
        const float* xr = xrow + (size_t)r * C_;
#pragma unroll
        for (int j = 0; j < 6; j++) xp[j] += xr[tid + j * 256];
    }
    float ssq = 0.f;
#pragma unroll
    for (int j = 0; j < 6; j++) { xp[j] *= (1.f / 16.f); ssq += xp[j] * xp[j]; }

    __shared__ float red[256];
    red[tid] = ssq;
    __syncthreads();
    for (int s = 128; s > 0; s >>= 1) {
        if (tid < s) red[tid] += red[tid + s];
        __syncthreads();
    }
    float scale = 1.f / sqrtf(red[0] * (1.f / (float)C_) + 1e-8f);

    size_t base = (size_t)bid * C_;
#pragma unroll
    for (int j = 0; j < 6; j++) {
        int ch = tid + j * 256;
        float v = xp[j] * scale * norm_w[ch];
        float gv = v * 0.5f * (1.f + erff(v * 0.70710678118654752f));
        g_xnh[base + ch] = __float2half(v);
        g_xgh[base + ch] = __float2half(gv);
    }
}

// ---------------- kernel: pos features @ Wpos + bpos (suffix-sum form) --------
// pos_enc[d][n] = bpos[n] + S1[t(d)][n] + sign(d)*S2[t(d)][n] where t is the
// count of center widths <= |rel|. Wpos read once per block; writes coalesced.
__global__ __launch_bounds__(128) void pos_kernel(
    const float* __restrict__ Wpos, const float* __restrict__ bpos)
{
    __shared__ float S1s[17][128], S2s[17][128];
    __shared__ float cent[16];
    __shared__ unsigned char tt[256];
    __shared__ signed char ss[256];

    int tid = threadIdx.x;
    int n   = blockIdx.x * 128 + tid;
    int d0  = blockIdx.y * 256;

    if (tid < 16) {
        double geo = exp((double)tid * (log(497.0) / 16.0));
        cent[tid] = (float)tid + (float)geo;
    }
    __syncthreads();

    // suffix sums of this thread's Wpos column
    float s1 = 0.f, s2 = 0.f;
    S1s[16][tid] = 0.f;
    S2s[16][tid] = 0.f;
#pragma unroll
    for (int c = 15; c >= 0; c--) {
        s1 += Wpos[(size_t)c * HF + n];
        s2 += Wpos[(size_t)(16 + c) * HF + n];
        S1s[c][tid] = s1;
        S2s[c][tid] = s2;
    }

    // t / sign table for this block's d-range
    for (int i = tid; i < 256; i += 128) {
        int rel = d0 + i - P_;
        float ar = fabsf((float)rel);
        int t = 0;
#pragma unroll
        for (int c = 0; c < 16; c++) t += (cent[c] <= ar) ? 1 : 0;
        tt[i] = (unsigned char)t;
        ss[i] = (rel > 0) ? 1 : ((rel < 0) ? -1 : 0);
    }
    __syncthreads();

    float bp = bpos[n];
    for (int i = 0; i < 256; i++) {
        int t = tt[i];
        float sg = (float)ss[i];
        float v = bp + S1s[t][tid] + sg * S2s[t][tid];
        __half h = __float2half(v);
        size_t ix = (size_t)(d0 + i) * HF + n;
        g_posh[ix] = h;
        g_posl[ix] = __float2half(v - __half2float(h));
    }
}

// ---------------- kernel: rel-bias tables Bias[sel][h][d] = 0.25*rb·pos -------
__global__ __launch_bounds__(256) void bias_kernel(
    const float* __restrict__ qrb, const float* __restrict__ krb)
{
    int d = blockIdx.x;
    int lane = threadIdx.x & 31, w = threadIdx.x >> 5;
    for (int h = w; h < H_; h += 8) {
        float sq = 0.f, sk = 0.f;
        size_t pb = (size_t)d * HF + h * F_;
        for (int c = lane; c < F_; c += 32) {
            float pv = __half2float(g_posh[pb + c]) + __half2float(g_posl[pb + c]);
            sq += qrb[h * F_ + c] * pv;
            sk += krb[h * F_ + c] * pv;
        }
#pragma unroll
        for (int o = 16; o; o >>= 1) {
            sq += __shfl_xor_sync(0xffffffffu, sq, o);
            sk += __shfl_xor_sync(0xffffffffu, sk, o);
        }
        if (lane == 0) {
            g_bias[h * P2 + d]           = 0.25f * sq;
            g_bias[H_ * P2 + h * P2 + d] = 0.25f * sk;
        }
    }
}

// ---------------- kernel: paired weight transpose-convert (z selects W) --------
__global__ __launch_bounds__(256) void wconv2_kernel(
    const float* __restrict__ W0, fp16* __restrict__ T0h, fp16* __restrict__ T0l,
    const float* __restrict__ W1, fp16* __restrict__ T1h, fp16* __restrict__ T1l,
    int K, int N)
{
    const float* W = blockIdx.z ? W1 : W0;
    fp16* Th = blockIdx.z ? T1h : T0h;
    fp16* Tl = blockIdx.z ? T1l : T0l;

    __shared__ float t[32][33];
    int nt0 = blockIdx.x * 32, kt0 = blockIdx.y * 32;
    int tx = threadIdx.x & 31, ty = threadIdx.x >> 5;
#pragma unroll
    for (int i = 0; i < 4; i++)
        t[ty + i * 8][tx] = W[(size_t)(kt0 + ty + i * 8) * N + nt0 + tx];
    __syncthreads();
#pragma unroll
    for (int i = 0; i < 4; i++) {
        int n = nt0 + ty + i * 8, k = kt0 + tx;
        float v = t[tx][ty + i * 8];
        __half h = __float2half(v);
        Th[(size_t)n * K + k] = h;
        Tl[(size_t)n * K + k] = __float2half(v - __half2float(h));
    }
}

// ---------------- kernel: merged q+k projection GEMM (z selects) ---------------
__global__ __launch_bounds__(256, 2) void proj_gemm(
    const fp16* __restrict__ Ah,
    const fp16* __restrict__ Bqh, const fp16* __restrict__ Bql,
    const fp16* __restrict__ Bkh, const fp16* __restrict__ Bkl,
    fp16* __restrict__ Oqh, fp16* __restrict__ Okh, fp16* __restrict__ Okl)
{
    GEMM_PREAMBLE
    int sel = blockIdx.z;
    const fp16* Bh = sel ? Bkh : Bqh;
    const fp16* Bl = sel ? Bkl : Bql;
    fp16* Oh = sel ? Okh : Oqh;
    fp16* Ol = sel ? Okl : (fp16*)0;
    int rowA0 = blockIdx.y * 128, col0 = blockIdx.x * 128;
    GEMM_MAIN(Ah, Bh, Bl, C_, C_, 0, C_ / 32);

    uint32_t* oh = (uint32_t*)Oh;
    uint32_t* ol = (uint32_t*)Ol;
#pragma unroll
    for (int mt = 0; mt < 2; mt++)
#pragma unroll
        for (int nt = 0; nt < 8; nt++) {
            int r = rowA0 + m0 + mt * 16 + g;
            int n = col0 + n0 + nt * 8 + tig * 2;
            uint32_t hw, lw;
            size_t ix0 = ((size_t)r * HF + n) >> 1;
            size_t ix1 = ((size_t)(r + 8) * HF + n) >> 1;
            hsplit2(acc[mt][nt][0], acc[mt][nt][1], hw, lw);
            oh[ix0] = hw;
            if (ol) ol[ix0] = lw;
            hsplit2(acc[mt][nt][2], acc[mt][nt][3], hw, lw);
            oh[ix1] = hw;
            if (ol) ol[ix1] = lw;
        }
}

// ---------------- kernel: yq/yk GEMM, split-K x4 -------------------------------
__global__ __launch_bounds__(256, 2) void y_gemm(
    const fp16* __restrict__ Ah,
    const fp16* __restrict__ B0h, const fp16* __restrict__ B0l,
    const fp16* __restrict__ B1h, const fp16* __restrict__ B1l,
    float* __restrict__ ypart)
{
    GEMM_PREAMBLE
    int z = blockIdx.z;
    const fp16* Bh = (z >= 4) ? B1h : B0h;
    const fp16* Bl = (z >= 4) ? B1l : B0l;
    int kb = (z & 3) * 384;
    int rowA0 = blockIdx.y * 128, col0 = 0;
    GEMM_MAIN(Ah, Bh, Bl, C_, C_, kb, 12);
    float* C = ypart + (size_t)z * M_ * F_;
    EPI_F32(C, F_, 1.0f)
}

// ---------------- kernel: QK GEMM (fp16 out) -----------------------------------
__global__ __launch_bounds__(256, 2) void qk_gemm(
    const fp16* __restrict__ Ahb,
    const fp16* __restrict__ Bhb, const fp16* __restrict__ Blb,
    fp16* __restrict__ Cbase)
{
    GEMM_PREAMBLE
    int z = blockIdx.z, b = z >> 5, h = z & 31;
    const fp16* Ah = Ahb + (size_t)b * P_ * HF + h * F_;
    const fp16* Bh = Bhb + (size_t)b * P_ * HF + h * F_;
    const fp16* Bl = Blb + (size_t)b * P_ * HF + h * F_;
    __half2* C = (__half2*)(Cbase + (size_t)z * P_ * P_);
    int rowA0 = blockIdx.y * 128, col0 = blockIdx.x * 128;
    GEMM_MAIN(Ah, Bh, Bl, HF, HF, 0, 4);

#pragma unroll
    for (int mt = 0; mt < 2; mt++)
#pragma unroll
        for (int nt = 0; nt < 8; nt++) {
            int r = rowA0 + m0 + mt * 16 + g;
            int cix = col0 + n0 + nt * 8 + tig * 2;
            C[((size_t)r * P_ + cix) >> 1] =
                __floats2half2_rn(acc[mt][nt][0], acc[mt][nt][1]);
            C[((size_t)(r + 8) * P_ + cix) >> 1] =
                __floats2half2_rn(acc[mt][nt][2], acc[mt][nt][3]);
        }
}

// ---------------- kernel: Qp+Kp merged band GEMM (fp16, SHIFTED rows) ----------
__global__ __launch_bounds__(256, 2) void qpkp_gemm(
    const fp16* __restrict__ qA, const fp16* __restrict__ kA,
    const fp16* __restrict__ Bh, const fp16* __restrict__ Bl,
    fp16* __restrict__ Qp, fp16* __restrict__ Kp,
    const float* __restrict__ biasT)
{
    GEMM_PREAMBLE
    int z = blockIdx.z;
    int sel = z >> 6, zz = z & 63, b = zz >> 5, h = zz & 31;
    int i = blockIdx.x;
    int ty = i / 5, tx = 3 - ty + (i % 5);
    const fp16* Ahp = (sel ? kA : qA) + (size_t)b * P_ * HF + h * F_;
    const fp16* Bhp = Bh + (size_t)h * F_;
    const fp16* Blp = Bl + (size_t)h * F_;
    fp16* C = (sel ? Kp : Qp) + (size_t)zz * P_ * P2S;
    const float* bp = biasT + (size_t)sel * H_ * P2 + (size_t)h * P2;
    int rowA0 = ty * 128, col0 = tx * 128;
    GEMM_MAIN(Ahp, Bhp, Blp, HF, HF, 0, 4);

#pragma unroll
    for (int mt = 0; mt < 2; mt++)
#pragma unroll
        for (int nt = 0; nt < 8; nt++) {
            int cix = col0 + n0 + nt * 8 + tig * 2;
            float2 bb = *(const float2*)(bp + cix);
#pragma unroll
            for (int half = 0; half < 2; half++) {
                int r = rowA0 + m0 + mt * 16 + g + half * 8;
                int sh = r & 31;
                size_t base = (size_t)r * P2S + cix + sh;
                C[base]     = __float2half(acc[mt][nt][half * 2]     * 0.25f + bb.x);
                C[base + 1] = __float2half(acc[mt][nt][half * 2 + 1] * 0.25f + bb.y);
            }
        }
}

// ---------------- kernel: fused gather + HMMA a@Wout (512 threads) -------------
#define FIN_A   0
#define FIN_YQ  81920
#define FIN_YK  (FIN_YQ + 16384)
#define FIN_WH  (FIN_YK + 16384)
#define FIN_WL  (FIN_WH + 10240)
#define SMEM_FINAL (FIN_WL + 10240)
#define M128 (M_ * F_)

__global__ __launch_bounds__(512) void final_kernel(
    const fp16* __restrict__ QK, const fp16* __restrict__ Qp,
    const fp16* __restrict__ Kp, const float* __restrict__ ypart,
    const float* __restrict__ Wout, const float* __restrict__ bout,
    float* __restrict__ out)
{
    extern __shared__ char smem[];
    __half* a_s  = (__half*)smem;
    float*  yq_s = (float*)(smem + FIN_YQ);
    float*  yk_s = (float*)(smem + FIN_YK);
    __half* wh_s = (__half*)(smem + FIN_WH);
    __half* wl_s = (__half*)(smem + FIN_WL);
    uint32_t smb = (uint32_t)__cvta_generic_to_shared(smem);

    int b  = blockIdx.z;
    int qt = blockIdx.y * 32;
    int kt = blockIdx.x * 32;
    int tid = threadIdx.x;

    // hoisted phase-2 Kp loads (independent of phase 1) -> high MLP
    uint4 kpre[8];
#pragma unroll
    for (int u = 0; u < 8; u++) {
        int i = tid + u * 512;
        int h  = (i & 15) | ((i >> 7) & 16);
        int q0 = ((i >> 4) & 3) * 8;
        int k  = (i >> 6) & 31;
        size_t zb = (size_t)(b * 32 + h);
        kpre[u] = *(const uint4*)(Kp + (zb * P_ + kt + k) * P2S + (P_ + qt - kt + q0));
    }

    // stage Wout^T split hi/lo, stride-40-half rows (rows = f)
    for (int i = tid; i < 32 * 128; i += 512) {
        int h = i >> 7, f = i & 127;
        float v = Wout[h * F_ + f];
        __half hi = __float2half(v);
        wh_s[f * 40 + h] = hi;
        wl_s[f * 40 + h] = __float2half(v - __half2float(hi));
    }

    // stage yq (+bout) / yk, float4 vectorized
#pragma unroll
    for (int u = 0; u < 2; u++) {
        int i = tid + u * 512;
        int q = i >> 5, f = (i & 31) * 4;
        size_t rq = ((size_t)(b * P_ + qt + q)) * F_ + f;
        size_t rk = ((size_t)(b * P_ + kt + q)) * F_ + f;
        float4 vq = *(const float4*)(bout + f);
        float4 vk = make_float4(0.f, 0.f, 0.f, 0.f);
#pragma unroll
        for (int s = 0; s < 4; s++) {
            float4 a = *(const float4*)(ypart + (size_t)s * M128 + rq);
            float4 c = *(const float4*)(ypart + (size_t)(4 + s) * M128 + rk);
            vq.x += a.x; vq.y += a.y; vq.z += a.z; vq.w += a.w;
            vk.x += c.x; vk.y += c.y; vk.z += c.z; vk.w += c.w;
        }
        *(float4*)(yq_s + q * 128 + f) = vq;
        *(float4*)(yk_s + q * 128 + f) = vk;
    }

    // gather phase 1: a = QK + Qp (h spread across lanes, fully unrolled)
#pragma unroll
    for (int u = 0; u < 8; u++) {
        int i = tid + u * 512;
        int h  = (i & 15) | ((i >> 7) & 16);
        int k0 = ((i >> 4) & 3) * 8;
        int q  = (i >> 6) & 31;
        int gq = qt + q;
        size_t zb = (size_t)(b * 32 + h);
        uint4 vqk = *(const uint4*)(QK + (zb * P_ + gq) * P_ + kt + k0);
        uint4 vqp = *(const uint4*)(Qp + (zb * P_ + gq) * P2S + (P_ + kt - qt + k0));
        const __half2* hqk = (const __half2*)&vqk;
        const __half2* hqp = (const __half2*)&vqp;
        int m = q * 32 + k0;
#pragma unroll
        for (int j = 0; j < 4; j++) {
            __half2 s = __hadd2(hqk[j], hqp[j]);
            a_s[(m + 2 * j)     * 40 + h] = __low2half(s);
            a_s[(m + 2 * j + 1) * 40 + h] = __high2half(s);
        }
    }
    __syncthreads();

    // gather phase 2: a += Kp using preloaded registers
#pragma unroll
    for (int u = 0; u < 8; u++) {
        int i = tid + u * 512;
        int h  = (i & 15) | ((i >> 7) & 16);
        int q0 = ((i >> 4) & 3) * 8;
        int k  = (i >> 6) & 31;
        const __half* hk = (const __half*)&kpre[u];
#pragma unroll
        for (int j = 0; j < 8; j++) {
            int ix = ((q0 + j) * 32 + k) * 40 + h;
            a_s[ix] = __hadd(a_s[ix], hk[j]);
        }
    }
    __syncthreads();

    // HMMA: out[m,f] = a[m,h] @ WoutT[f,h], 16 warps x 64 rows
    int warp = tid >> 5, lane = tid & 31;
    int g = lane >> 2, tig = lane & 3;
    int lr = lane & 15, lh = lane >> 4;
    int warpM = warp * 64;

    uint32_t af[4][2][4];
#pragma unroll
    for (int mf = 0; mf < 4; mf++)
#pragma unroll
        for (int ks = 0; ks < 2; ks++) {
            uint32_t aa = smb + ((warpM + mf * 16 + lr) * 20 + lh * 4 + ks * 8) * 4;
            LDSM4(af[mf][ks][0], af[mf][ks][1], af[mf][ks][2], af[mf][ks][3], aa);
        }

#pragma unroll
    for (int np = 0; np < 4; np++) {      // 4 passes over f (32 cols each)
        float acc[4][4][4];
#pragma unroll
        for (int i = 0; i < 4; i++)
#pragma unroll
            for (int j = 0; j < 4; j++)
#pragma unroll
                for (int l = 0; l < 4; l++) acc[i][j][l] = 0.f;

#pragma unroll
        for (int ks = 0; ks < 2; ks++) {
            uint32_t bh[4][2], bl[4][2];
#pragma unroll
            for (int tp = 0; tp < 2; tp++) {
                uint32_t ba = smb + FIN_WH +
                    ((np * 32 + tp * 16 + lr) * 20 + lh * 4 + ks * 8) * 4;
                LDSM4(bh[2*tp][0], bh[2*tp+1][0], bh[2*tp][1], bh[2*tp+1][1], ba);
                LDSM4(bl[2*tp][0], bl[2*tp+1][0], bl[2*tp][1], bl[2*tp+1][1],
                      ba + 10240u);
            }
#pragma unroll
            for (int mf = 0; mf < 4; mf++)
#pragma unroll
                for (int nf = 0; nf < 4; nf++)
                    MMA_FP16(acc[mf][nf], af[mf][ks], bh[nf]);
#pragma unroll
            for (int mf = 0; mf < 4; mf++)
#pragma unroll
                for (int nf = 0; nf < 4; nf++)
                    MMA_FP16(acc[mf][nf], af[mf][ks], bl[nf]);
        }

        // store pass: add yq+bout and yk, write fp32 out
#pragma unroll
        for (int mf = 0; mf < 4; mf++)
#pragma unroll
            for (int nf = 0; nf < 4; nf++) {
                int f = np * 32 + nf * 8 + tig * 2;
#pragma unroll
                for (int half = 0; half < 2; half++) {
                    int r = warpM + mf * 16 + g + half * 8;
                    int q = r >> 5, k = r & 31;
                    float b0 = yq_s[q * 128 + f]     + yk_s[k * 128 + f];
                    float b1 = yq_s[q * 128 + f + 1] + yk_s[k * 128 + f + 1];
                    float* orow = out +
                        (((size_t)(b * P_) + qt + q) * P_ + kt + k) * F_ + f;
                    *(float2*)orow = make_float2(acc[mf][nf][half * 2] + b0,
                                                 acc[mf][nf][half * 2 + 1] + b1);
                }
            }
    }
}

// ---------------- launch ------------------------------------------------------
extern "C" void kernel_launch(void* const* d_in, const int* in_sizes, int n_in,
                              void* d_out, int out_size)
{
    const float* x        = (const float*)d_in[0];
    const float* norm_w   = (const float*)d_in[1];
    const float* Wq       = (const float*)d_in[2];
    const float* Wk       = (const float*)d_in[3];
    const float* Wpos     = (const float*)d_in[4];
    const float* bpos     = (const float*)d_in[5];
    const float* q_r_bias = (const float*)d_in[6];
    const float* k_r_bias = (const float*)d_in[7];
    const float* Wyq      = (const float*)d_in[8];
    const float* Wyk      = (const float*)d_in[9];
    const float* Wout     = (const float*)d_in[10];
    const float* bout     = (const float*)d_in[11];
    float* out = (float*)d_out;

    fp16 *p_xnh, *p_xgh;
    fp16 *p_wqth, *p_wqtl, *p_wkth, *p_wktl, *p_wyqh, *p_wyql, *p_wykh, *p_wykl;
    fp16 *p_posh, *p_posl, *p_qh, *p_kh, *p_kl, *p_QK, *p_Qp, *p_Kp;
    float *p_bias, *p_ypart;
    cudaGetSymbolAddress((void**)&p_xnh,  g_xnh);
    cudaGetSymbolAddress((void**)&p_xgh,  g_xgh);
    cudaGetSymbolAddress((void**)&p_wqth, g_wqth);
    cudaGetSymbolAddress((void**)&p_wqtl, g_wqtl);
    cudaGetSymbolAddress((void**)&p_wkth, g_wkth);
    cudaGetSymbolAddress((void**)&p_wktl, g_wktl);
    cudaGetSymbolAddress((void**)&p_wyqh, g_wyqh);
    cudaGetSymbolAddress((void**)&p_wyql, g_wyql);
    cudaGetSymbolAddress((void**)&p_wykh, g_wykh);
    cudaGetSymbolAddress((void**)&p_wykl, g_wykl);
    cudaGetSymbolAddress((void**)&p_posh, g_posh);
    cudaGetSymbolAddress((void**)&p_posl, g_posl);
    cudaGetSymbolAddress((void**)&p_qh,   g_qh);
    cudaGetSymbolAddress((void**)&p_kh,   g_kh);
    cudaGetSymbolAddress((void**)&p_kl,   g_kl);
    cudaGetSymbolAddress((void**)&p_bias, g_bias);
    cudaGetSymbolAddress((void**)&p_ypart, g_ypart);
    cudaGetSymbolAddress((void**)&p_QK,   g_QK);
    cudaGetSymbolAddress((void**)&p_Qp,   g_Qp);
    cudaGetSymbolAddress((void**)&p_Kp,   g_Kp);

    cudaFuncSetAttribute(proj_gemm, cudaFuncAttributeMaxDynamicSharedMemorySize, GEMM_SMEM);
    cudaFuncSetAttribute(y_gemm,    cudaFuncAttributeMaxDynamicSharedMemorySize, GEMM_SMEM);
    cudaFuncSetAttribute(qk_gemm,   cudaFuncAttributeMaxDynamicSharedMemorySize, GEMM_SMEM);
    cudaFuncSetAttribute(qpkp_gemm, cudaFuncAttributeMaxDynamicSharedMemorySize, GEMM_SMEM);
    cudaFuncSetAttribute(final_kernel, cudaFuncAttributeMaxDynamicSharedMemorySize, SMEM_FINAL);

    wconv2_kernel<<<dim3(128, 48, 2), 256>>>(
        Wq, p_wqth, p_wqtl, Wk, p_wkth, p_wktl, C_, HF);
    pool_norm_kernel<<<1024, 256>>>(x, norm_w);
    proj_gemm<<<dim3(32, 8, 2), 256, GEMM_SMEM>>>(
        p_xnh, p_wqth, p_wqtl, p_wkth, p_wktl, p_qh, p_kh, p_kl);

    pos_kernel<<<dim3(32, 4), 128>>>(Wpos, bpos);
    bias_kernel<<<1024, 256>>>(q_r_bias, k_r_bias);
    wconv2_kernel<<<dim3(4, 48, 2), 256>>>(
        Wyq, p_wyqh, p_wyql, Wyk, p_wykh, p_wykl, C_, F_);
    y_gemm<<<dim3(1, 8, 8), 256, GEMM_SMEM>>>(
        p_xgh, p_wyqh, p_wyql, p_wykh, p_wykl, p_ypart);

    qk_gemm<<<dim3(4, 4, 64), 256, GEMM_SMEM>>>(p_qh, p_kh, p_kl, p_QK);
    qpkp_gemm<<<dim3(20, 1, 128), 256, GEMM_SMEM>>>(
        p_qh, p_kh, p_posh, p_posl, p_Qp, p_Kp, p_bias);

    final_kernel<<<dim3(16, 16, 2), 512, SMEM_FINAL>>>(
        p_QK, p_Qp, p_Kp, p_ypart, Wout, bout, out);
}